// round 2
// baseline (speedup 1.0000x reference)
#include <cuda_runtime.h>
#include <math.h>

#define S_LEN 1536
#define DM    1024
#define NH    16
#define HD    64
#define H2    32
#define DQK   48
#define KVCC  256
#define ROPE_ 32
#define QCC   384
#define DFF   4096
#define SPP   384
#define EPS_RMS 1.1920929e-07f
#define ATTN_EPS 1e-5f
#define SCALING 0.14433756729740643f  /* 48^-0.5 */
#define LAMBDA_INIT 0.2f

// ------------------------- device scratch -------------------------
__device__ float g_xin [S_LEN * DM];
__device__ float g_ckv [S_LEN * (KVCC + ROPE_)];
__device__ float g_ckvn[S_LEN * KVCC];
__device__ float g_kvup[S_LEN * 2048];
__device__ float g_cq  [S_LEN * QCC];
__device__ float g_cqn [S_LEN * QCC];
__device__ float g_qf  [S_LEN * 1536];
__device__ float g_Q   [(size_t)H2 * S_LEN * DQK];
__device__ float g_K   [(size_t)H2 * S_LEN * DQK];
__device__ float g_V   [(size_t)NH * S_LEN * HD];
__device__ float g_P   [(size_t)H2 * S_LEN * S_LEN];   // ~302 MB
__device__ float g_g   [NH * S_LEN];
__device__ float g_ao  [(size_t)NH * S_LEN * HD];
__device__ float g_af  [S_LEN * DM];
__device__ float g_x2  [S_LEN * DM];
__device__ float g_hb  [S_LEN * DM];
__device__ float g_uv  [(size_t)S_LEN * 2 * DFF];
__device__ float g_act [(size_t)S_LEN * DFF];
__device__ float g_lambda;

// ------------------------- generic SGEMM -------------------------
// C[M,N] = A[M,K] * op(B) (+ Res), op(B)=B^T if TB (B is [N,K]) else B ([K,N]).
// Batched via blockIdx.z with strides sA,sB,sC. Res is non-batched (or null).
#define BM 64
#define BN 64
#define BK 16

template <bool TB>
__global__ void sgemm_k(const float* __restrict__ A, const float* __restrict__ B,
                        const float* __restrict__ Res, float* __restrict__ C,
                        int M, int N, int K,
                        long long sA, long long sB, long long sC)
{
    A += (long long)blockIdx.z * sA;
    B += (long long)blockIdx.z * sB;
    C += (long long)blockIdx.z * sC;

    __shared__ float As[BK][BM];
    __shared__ float Bs[BK][BN + 1];

    const int tid = threadIdx.x;            // 256 threads
    const int tx = tid & 15, ty = tid >> 4;
    const int row0 = blockIdx.y * BM;
    const int col0 = blockIdx.x * BN;

    float acc[4][4];
#pragma unroll
    for (int i = 0; i < 4; i++)
#pragma unroll
        for (int j = 0; j < 4; j++) acc[i][j] = 0.f;

    for (int k0 = 0; k0 < K; k0 += BK) {
        // load A tile (BM x BK)
#pragma unroll
        for (int e = tid; e < BM * BK; e += 256) {
            int m = e >> 4, kk = e & 15;
            float v = 0.f;
            if (row0 + m < M && k0 + kk < K)
                v = A[(long long)(row0 + m) * K + k0 + kk];
            As[kk][m] = v;
        }
        // load B tile
        if (TB) {
#pragma unroll
            for (int e = tid; e < BN * BK; e += 256) {
                int n = e >> 4, kk = e & 15;
                float v = 0.f;
                if (col0 + n < N && k0 + kk < K)
                    v = B[(long long)(col0 + n) * K + k0 + kk];
                Bs[kk][n] = v;
            }
        } else {
#pragma unroll
            for (int e = tid; e < BN * BK; e += 256) {
                int n = e & 63, kk = e >> 6;
                float v = 0.f;
                if (col0 + n < N && k0 + kk < K)
                    v = B[(long long)(k0 + kk) * N + col0 + n];
                Bs[kk][n] = v;
            }
        }
        __syncthreads();
#pragma unroll
        for (int kk = 0; kk < BK; kk++) {
            float a[4], b[4];
#pragma unroll
            for (int i = 0; i < 4; i++) a[i] = As[kk][ty * 4 + i];
#pragma unroll
            for (int j = 0; j < 4; j++) b[j] = Bs[kk][tx * 4 + j];
#pragma unroll
            for (int i = 0; i < 4; i++)
#pragma unroll
                for (int j = 0; j < 4; j++) acc[i][j] += a[i] * b[j];
        }
        __syncthreads();
    }

#pragma unroll
    for (int i = 0; i < 4; i++) {
        int m = row0 + ty * 4 + i;
        if (m >= M) continue;
#pragma unroll
        for (int j = 0; j < 4; j++) {
            int n = col0 + tx * 4 + j;
            if (n >= N) continue;
            float v = acc[i][j];
            if (Res) v += Res[(long long)m * N + n];
            C[(long long)m * N + n] = v;
        }
    }
}

// ------------------------- rmsnorm -------------------------
__global__ void rmsnorm_k(const float* __restrict__ in, const float* __restrict__ w,
                          float* __restrict__ out, int cols, int in_ld, int out_ld, float eps)
{
    const long long row = blockIdx.x;
    const float* ip = in + row * in_ld;
    float* op = out + row * out_ld;

    float ss = 0.f;
    for (int j = threadIdx.x; j < cols; j += blockDim.x) {
        float v = ip[j];
        ss += v * v;
    }
    __shared__ float sh[32];
    int lane = threadIdx.x & 31, wid = threadIdx.x >> 5;
#pragma unroll
    for (int o = 16; o; o >>= 1) ss += __shfl_xor_sync(0xffffffffu, ss, o);
    if (lane == 0) sh[wid] = ss;
    __syncthreads();
    int nw = (blockDim.x + 31) >> 5;
    float tot = 0.f;
    if (threadIdx.x < nw) tot = sh[threadIdx.x];
    if (wid == 0) {
#pragma unroll
        for (int o = 16; o; o >>= 1) tot += __shfl_xor_sync(0xffffffffu, tot, o);
        if (lane == 0) sh[0] = tot;
    }
    __syncthreads();
    float inv = rsqrtf(sh[0] / (float)cols + eps);
    for (int j = threadIdx.x; j < cols; j += blockDim.x)
        op[j] = ip[j] * inv * w[j];
}

// ------------------------- build Q/K/V with RoPE -------------------------
__global__ void build_qkv_k(const float* __restrict__ qf, const float* __restrict__ kvup,
                            const float* __restrict__ ckv,
                            const float* __restrict__ fcos, const float* __restrict__ fsin,
                            float* __restrict__ Q, float* __restrict__ K, float* __restrict__ V)
{
    const int i = blockIdx.x;                 // token
    const int tid = threadIdx.x;              // 128
    __shared__ float cs[8], sn[8];
    int p = i >> 2;                           // rope position = i // NUM_SEQ
    if (tid < 8) {
        if (p == 0) { cs[tid] = 1.f; sn[tid] = 0.f; }
        else { cs[tid] = fcos[(p - 1) * 8 + tid]; sn[tid] = fsin[(p - 1) * 8 + tid]; }
    }
    __syncthreads();

    const float* qrow = qf + (long long)i * 1536;
    const float* krow = kvup + (long long)i * 2048;
    const float* crow = ckv + (long long)i * (KVCC + ROPE_);

    for (int e = tid; e < H2 * DQK; e += 128) {
        int h2 = e / DQK, d = e % DQK;
        int h = h2 >> 1, c = h2 & 1;
        float qv, kv;
        if (d < 32) {
            qv = qrow[h * 96 + c * 32 + d];
            kv = krow[h * 128 + c * 32 + d];
        } else {
            int ee = d - 32;
            int f = ee >> 1;
            float q0 = qrow[h * 96 + 64 + c * 16 + 2 * f];
            float q1 = qrow[h * 96 + 64 + c * 16 + 2 * f + 1];
            float k0 = crow[KVCC + c * 16 + 2 * f];
            float k1 = crow[KVCC + c * 16 + 2 * f + 1];
            float C = cs[f], Sv = sn[f];
            if ((ee & 1) == 0) { qv = q0 * C - q1 * Sv; kv = k0 * C - k1 * Sv; }
            else               { qv = q0 * Sv + q1 * C; kv = k0 * Sv + k1 * C; }
        }
        Q[(long long)h2 * S_LEN * DQK + (long long)i * DQK + d] = qv;
        K[(long long)h2 * S_LEN * DQK + (long long)i * DQK + d] = kv;
    }
    for (int e = tid; e < NH * HD; e += 128) {
        int h = e >> 6, d = e & 63;
        V[(long long)h * S_LEN * HD + (long long)i * HD + d] = krow[h * 128 + 64 + d];
    }
}

// ------------------------- softmax with fused scale+mask -------------------------
__global__ void softmax_k(float* __restrict__ P)
{
    const long long rowi = blockIdx.x;         // 0 .. H2*S-1
    const int r = (int)(rowi % S_LEN);
    float* row = P + rowi * S_LEN;
    const int rp = r % SPP;

    __shared__ float sh[32];
    int lane = threadIdx.x & 31, wid = threadIdx.x >> 5;

    // pass 1: max
    float mx = -3.4e38f;
    for (int j = threadIdx.x; j < S_LEN; j += 256) {
        float v = ((j % SPP) > rp) ? -1e9f : row[j] * SCALING;
        mx = fmaxf(mx, v);
    }
#pragma unroll
    for (int o = 16; o; o >>= 1) mx = fmaxf(mx, __shfl_xor_sync(0xffffffffu, mx, o));
    if (lane == 0) sh[wid] = mx;
    __syncthreads();
    float gmx = -3.4e38f;
    if (threadIdx.x < 8) gmx = sh[threadIdx.x];
    if (wid == 0) {
#pragma unroll
        for (int o = 16; o; o >>= 1) gmx = fmaxf(gmx, __shfl_xor_sync(0xffffffffu, gmx, o));
        if (lane == 0) sh[0] = gmx;
    }
    __syncthreads();
    gmx = sh[0];
    __syncthreads();

    // pass 2: exp + sum
    float sum = 0.f;
    for (int j = threadIdx.x; j < S_LEN; j += 256) {
        float v = ((j % SPP) > rp) ? -1e9f : row[j] * SCALING;
        float e = __expf(v - gmx);
        row[j] = e;
        sum += e;
    }
#pragma unroll
    for (int o = 16; o; o >>= 1) sum += __shfl_xor_sync(0xffffffffu, sum, o);
    if (lane == 0) sh[wid] = sum;
    __syncthreads();
    float gs = 0.f;
    if (threadIdx.x < 8) gs = sh[threadIdx.x];
    if (wid == 0) {
#pragma unroll
        for (int o = 16; o; o >>= 1) gs += __shfl_xor_sync(0xffffffffu, gs, o);
        if (lane == 0) sh[0] = gs;
    }
    __syncthreads();
    float inv = 1.f / sh[0];

    // pass 3: normalize
    for (int j = threadIdx.x; j < S_LEN; j += 256)
        row[j] *= inv;
}

// ------------------------- column mean of even sub-heads -------------------------
__global__ void colmean_k(const float* __restrict__ P, float* __restrict__ g)
{
    int j = blockIdx.x * blockDim.x + threadIdx.x;
    int h = blockIdx.y;
    if (j >= S_LEN) return;
    const float* base = P + (long long)(2 * h) * S_LEN * S_LEN + j;
    float s = 0.f;
    for (int i = 0; i < S_LEN; i++) s += base[(long long)i * S_LEN];
    g[h * S_LEN + j] = s / (float)S_LEN;
}

// ------------------------- lambda scalar -------------------------
__global__ void lambda_k_(const float* __restrict__ q1, const float* __restrict__ k1,
                          const float* __restrict__ q2, const float* __restrict__ k2,
                          float* __restrict__ out)
{
    int t = threadIdx.x;  // 32
    float a = q1[t] * k1[t];
    float b = q2[t] * k2[t];
#pragma unroll
    for (int o = 16; o; o >>= 1) {
        a += __shfl_xor_sync(0xffffffffu, a, o);
        b += __shfl_xor_sync(0xffffffffu, b, o);
    }
    if (t == 0) *out = expf(a) - expf(b) + LAMBDA_INIT;
}

// ------------------------- differential combine (in-place into even head) -----
__global__ void combine_k(float* __restrict__ P, const float* __restrict__ g,
                          const float* __restrict__ lamp)
{
    long long idx = (long long)blockIdx.x * blockDim.x + threadIdx.x;
    if (idx >= (long long)S_LEN * S_LEN) return;
    int h = blockIdx.y;
    int i = (int)(idx / S_LEN), j = (int)(idx % S_LEN);
    float* p1 = P + (long long)(2 * h) * S_LEN * S_LEN;
    const float* p2 = P + (long long)(2 * h + 1) * S_LEN * S_LEN;
    float v;
    if ((j % SPP) > (i % SPP)) v = 0.f;
    else {
        float lam = *lamp;
        v = p1[idx] - lam * p2[idx] + lam * g[h * S_LEN + j];
    }
    p1[idx] = v;
}

// ------------------------- per (token, head) rmsnorm -------------------------
// NOTE: reference reshapes the (b, NH, s, HD) tensor directly to (b, s, NH*HD),
// i.e. a raw memory reinterpretation. So we keep [h][i][d] layout: the o_w GEMM
// then reads this buffer as a [S_LEN][DM] row-major matrix.
__global__ void attn_norm_k(const float* __restrict__ ao, const float* __restrict__ w,
                            float* __restrict__ outf)
{
    int i = blockIdx.x, h = blockIdx.y, d = threadIdx.x;  // 64 threads
    long long idx = ((long long)h * S_LEN + i) * HD + d;
    float v = ao[idx];
    float sq = v * v;
    __shared__ float sh[2];
#pragma unroll
    for (int o = 16; o; o >>= 1) sq += __shfl_xor_sync(0xffffffffu, sq, o);
    if ((d & 31) == 0) sh[d >> 5] = sq;
    __syncthreads();
    float tot = sh[0] + sh[1];
    outf[idx] = v * rsqrtf(tot / (float)HD + ATTN_EPS) * w[d];
}

// ------------------------- SwiGLU -------------------------
__global__ void swiglu_k(const float* __restrict__ uv, float* __restrict__ act)
{
    long long idx = (long long)blockIdx.x * blockDim.x + threadIdx.x;
    if (idx >= (long long)S_LEN * DFF) return;
    long long i = idx / DFF, j = idx % DFF;
    float u = uv[i * (2 * DFF) + j];
    float vg = uv[i * (2 * DFF) + DFF + j];
    act[idx] = u * (vg / (1.f + __expf(-vg)));
}

// ------------------------- host -------------------------
extern "C" void kernel_launch(void* const* d_in, const int* in_sizes, int n_in,
                              void* d_out, int out_size)
{
    const float* x    = (const float*)d_in[0];
    const float* fc   = (const float*)d_in[1];
    const float* fs   = (const float*)d_in[2];
    const float* n1w  = (const float*)d_in[3];
    const float* n2w  = (const float*)d_in[4];
    const float* kvdw = (const float*)d_in[5];
    const float* qdw  = (const float*)d_in[6];
    const float* kvnw = (const float*)d_in[7];
    const float* qnw  = (const float*)d_in[8];
    const float* kvuw = (const float*)d_in[9];
    const float* quw  = (const float*)d_in[10];
    const float* lq1  = (const float*)d_in[11];
    const float* lk1  = (const float*)d_in[12];
    const float* lq2  = (const float*)d_in[13];
    const float* lk2  = (const float*)d_in[14];
    const float* anw  = (const float*)d_in[15];
    const float* ow   = (const float*)d_in[16];
    const float* fiw  = (const float*)d_in[17];
    const float* fow  = (const float*)d_in[18];
    float* outp = (float*)d_out;

    float *xin, *ckv, *ckvn, *kvup, *cq, *cqn, *qf, *Q, *K, *V, *P, *gg, *ao, *af, *x2, *hb, *uv, *act, *lam;
    cudaGetSymbolAddress((void**)&xin,  g_xin);
    cudaGetSymbolAddress((void**)&ckv,  g_ckv);
    cudaGetSymbolAddress((void**)&ckvn, g_ckvn);
    cudaGetSymbolAddress((void**)&kvup, g_kvup);
    cudaGetSymbolAddress((void**)&cq,   g_cq);
    cudaGetSymbolAddress((void**)&cqn,  g_cqn);
    cudaGetSymbolAddress((void**)&qf,   g_qf);
    cudaGetSymbolAddress((void**)&Q,    g_Q);
    cudaGetSymbolAddress((void**)&K,    g_K);
    cudaGetSymbolAddress((void**)&V,    g_V);
    cudaGetSymbolAddress((void**)&P,    g_P);
    cudaGetSymbolAddress((void**)&gg,   g_g);
    cudaGetSymbolAddress((void**)&ao,   g_ao);
    cudaGetSymbolAddress((void**)&af,   g_af);
    cudaGetSymbolAddress((void**)&x2,   g_x2);
    cudaGetSymbolAddress((void**)&hb,   g_hb);
    cudaGetSymbolAddress((void**)&uv,   g_uv);
    cudaGetSymbolAddress((void**)&act,  g_act);
    cudaGetSymbolAddress((void**)&lam,  g_lambda);

    auto grid_for = [](int M, int N, int batch) {
        return dim3((unsigned)((N + BN - 1) / BN), (unsigned)((M + BM - 1) / BM), (unsigned)batch);
    };

    // 1. xin = rmsnorm(x, norm1_w)
    rmsnorm_k<<<S_LEN, 256>>>(x, n1w, xin, DM, DM, DM, EPS_RMS);
    // 2. ckv = xin @ kv_down_w^T  [1536, 288]
    sgemm_k<true><<<grid_for(S_LEN, KVCC + ROPE_, 1), 256>>>(xin, kvdw, nullptr, ckv,
        S_LEN, KVCC + ROPE_, DM, 0, 0, 0);
    // 3. ckvn = rmsnorm(ckv[:, :256])
    rmsnorm_k<<<S_LEN, 256>>>(ckv, kvnw, ckvn, KVCC, KVCC + ROPE_, KVCC, EPS_RMS);
    // 4. kvup = ckvn @ kv_up_w^T  [1536, 2048]
    sgemm_k<true><<<grid_for(S_LEN, 2048, 1), 256>>>(ckvn, kvuw, nullptr, kvup,
        S_LEN, 2048, KVCC, 0, 0, 0);
    // 5. cq = xin @ q_down_w^T [1536, 384]
    sgemm_k<true><<<grid_for(S_LEN, QCC, 1), 256>>>(xin, qdw, nullptr, cq,
        S_LEN, QCC, DM, 0, 0, 0);
    // 6. cqn = rmsnorm(cq)
    rmsnorm_k<<<S_LEN, 256>>>(cq, qnw, cqn, QCC, QCC, QCC, EPS_RMS);
    // 7. qf = cqn @ q_up_w^T [1536, 1536]
    sgemm_k<true><<<grid_for(S_LEN, 1536, 1), 256>>>(cqn, quw, nullptr, qf,
        S_LEN, 1536, QCC, 0, 0, 0);
    // 8. build Q/K/V with RoPE
    build_qkv_k<<<S_LEN, 128>>>(qf, kvup, ckv, fc, fs, Q, K, V);
    // 9. logits: P[h] = Q[h] @ K[h]^T, batched over 32 sub-heads
    sgemm_k<true><<<grid_for(S_LEN, S_LEN, H2), 256>>>(Q, K, nullptr, P,
        S_LEN, S_LEN, DQK,
        (long long)S_LEN * DQK, (long long)S_LEN * DQK, (long long)S_LEN * S_LEN);
    // 10. lambda scalar
    lambda_k_<<<1, 32>>>(lq1, lk1, lq2, lk2, lam);
    // 11. softmax rows (fused scale + mask)
    softmax_k<<<H2 * S_LEN, 256>>>(P);
    // 12. column means of even sub-heads
    colmean_k<<<dim3((S_LEN + 255) / 256, NH), 256>>>(P, gg);
    // 13. differential combine (in place into even sub-head slot)
    {
        long long tot = (long long)S_LEN * S_LEN;
        combine_k<<<dim3((unsigned)((tot + 255) / 256), NH), 256>>>(P, gg, lam);
    }
    // 14. ao[h] = Pdiff[h] @ V[h], batched over 16 heads (NN gemm)
    sgemm_k<false><<<grid_for(S_LEN, HD, NH), 256>>>(P, V, nullptr, ao,
        S_LEN, HD, S_LEN,
        (long long)2 * S_LEN * S_LEN, (long long)S_LEN * HD, (long long)S_LEN * HD);
    // 15. per (token, head) rmsnorm -> af, SAME [h][i][d] layout (reference's
    //     scrambled reshape: (b,NH,s,HD) memory read as (b,s,NH*HD))
    attn_norm_k<<<dim3(S_LEN, NH), 64>>>(ao, anw, af);
    // 16. x2 = x + af @ o_w^T   (af interpreted as [S_LEN][DM] row-major)
    sgemm_k<true><<<grid_for(S_LEN, DM, 1), 256>>>(af, ow, x, x2,
        S_LEN, DM, DM, 0, 0, 0);
    // 17. hb = rmsnorm(x2, norm2_w)
    rmsnorm_k<<<S_LEN, 256>>>(x2, n2w, hb, DM, DM, DM, EPS_RMS);
    // 18. uv = hb @ ff_in_w^T [1536, 8192]
    sgemm_k<true><<<grid_for(S_LEN, 2 * DFF, 1), 256>>>(hb, fiw, nullptr, uv,
        S_LEN, 2 * DFF, DM, 0, 0, 0);
    // 19. act = u * silu(vg)
    {
        long long tot = (long long)S_LEN * DFF;
        swiglu_k<<<(unsigned)((tot + 255) / 256), 256>>>(uv, act);
    }
    // 20. out = x2 + act @ ff_out_w^T
    sgemm_k<true><<<grid_for(S_LEN, DM, 1), 256>>>(act, fow, x2, outp,
        S_LEN, DM, DFF, 0, 0, 0);
}

// round 3
// speedup vs baseline: 2.9290x; 2.9290x over previous
#include <cuda_runtime.h>
#include <math.h>

#define S_LEN 1536
#define DM    1024
#define NH    16
#define HD    64
#define H2    32
#define DQK   48
#define DQKP  64      /* padded */
#define KVCC  256
#define ROPE_ 32
#define QCC   384
#define DFF   4096
#define SPP   384
#define EPS_RMS 1.1920929e-07f
#define ATTN_EPS 1e-5f
#define SCALING 0.14433756729740643f  /* 48^-0.5 */
#define LAMBDA_INIT 0.2f

// ------------------------- device scratch -------------------------
__device__ float g_xin [S_LEN * DM];
__device__ float g_ckv [S_LEN * (KVCC + ROPE_)];
__device__ float g_ckvn[S_LEN * KVCC];
__device__ float g_kvup[S_LEN * 2048];
__device__ float g_cq  [S_LEN * QCC];
__device__ float g_cqn [S_LEN * QCC];
__device__ float g_qf  [S_LEN * 1536];
__device__ float g_Q   [(size_t)H2 * S_LEN * DQKP];
__device__ float g_K   [(size_t)H2 * S_LEN * DQKP];
__device__ float g_V   [(size_t)NH * S_LEN * HD];
__device__ float g_P   [(size_t)H2 * S_LEN * S_LEN];   // ~302 MB
__device__ float g_g   [NH * S_LEN];
__device__ float g_ao  [(size_t)NH * S_LEN * HD];
__device__ float g_af  [S_LEN * DM];
__device__ float g_x2  [S_LEN * DM];
__device__ float g_hb  [S_LEN * DM];
__device__ float g_uv  [(size_t)S_LEN * 2 * DFF];
__device__ float g_act [(size_t)S_LEN * DFF];
__device__ float g_lambda;

// ------------------------- TF32 tensor-core GEMM -------------------------
// C[M,N] = A[M,K] * op(B) (+ Res).  TB: B is [N,K] row-major (op=B^T).
//                                   !TB: B is [K,N] row-major.
// Requirements: M % 128 == 0, K % 32 == 0, N % 4 == 0.  Batched via grid.z.
#define TBM 128
#define TBN 64
#define TBK 32
#define ASTR 36    /* As row stride: banks (4r + c) distinct for 8x4 frag */
#define BSTR 72    /* Bs row stride: banks (8k + n) distinct for 4x8 frag */

__device__ __forceinline__ unsigned f2tf32(float x) {
    unsigned r;
    asm("cvt.rna.tf32.f32 %0, %1;" : "=r"(r) : "f"(x));
    return r;
}

template <bool TB>
__global__ __launch_bounds__(256, 2)
void tgemm_k(const float* __restrict__ A, const float* __restrict__ B,
             const float* __restrict__ Res, float* __restrict__ C,
             int M, int N, int K,
             long long sA, long long sB, long long sC)
{
    A += (long long)blockIdx.z * sA;
    B += (long long)blockIdx.z * sB;
    C += (long long)blockIdx.z * sC;

    __shared__ float As[TBM * ASTR];
    __shared__ float Bs[TBK * BSTR];

    const int tid  = threadIdx.x;          // 256
    const int lane = tid & 31;
    const int warp = tid >> 5;             // 8 warps: 4 (M) x 2 (N)
    const int wm   = warp >> 1;
    const int wn   = warp & 1;
    const int row0 = blockIdx.y * TBM;
    const int col0 = blockIdx.x * TBN;

    const int grp = lane >> 2;             // 0..7
    const int tig = lane & 3;              // 0..3

    float acc[2][4][4];
#pragma unroll
    for (int i = 0; i < 2; i++)
#pragma unroll
        for (int j = 0; j < 4; j++)
#pragma unroll
            for (int l = 0; l < 4; l++) acc[i][j][l] = 0.f;

    for (int k0 = 0; k0 < K; k0 += TBK) {
        // ---- load A tile: 128 rows x 32 cols = 1024 float4, 4/thread ----
#pragma unroll
        for (int it = 0; it < 4; it++) {
            int f4 = tid + it * 256;
            int r  = f4 >> 3, c4 = f4 & 7;
            float4 v = *(const float4*)(A + (long long)(row0 + r) * K + k0 + c4 * 4);
            unsigned t0 = f2tf32(v.x), t1 = f2tf32(v.y), t2 = f2tf32(v.z), t3 = f2tf32(v.w);
            float* dst = &As[r * ASTR + c4 * 4];
            ((float4*)dst)[0] = make_float4(__uint_as_float(t0), __uint_as_float(t1),
                                            __uint_as_float(t2), __uint_as_float(t3));
        }
        // ---- load B tile ----
        if (TB) {
            // B [N,K]: 64 rows x 32 cols = 512 f4, 2/thread -> Bs[k][n]
#pragma unroll
            for (int it = 0; it < 2; it++) {
                int f4 = tid + it * 256;
                int n  = f4 >> 3, c4 = f4 & 7;
                float4 v = make_float4(0.f, 0.f, 0.f, 0.f);
                if (col0 + n < N)
                    v = *(const float4*)(B + (long long)(col0 + n) * K + k0 + c4 * 4);
                Bs[(c4 * 4 + 0) * BSTR + n] = __uint_as_float(f2tf32(v.x));
                Bs[(c4 * 4 + 1) * BSTR + n] = __uint_as_float(f2tf32(v.y));
                Bs[(c4 * 4 + 2) * BSTR + n] = __uint_as_float(f2tf32(v.z));
                Bs[(c4 * 4 + 3) * BSTR + n] = __uint_as_float(f2tf32(v.w));
            }
        } else {
            // B [K,N]: 32 rows x 64 cols = 512 f4, 2/thread -> Bs[k][n]
#pragma unroll
            for (int it = 0; it < 2; it++) {
                int f4 = tid + it * 256;
                int k  = f4 >> 4, c4 = f4 & 15;
                float4 v = make_float4(0.f, 0.f, 0.f, 0.f);
                if (col0 + c4 * 4 < N)
                    v = *(const float4*)(B + (long long)(k0 + k) * N + col0 + c4 * 4);
                unsigned t0 = f2tf32(v.x), t1 = f2tf32(v.y), t2 = f2tf32(v.z), t3 = f2tf32(v.w);
                float* dst = &Bs[k * BSTR + c4 * 4];
                ((float4*)dst)[0] = make_float4(__uint_as_float(t0), __uint_as_float(t1),
                                                __uint_as_float(t2), __uint_as_float(t3));
            }
        }
        __syncthreads();

        // ---- compute: 4 k-steps of 8 ----
#pragma unroll
        for (int kk = 0; kk < TBK; kk += 8) {
            unsigned af[2][4], bf[4][2];
#pragma unroll
            for (int mi = 0; mi < 2; mi++) {
                int r = wm * 32 + mi * 16 + grp;
                int c = kk + tig;
                af[mi][0] = __float_as_uint(As[r * ASTR + c]);
                af[mi][1] = __float_as_uint(As[(r + 8) * ASTR + c]);
                af[mi][2] = __float_as_uint(As[r * ASTR + c + 4]);
                af[mi][3] = __float_as_uint(As[(r + 8) * ASTR + c + 4]);
            }
#pragma unroll
            for (int ni = 0; ni < 4; ni++) {
                int n = wn * 32 + ni * 8 + grp;
                int k = kk + tig;
                bf[ni][0] = __float_as_uint(Bs[k * BSTR + n]);
                bf[ni][1] = __float_as_uint(Bs[(k + 4) * BSTR + n]);
            }
#pragma unroll
            for (int mi = 0; mi < 2; mi++)
#pragma unroll
                for (int ni = 0; ni < 4; ni++) {
                    asm volatile(
                        "mma.sync.aligned.m16n8k8.row.col.f32.tf32.tf32.f32 "
                        "{%0,%1,%2,%3}, {%4,%5,%6,%7}, {%8,%9}, {%0,%1,%2,%3};"
                        : "+f"(acc[mi][ni][0]), "+f"(acc[mi][ni][1]),
                          "+f"(acc[mi][ni][2]), "+f"(acc[mi][ni][3])
                        : "r"(af[mi][0]), "r"(af[mi][1]), "r"(af[mi][2]), "r"(af[mi][3]),
                          "r"(bf[ni][0]), "r"(bf[ni][1]));
                }
        }
        __syncthreads();
    }

    // ---- epilogue ----
#pragma unroll
    for (int mi = 0; mi < 2; mi++) {
#pragma unroll
        for (int ni = 0; ni < 4; ni++) {
#pragma unroll
            for (int h = 0; h < 2; h++) {
                int r = row0 + wm * 32 + mi * 16 + grp + h * 8;
                int cc = col0 + wn * 32 + ni * 8 + tig * 2;
                float v0 = acc[mi][ni][h * 2 + 0];
                float v1 = acc[mi][ni][h * 2 + 1];
                if (cc < N) {
                    long long o = (long long)r * N + cc;
                    if (Res) { v0 += Res[o]; v1 += Res[o + 1]; }
                    C[o] = v0; C[o + 1] = v1;
                }
            }
        }
    }
}

// ------------------------- rmsnorm -------------------------
__global__ void rmsnorm_k(const float* __restrict__ in, const float* __restrict__ w,
                          float* __restrict__ out, int cols, int in_ld, int out_ld, float eps)
{
    const long long row = blockIdx.x;
    const float* ip = in + row * in_ld;
    float* op = out + row * out_ld;

    float ss = 0.f;
    for (int j = threadIdx.x; j < cols; j += blockDim.x) {
        float v = ip[j];
        ss += v * v;
    }
    __shared__ float sh[32];
    int lane = threadIdx.x & 31, wid = threadIdx.x >> 5;
#pragma unroll
    for (int o = 16; o; o >>= 1) ss += __shfl_xor_sync(0xffffffffu, ss, o);
    if (lane == 0) sh[wid] = ss;
    __syncthreads();
    int nw = (blockDim.x + 31) >> 5;
    float tot = 0.f;
    if (threadIdx.x < nw) tot = sh[threadIdx.x];
    if (wid == 0) {
#pragma unroll
        for (int o = 16; o; o >>= 1) tot += __shfl_xor_sync(0xffffffffu, tot, o);
        if (lane == 0) sh[0] = tot;
    }
    __syncthreads();
    float inv = rsqrtf(sh[0] / (float)cols + eps);
    for (int j = threadIdx.x; j < cols; j += blockDim.x)
        op[j] = ip[j] * inv * w[j];
}

// ------------------------- build Q/K/V with RoPE (Q/K padded to 64) --------
__global__ void build_qkv_k(const float* __restrict__ qf, const float* __restrict__ kvup,
                            const float* __restrict__ ckv,
                            const float* __restrict__ fcos, const float* __restrict__ fsin,
                            float* __restrict__ Q, float* __restrict__ K, float* __restrict__ V)
{
    const int i = blockIdx.x;                 // token
    const int tid = threadIdx.x;              // 128
    __shared__ float cs[8], sn[8];
    int p = i >> 2;                           // rope position = i // NUM_SEQ
    if (tid < 8) {
        if (p == 0) { cs[tid] = 1.f; sn[tid] = 0.f; }
        else { cs[tid] = fcos[(p - 1) * 8 + tid]; sn[tid] = fsin[(p - 1) * 8 + tid]; }
    }
    __syncthreads();

    const float* qrow = qf + (long long)i * 1536;
    const float* krow = kvup + (long long)i * 2048;
    const float* crow = ckv + (long long)i * (KVCC + ROPE_);

    for (int e = tid; e < H2 * DQKP; e += 128) {
        int h2 = e / DQKP, d = e % DQKP;
        int h = h2 >> 1, c = h2 & 1;
        float qv = 0.f, kv = 0.f;
        if (d < 32) {
            qv = qrow[h * 96 + c * 32 + d];
            kv = krow[h * 128 + c * 32 + d];
        } else if (d < DQK) {
            int ee = d - 32;
            int f = ee >> 1;
            float q0 = qrow[h * 96 + 64 + c * 16 + 2 * f];
            float q1 = qrow[h * 96 + 64 + c * 16 + 2 * f + 1];
            float k0 = crow[KVCC + c * 16 + 2 * f];
            float k1 = crow[KVCC + c * 16 + 2 * f + 1];
            float C = cs[f], Sv = sn[f];
            if ((ee & 1) == 0) { qv = q0 * C - q1 * Sv; kv = k0 * C - k1 * Sv; }
            else               { qv = q0 * Sv + q1 * C; kv = k0 * Sv + k1 * C; }
        }
        Q[(long long)h2 * S_LEN * DQKP + (long long)i * DQKP + d] = qv;
        K[(long long)h2 * S_LEN * DQKP + (long long)i * DQKP + d] = kv;
    }
    for (int e = tid; e < NH * HD; e += 128) {
        int h = e >> 6, d = e & 63;
        V[(long long)h * S_LEN * HD + (long long)i * HD + d] = krow[h * 128 + 64 + d];
    }
}

// ------------------------- softmax with fused scale+mask -------------------------
__global__ void softmax_k(float* __restrict__ P)
{
    const long long rowi = blockIdx.x;         // 0 .. H2*S-1
    const int r = (int)(rowi % S_LEN);
    float* row = P + rowi * S_LEN;
    const int rp = r % SPP;

    __shared__ float sh[32];
    int lane = threadIdx.x & 31, wid = threadIdx.x >> 5;

    // pass 1: max
    float mx = -3.4e38f;
    for (int j = threadIdx.x; j < S_LEN; j += 256) {
        float v = ((j % SPP) > rp) ? -1e9f : row[j] * SCALING;
        mx = fmaxf(mx, v);
    }
#pragma unroll
    for (int o = 16; o; o >>= 1) mx = fmaxf(mx, __shfl_xor_sync(0xffffffffu, mx, o));
    if (lane == 0) sh[wid] = mx;
    __syncthreads();
    float gmx = -3.4e38f;
    if (threadIdx.x < 8) gmx = sh[threadIdx.x];
    if (wid == 0) {
#pragma unroll
        for (int o = 16; o; o >>= 1) gmx = fmaxf(gmx, __shfl_xor_sync(0xffffffffu, gmx, o));
        if (lane == 0) sh[0] = gmx;
    }
    __syncthreads();
    gmx = sh[0];
    __syncthreads();

    // pass 2: exp + sum
    float sum = 0.f;
    for (int j = threadIdx.x; j < S_LEN; j += 256) {
        float v = ((j % SPP) > rp) ? -1e9f : row[j] * SCALING;
        float e = __expf(v - gmx);
        row[j] = e;
        sum += e;
    }
#pragma unroll
    for (int o = 16; o; o >>= 1) sum += __shfl_xor_sync(0xffffffffu, sum, o);
    if (lane == 0) sh[wid] = sum;
    __syncthreads();
    float gs = 0.f;
    if (threadIdx.x < 8) gs = sh[threadIdx.x];
    if (wid == 0) {
#pragma unroll
        for (int o = 16; o; o >>= 1) gs += __shfl_xor_sync(0xffffffffu, gs, o);
        if (lane == 0) sh[0] = gs;
    }
    __syncthreads();
    float inv = 1.f / sh[0];

    // pass 3: normalize
    for (int j = threadIdx.x; j < S_LEN; j += 256)
        row[j] *= inv;
}

// ------------------------- column mean of even sub-heads -------------------------
__global__ void colmean_k(const float* __restrict__ P, float* __restrict__ g)
{
    int j = blockIdx.x * blockDim.x + threadIdx.x;
    int h = blockIdx.y;
    if (j >= S_LEN) return;
    const float* base = P + (long long)(2 * h) * S_LEN * S_LEN + j;
    float s = 0.f;
    for (int i = 0; i < S_LEN; i++) s += base[(long long)i * S_LEN];
    g[h * S_LEN + j] = s / (float)S_LEN;
}

// ------------------------- lambda scalar -------------------------
__global__ void lambda_k_(const float* __restrict__ q1, const float* __restrict__ k1,
                          const float* __restrict__ q2, const float* __restrict__ k2,
                          float* __restrict__ out)
{
    int t = threadIdx.x;  // 32
    float a = q1[t] * k1[t];
    float b = q2[t] * k2[t];
#pragma unroll
    for (int o = 16; o; o >>= 1) {
        a += __shfl_xor_sync(0xffffffffu, a, o);
        b += __shfl_xor_sync(0xffffffffu, b, o);
    }
    if (t == 0) *out = expf(a) - expf(b) + LAMBDA_INIT;
}

// ------------------------- differential combine (in-place into even head) -----
__global__ void combine_k(float* __restrict__ P, const float* __restrict__ g,
                          const float* __restrict__ lamp)
{
    long long idx = (long long)blockIdx.x * blockDim.x + threadIdx.x;
    if (idx >= (long long)S_LEN * S_LEN) return;
    int h = blockIdx.y;
    int i = (int)(idx / S_LEN), j = (int)(idx % S_LEN);
    float* p1 = P + (long long)(2 * h) * S_LEN * S_LEN;
    const float* p2 = P + (long long)(2 * h + 1) * S_LEN * S_LEN;
    float v;
    if ((j % SPP) > (i % SPP)) v = 0.f;
    else {
        float lam = *lamp;
        v = p1[idx] - lam * p2[idx] + lam * g[h * S_LEN + j];
    }
    p1[idx] = v;
}

// ------------------------- per (token, head) rmsnorm -------------------------
// Reference reshapes (b, NH, s, HD) memory directly as (b, s, NH*HD): keep
// [h][i][d] layout; o_w GEMM reads this buffer as [S_LEN][DM] row-major.
__global__ void attn_norm_k(const float* __restrict__ ao, const float* __restrict__ w,
                            float* __restrict__ outf)
{
    int i = blockIdx.x, h = blockIdx.y, d = threadIdx.x;  // 64 threads
    long long idx = ((long long)h * S_LEN + i) * HD + d;
    float v = ao[idx];
    float sq = v * v;
    __shared__ float sh[2];
#pragma unroll
    for (int o = 16; o; o >>= 1) sq += __shfl_xor_sync(0xffffffffu, sq, o);
    if ((d & 31) == 0) sh[d >> 5] = sq;
    __syncthreads();
    float tot = sh[0] + sh[1];
    outf[idx] = v * rsqrtf(tot / (float)HD + ATTN_EPS) * w[d];
}

// ------------------------- SwiGLU -------------------------
__global__ void swiglu_k(const float* __restrict__ uv, float* __restrict__ act)
{
    long long idx = (long long)blockIdx.x * blockDim.x + threadIdx.x;
    if (idx >= (long long)S_LEN * DFF) return;
    long long i = idx / DFF, j = idx % DFF;
    float u = uv[i * (2 * DFF) + j];
    float vg = uv[i * (2 * DFF) + DFF + j];
    act[idx] = u * (vg / (1.f + __expf(-vg)));
}

// ------------------------- host -------------------------
extern "C" void kernel_launch(void* const* d_in, const int* in_sizes, int n_in,
                              void* d_out, int out_size)
{
    const float* x    = (const float*)d_in[0];
    const float* fc   = (const float*)d_in[1];
    const float* fs   = (const float*)d_in[2];
    const float* n1w  = (const float*)d_in[3];
    const float* n2w  = (const float*)d_in[4];
    const float* kvdw = (const float*)d_in[5];
    const float* qdw  = (const float*)d_in[6];
    const float* kvnw = (const float*)d_in[7];
    const float* qnw  = (const float*)d_in[8];
    const float* kvuw = (const float*)d_in[9];
    const float* quw  = (const float*)d_in[10];
    const float* lq1  = (const float*)d_in[11];
    const float* lk1  = (const float*)d_in[12];
    const float* lq2  = (const float*)d_in[13];
    const float* lk2  = (const float*)d_in[14];
    const float* anw  = (const float*)d_in[15];
    const float* ow   = (const float*)d_in[16];
    const float* fiw  = (const float*)d_in[17];
    const float* fow  = (const float*)d_in[18];
    float* outp = (float*)d_out;

    float *xin, *ckv, *ckvn, *kvup, *cq, *cqn, *qf, *Q, *K, *V, *P, *gg, *ao, *af, *x2, *hb, *uv, *act, *lam;
    cudaGetSymbolAddress((void**)&xin,  g_xin);
    cudaGetSymbolAddress((void**)&ckv,  g_ckv);
    cudaGetSymbolAddress((void**)&ckvn, g_ckvn);
    cudaGetSymbolAddress((void**)&kvup, g_kvup);
    cudaGetSymbolAddress((void**)&cq,   g_cq);
    cudaGetSymbolAddress((void**)&cqn,  g_cqn);
    cudaGetSymbolAddress((void**)&qf,   g_qf);
    cudaGetSymbolAddress((void**)&Q,    g_Q);
    cudaGetSymbolAddress((void**)&K,    g_K);
    cudaGetSymbolAddress((void**)&V,    g_V);
    cudaGetSymbolAddress((void**)&P,    g_P);
    cudaGetSymbolAddress((void**)&gg,   g_g);
    cudaGetSymbolAddress((void**)&ao,   g_ao);
    cudaGetSymbolAddress((void**)&af,   g_af);
    cudaGetSymbolAddress((void**)&x2,   g_x2);
    cudaGetSymbolAddress((void**)&hb,   g_hb);
    cudaGetSymbolAddress((void**)&uv,   g_uv);
    cudaGetSymbolAddress((void**)&act,  g_act);
    cudaGetSymbolAddress((void**)&lam,  g_lambda);

    auto grid_for = [](int M, int N, int batch) {
        return dim3((unsigned)((N + TBN - 1) / TBN), (unsigned)(M / TBM), (unsigned)batch);
    };

    // 1. xin = rmsnorm(x, norm1_w)
    rmsnorm_k<<<S_LEN, 256>>>(x, n1w, xin, DM, DM, DM, EPS_RMS);
    // 2. ckv = xin @ kv_down_w^T  [1536, 288]
    tgemm_k<true><<<grid_for(S_LEN, KVCC + ROPE_, 1), 256>>>(xin, kvdw, nullptr, ckv,
        S_LEN, KVCC + ROPE_, DM, 0, 0, 0);
    // 3. ckvn = rmsnorm(ckv[:, :256])
    rmsnorm_k<<<S_LEN, 256>>>(ckv, kvnw, ckvn, KVCC, KVCC + ROPE_, KVCC, EPS_RMS);
    // 4. kvup = ckvn @ kv_up_w^T  [1536, 2048]
    tgemm_k<true><<<grid_for(S_LEN, 2048, 1), 256>>>(ckvn, kvuw, nullptr, kvup,
        S_LEN, 2048, KVCC, 0, 0, 0);
    // 5. cq = xin @ q_down_w^T [1536, 384]
    tgemm_k<true><<<grid_for(S_LEN, QCC, 1), 256>>>(xin, qdw, nullptr, cq,
        S_LEN, QCC, DM, 0, 0, 0);
    // 6. cqn = rmsnorm(cq)
    rmsnorm_k<<<S_LEN, 256>>>(cq, qnw, cqn, QCC, QCC, QCC, EPS_RMS);
    // 7. qf = cqn @ q_up_w^T [1536, 1536]
    tgemm_k<true><<<grid_for(S_LEN, 1536, 1), 256>>>(cqn, quw, nullptr, qf,
        S_LEN, 1536, QCC, 0, 0, 0);
    // 8. build Q/K/V with RoPE (Q/K padded to 64 cols)
    build_qkv_k<<<S_LEN, 128>>>(qf, kvup, ckv, fc, fs, Q, K, V);
    // 9. logits: P[h] = Q[h] @ K[h]^T, batched over 32 sub-heads, K=64 (padded)
    tgemm_k<true><<<grid_for(S_LEN, S_LEN, H2), 256>>>(Q, K, nullptr, P,
        S_LEN, S_LEN, DQKP,
        (long long)S_LEN * DQKP, (long long)S_LEN * DQKP, (long long)S_LEN * S_LEN);
    // 10. lambda scalar
    lambda_k_<<<1, 32>>>(lq1, lk1, lq2, lk2, lam);
    // 11. softmax rows (fused scale + mask)
    softmax_k<<<H2 * S_LEN, 256>>>(P);
    // 12. column means of even sub-heads
    colmean_k<<<dim3((S_LEN + 255) / 256, NH), 256>>>(P, gg);
    // 13. differential combine (in place into even sub-head slot)
    {
        long long tot = (long long)S_LEN * S_LEN;
        combine_k<<<dim3((unsigned)((tot + 255) / 256), NH), 256>>>(P, gg, lam);
    }
    // 14. ao[h] = Pdiff[h] @ V[h], batched over 16 heads (NN gemm)
    tgemm_k<false><<<grid_for(S_LEN, HD, NH), 256>>>(P, V, nullptr, ao,
        S_LEN, HD, S_LEN,
        (long long)2 * S_LEN * S_LEN, (long long)S_LEN * HD, (long long)S_LEN * HD);
    // 15. per (token, head) rmsnorm -> af (same [h][i][d] layout)
    attn_norm_k<<<dim3(S_LEN, NH), 64>>>(ao, anw, af);
    // 16. x2 = x + af @ o_w^T
    tgemm_k<true><<<grid_for(S_LEN, DM, 1), 256>>>(af, ow, x, x2,
        S_LEN, DM, DM, 0, 0, 0);
    // 17. hb = rmsnorm(x2, norm2_w)
    rmsnorm_k<<<S_LEN, 256>>>(x2, n2w, hb, DM, DM, DM, EPS_RMS);
    // 18. uv = hb @ ff_in_w^T [1536, 8192]
    tgemm_k<true><<<grid_for(S_LEN, 2 * DFF, 1), 256>>>(hb, fiw, nullptr, uv,
        S_LEN, 2 * DFF, DM, 0, 0, 0);
    // 19. act = u * silu(vg)
    {
        long long tot = (long long)S_LEN * DFF;
        swiglu_k<<<(unsigned)((tot + 255) / 256), 256>>>(uv, act);
    }
    // 20. out = x2 + act @ ff_out_w^T
    tgemm_k<true><<<grid_for(S_LEN, DM, 1), 256>>>(act, fow, x2, outp,
        S_LEN, DM, DFF, 0, 0, 0);
}

// round 4
// speedup vs baseline: 4.1971x; 1.4329x over previous
#include <cuda_runtime.h>
#include <math.h>

#define S_LEN 1536
#define DM    1024
#define NH    16
#define HD    64
#define H2    32
#define DQK   48
#define DQKP  64      /* padded */
#define KVCC  256
#define ROPE_ 32
#define QCC   384
#define DFF   4096
#define SPP   384
#define EPS_RMS 1.1920929e-07f
#define ATTN_EPS 1e-5f
#define SCALING 0.14433756729740643f  /* 48^-0.5 */
#define LAMBDA_INIT 0.2f

// ------------------------- device scratch -------------------------
__device__ float g_xin [S_LEN * DM];
__device__ float g_ckv [S_LEN * (KVCC + ROPE_)];
__device__ float g_ckvn[S_LEN * KVCC];
__device__ float g_kvup[S_LEN * 2048];
__device__ float g_cq  [S_LEN * QCC];
__device__ float g_cqn [S_LEN * QCC];
__device__ float g_qf  [S_LEN * 1536];
__device__ float g_Q   [(size_t)H2 * S_LEN * DQKP];
__device__ float g_K   [(size_t)H2 * S_LEN * DQKP];
__device__ float g_V   [(size_t)NH * S_LEN * HD];
__device__ float g_P   [(size_t)H2 * S_LEN * S_LEN];   // ~302 MB
__device__ float g_g   [NH * S_LEN];
__device__ float g_ao  [(size_t)NH * S_LEN * HD];
__device__ float g_af  [S_LEN * DM];
__device__ float g_x2  [S_LEN * DM];
__device__ float g_hb  [S_LEN * DM];
__device__ float g_uv  [(size_t)S_LEN * 2 * DFF];
__device__ float g_act [(size_t)S_LEN * DFF];
__device__ float g_lambda;

// ------------------------- helpers -------------------------
__device__ __forceinline__ unsigned f2tf32(float x) {
    unsigned r;
    asm("cvt.rna.tf32.f32 %0, %1;" : "=r"(r) : "f"(x));
    return r;
}
__device__ __forceinline__ void cpa16(float* smem_dst, const float* gsrc, bool pred) {
    unsigned a = (unsigned)__cvta_generic_to_shared(smem_dst);
    asm volatile("cp.async.ca.shared.global [%0], [%1], 16, %2;\n"
                 :: "r"(a), "l"(gsrc), "r"(pred ? 16 : 0));
}
__device__ __forceinline__ void cpa_commit() { asm volatile("cp.async.commit_group;\n"); }
template <int NG>
__device__ __forceinline__ void cpa_wait() { asm volatile("cp.async.wait_group %0;\n" :: "n"(NG)); }

#define MMA_TF32(d, a, b) \
    asm volatile( \
        "mma.sync.aligned.m16n8k8.row.col.f32.tf32.tf32.f32 " \
        "{%0,%1,%2,%3}, {%4,%5,%6,%7}, {%8,%9}, {%0,%1,%2,%3};" \
        : "+f"(d[0]), "+f"(d[1]), "+f"(d[2]), "+f"(d[3]) \
        : "r"(a[0]), "r"(a[1]), "r"(a[2]), "r"(a[3]), "r"(b[0]), "r"(b[1]))

// ------------------------- TF32 tensor-core GEMM (TB only) -------------------------
// C[M,N] = A[M,K] * B^T (+ Res), B is [N,K] row-major. Batched via grid.z.
// M % 128 == 0, K % 32 == 0. N arbitrary (guarded per 64-col tile).
#define TBM 128
#define TBN 64
#define TBK 32
#define ASTR 36
#define SMEM_T (2 * (TBM + TBN) * ASTR * 4)

__global__ __launch_bounds__(256, 2)
void tgemm_k(const float* __restrict__ A, const float* __restrict__ B,
             const float* __restrict__ Res, float* __restrict__ C,
             int M, int N, int K,
             long long sA, long long sB, long long sC)
{
    extern __shared__ float sm[];
    float* AsB = sm;                      // [2][TBM*ASTR]
    float* BsB = sm + 2 * TBM * ASTR;     // [2][TBN*ASTR]

    A += (long long)blockIdx.z * sA;
    B += (long long)blockIdx.z * sB;
    C += (long long)blockIdx.z * sC;

    const int tid  = threadIdx.x;
    const int lane = tid & 31;
    const int warp = tid >> 5;
    const int wm   = warp >> 1;
    const int wn   = warp & 1;
    const int row0 = blockIdx.y * TBM;
    const int col0 = blockIdx.x * TBN;
    const int grp  = lane >> 2;
    const int tig  = lane & 3;

    const int nk = K / TBK;

    auto load_tiles = [&](int ki, int buf) {
        const float* Ab = A + (long long)row0 * K + ki * TBK;
        float* Ad = AsB + buf * TBM * ASTR;
#pragma unroll
        for (int it = 0; it < 4; it++) {
            int f4 = tid + it * 256;
            int r = f4 >> 3, c4 = f4 & 7;
            cpa16(Ad + r * ASTR + c4 * 4, Ab + (long long)r * K + c4 * 4, true);
        }
        float* Bd = BsB + buf * TBN * ASTR;
#pragma unroll
        for (int it = 0; it < 2; it++) {
            int f4 = tid + it * 256;
            int n = f4 >> 3, c4 = f4 & 7;
            bool p = (col0 + n) < N;
            const float* src = B + (long long)(p ? (col0 + n) : 0) * K + ki * TBK + c4 * 4;
            cpa16(Bd + n * ASTR + c4 * 4, src, p);
        }
    };

    float acc[2][4][4];
#pragma unroll
    for (int i = 0; i < 2; i++)
#pragma unroll
        for (int j = 0; j < 4; j++)
#pragma unroll
            for (int l = 0; l < 4; l++) acc[i][j][l] = 0.f;

    load_tiles(0, 0);
    cpa_commit();

    for (int i = 0; i < nk; i++) {
        int cur = i & 1;
        if (i + 1 < nk) { load_tiles(i + 1, cur ^ 1); cpa_commit(); cpa_wait<1>(); }
        else            { cpa_wait<0>(); }
        __syncthreads();

        const float* Ab = AsB + cur * TBM * ASTR;
        const float* Bb = BsB + cur * TBN * ASTR;
#pragma unroll
        for (int kk = 0; kk < TBK; kk += 8) {
            unsigned af[2][4], bf[4][2];
#pragma unroll
            for (int mi = 0; mi < 2; mi++) {
                int r = wm * 32 + mi * 16 + grp;
                int c = kk + tig;
                af[mi][0] = f2tf32(Ab[r * ASTR + c]);
                af[mi][1] = f2tf32(Ab[(r + 8) * ASTR + c]);
                af[mi][2] = f2tf32(Ab[r * ASTR + c + 4]);
                af[mi][3] = f2tf32(Ab[(r + 8) * ASTR + c + 4]);
            }
#pragma unroll
            for (int ni = 0; ni < 4; ni++) {
                int n = wn * 32 + ni * 8 + grp;
                int c = kk + tig;
                bf[ni][0] = f2tf32(Bb[n * ASTR + c]);
                bf[ni][1] = f2tf32(Bb[n * ASTR + c + 4]);
            }
#pragma unroll
            for (int mi = 0; mi < 2; mi++)
#pragma unroll
                for (int ni = 0; ni < 4; ni++)
                    MMA_TF32(acc[mi][ni], af[mi], bf[ni]);
        }
        __syncthreads();
    }

#pragma unroll
    for (int mi = 0; mi < 2; mi++)
#pragma unroll
        for (int ni = 0; ni < 4; ni++)
#pragma unroll
            for (int h = 0; h < 2; h++) {
                int r = row0 + wm * 32 + mi * 16 + grp + h * 8;
                int cc = col0 + wn * 32 + ni * 8 + tig * 2;
                if (cc < N) {
                    float v0 = acc[mi][ni][h * 2 + 0];
                    float v1 = acc[mi][ni][h * 2 + 1];
                    long long o = (long long)r * N + cc;
                    if (Res) { v0 += Res[o]; v1 += Res[o + 1]; }
                    C[o] = v0; C[o + 1] = v1;
                }
            }
}

// ------------------------- fused differential-combine + AV GEMM -------------------
// ao[h] = Pdiff[h] @ V[h]; Pdiff = mask ? 0 : p1 - lam*p2 + lam*g[h][j]
// 64-row M tiles, N = 64 (full), K = S_LEN in steps of 32.
#define AVM 64
#define BSTR 72

__global__ __launch_bounds__(256)
void av_k(const float* __restrict__ P, const float* __restrict__ V,
          const float* __restrict__ g, const float* __restrict__ lamp,
          float* __restrict__ O)
{
    __shared__ float As[AVM * ASTR];     // 64 x 32 diff tile
    __shared__ float Bs[TBK * BSTR];     // 32 x 64 V tile [k][n]

    const int h    = blockIdx.y;
    const int row0 = blockIdx.x * AVM;
    const int tid  = threadIdx.x;
    const int lane = tid & 31;
    const int warp = tid >> 5;
    const int wm   = warp >> 1;          // 0..3 -> 16-row slices
    const int wn   = warp & 1;           // 0..1 -> 32-col slices
    const int grp  = lane >> 2;
    const int tig  = lane & 3;

    const float lam = *lamp;
    const float* p1 = P + (long long)(2 * h) * S_LEN * S_LEN;
    const float* p2 = P + (long long)(2 * h + 1) * S_LEN * S_LEN;
    const float* Vh = V + (long long)h * S_LEN * HD;
    const float* gh = g + h * S_LEN;

    float acc[4][4];
#pragma unroll
    for (int j = 0; j < 4; j++)
#pragma unroll
        for (int l = 0; l < 4; l++) acc[j][l] = 0.f;

    for (int j0 = 0; j0 < S_LEN; j0 += TBK) {
        // V tile via cp.async: 32 rows x 64 cols = 512 f4, 2 per thread
#pragma unroll
        for (int it = 0; it < 2; it++) {
            int f4 = tid + it * 256;
            int k = f4 >> 4, c4 = f4 & 15;
            cpa16(&Bs[k * BSTR + c4 * 4], Vh + (long long)(j0 + k) * HD + c4 * 4, true);
        }
        cpa_commit();

        // A (diff) tile: 64 rows x 32 cols = 512 f4, 2 per thread
#pragma unroll
        for (int it = 0; it < 2; it++) {
            int f4 = tid + it * 256;
            int r = f4 >> 3, c4 = f4 & 7;
            int i = row0 + r;
            int ip = i % SPP;
            long long off = (long long)i * S_LEN + j0 + c4 * 4;
            float4 a1 = *(const float4*)(p1 + off);
            float4 a2 = *(const float4*)(p2 + off);
            float out[4];
            int jb = j0 + c4 * 4;
#pragma unroll
            for (int e = 0; e < 4; e++) {
                int j = jb + e;
                float v1 = e == 0 ? a1.x : e == 1 ? a1.y : e == 2 ? a1.z : a1.w;
                float v2 = e == 0 ? a2.x : e == 1 ? a2.y : e == 2 ? a2.z : a2.w;
                out[e] = ((j % SPP) > ip) ? 0.f : (v1 - lam * v2 + lam * gh[j]);
            }
            float* dst = &As[r * ASTR + c4 * 4];
            dst[0] = out[0]; dst[1] = out[1]; dst[2] = out[2]; dst[3] = out[3];
        }
        cpa_wait<0>();
        __syncthreads();

#pragma unroll
        for (int kk = 0; kk < TBK; kk += 8) {
            unsigned af[4], bf[4][2];
            {
                int r = wm * 16 + grp;
                int c = kk + tig;
                af[0] = f2tf32(As[r * ASTR + c]);
                af[1] = f2tf32(As[(r + 8) * ASTR + c]);
                af[2] = f2tf32(As[r * ASTR + c + 4]);
                af[3] = f2tf32(As[(r + 8) * ASTR + c + 4]);
            }
#pragma unroll
            for (int ni = 0; ni < 4; ni++) {
                int n = wn * 32 + ni * 8 + grp;
                int c = kk + tig;
                bf[ni][0] = f2tf32(Bs[c * BSTR + n]);
                bf[ni][1] = f2tf32(Bs[(c + 4) * BSTR + n]);
            }
#pragma unroll
            for (int ni = 0; ni < 4; ni++)
                MMA_TF32(acc[ni], af, bf[ni]);
        }
        __syncthreads();
    }

#pragma unroll
    for (int ni = 0; ni < 4; ni++)
#pragma unroll
        for (int hh = 0; hh < 2; hh++) {
            int r = row0 + wm * 16 + grp + hh * 8;
            int cc = wn * 32 + ni * 8 + tig * 2;
            long long o = ((long long)h * S_LEN + r) * HD + cc;
            O[o]     = acc[ni][hh * 2 + 0];
            O[o + 1] = acc[ni][hh * 2 + 1];
        }
}

// ------------------------- rmsnorm -------------------------
__global__ void rmsnorm_k(const float* __restrict__ in, const float* __restrict__ w,
                          float* __restrict__ out, int cols, int in_ld, int out_ld, float eps)
{
    const long long row = blockIdx.x;
    const float* ip = in + row * in_ld;
    float* op = out + row * out_ld;

    float ss = 0.f;
    for (int j = threadIdx.x; j < cols; j += blockDim.x) {
        float v = ip[j];
        ss += v * v;
    }
    __shared__ float sh[32];
    int lane = threadIdx.x & 31, wid = threadIdx.x >> 5;
#pragma unroll
    for (int o = 16; o; o >>= 1) ss += __shfl_xor_sync(0xffffffffu, ss, o);
    if (lane == 0) sh[wid] = ss;
    __syncthreads();
    int nw = (blockDim.x + 31) >> 5;
    float tot = 0.f;
    if (threadIdx.x < nw) tot = sh[threadIdx.x];
    if (wid == 0) {
#pragma unroll
        for (int o = 16; o; o >>= 1) tot += __shfl_xor_sync(0xffffffffu, tot, o);
        if (lane == 0) sh[0] = tot;
    }
    __syncthreads();
    float inv = rsqrtf(sh[0] / (float)cols + eps);
    for (int j = threadIdx.x; j < cols; j += blockDim.x)
        op[j] = ip[j] * inv * w[j];
}

// ------------------------- build Q/K/V with RoPE (Q/K padded to 64) --------
__global__ void build_qkv_k(const float* __restrict__ qf, const float* __restrict__ kvup,
                            const float* __restrict__ ckv,
                            const float* __restrict__ fcos, const float* __restrict__ fsin,
                            float* __restrict__ Q, float* __restrict__ K, float* __restrict__ V)
{
    const int i = blockIdx.x;                 // token
    const int tid = threadIdx.x;              // 128
    __shared__ float cs[8], sn[8];
    int p = i >> 2;                           // rope position = i // NUM_SEQ
    if (tid < 8) {
        if (p == 0) { cs[tid] = 1.f; sn[tid] = 0.f; }
        else { cs[tid] = fcos[(p - 1) * 8 + tid]; sn[tid] = fsin[(p - 1) * 8 + tid]; }
    }
    __syncthreads();

    const float* qrow = qf + (long long)i * 1536;
    const float* krow = kvup + (long long)i * 2048;
    const float* crow = ckv + (long long)i * (KVCC + ROPE_);

    for (int e = tid; e < H2 * DQKP; e += 128) {
        int h2 = e / DQKP, d = e % DQKP;
        int h = h2 >> 1, c = h2 & 1;
        float qv = 0.f, kv = 0.f;
        if (d < 32) {
            qv = qrow[h * 96 + c * 32 + d];
            kv = krow[h * 128 + c * 32 + d];
        } else if (d < DQK) {
            int ee = d - 32;
            int f = ee >> 1;
            float q0 = qrow[h * 96 + 64 + c * 16 + 2 * f];
            float q1 = qrow[h * 96 + 64 + c * 16 + 2 * f + 1];
            float k0 = crow[KVCC + c * 16 + 2 * f];
            float k1 = crow[KVCC + c * 16 + 2 * f + 1];
            float C = cs[f], Sv = sn[f];
            if ((ee & 1) == 0) { qv = q0 * C - q1 * Sv; kv = k0 * C - k1 * Sv; }
            else               { qv = q0 * Sv + q1 * C; kv = k0 * Sv + k1 * C; }
        }
        Q[(long long)h2 * S_LEN * DQKP + (long long)i * DQKP + d] = qv;
        K[(long long)h2 * S_LEN * DQKP + (long long)i * DQKP + d] = kv;
    }
    for (int e = tid; e < NH * HD; e += 128) {
        int h = e >> 6, d = e & 63;
        V[(long long)h * S_LEN * HD + (long long)i * HD + d] = krow[h * 128 + 64 + d];
    }
}

// ------------------------- register softmax (1 read + 1 write) -----------------
__global__ __launch_bounds__(256)
void softmax2_k(float* __restrict__ P)
{
    const long long rowi = blockIdx.x;         // 0 .. H2*S-1
    const int r = (int)(rowi % S_LEN);
    float* row = P + rowi * S_LEN;
    const int rp = r % SPP;
    const int tid = threadIdx.x;

    __shared__ float sh[32];
    int lane = tid & 31, wid = tid >> 5;

    float v[6];
    bool msk[6];
#pragma unroll
    for (int l = 0; l < 6; l++) {
        int j = tid + l * 256;
        msk[l] = (j % SPP) > rp;
        v[l] = msk[l] ? -3.4e38f : row[j] * SCALING;
    }
    float mx = v[0];
#pragma unroll
    for (int l = 1; l < 6; l++) mx = fmaxf(mx, v[l]);
#pragma unroll
    for (int o = 16; o; o >>= 1) mx = fmaxf(mx, __shfl_xor_sync(0xffffffffu, mx, o));
    if (lane == 0) sh[wid] = mx;
    __syncthreads();
    float gmx = sh[lane & 7];
#pragma unroll
    for (int o = 4; o; o >>= 1) gmx = fmaxf(gmx, __shfl_xor_sync(0xffffffffu, gmx, o));

    float sum = 0.f;
#pragma unroll
    for (int l = 0; l < 6; l++) {
        float e = msk[l] ? 0.f : __expf(v[l] - gmx);
        v[l] = e;
        sum += e;
    }
#pragma unroll
    for (int o = 16; o; o >>= 1) sum += __shfl_xor_sync(0xffffffffu, sum, o);
    __syncthreads();
    if (lane == 0) sh[wid] = sum;
    __syncthreads();
    float gs = sh[lane & 7];
#pragma unroll
    for (int o = 4; o; o >>= 1) gs += __shfl_xor_sync(0xffffffffu, gs, o);
    float inv = 1.f / gs;

#pragma unroll
    for (int l = 0; l < 6; l++)
        row[tid + l * 256] = v[l] * inv;
}

// ------------------------- column mean of even sub-heads -------------------------
__global__ void colmean_k(const float* __restrict__ P, float* __restrict__ g)
{
    int j = blockIdx.x * blockDim.x + threadIdx.x;
    int h = blockIdx.y;
    if (j >= S_LEN) return;
    const float* base = P + (long long)(2 * h) * S_LEN * S_LEN + j;
    float s = 0.f;
    for (int i = 0; i < S_LEN; i++) s += base[(long long)i * S_LEN];
    g[h * S_LEN + j] = s / (float)S_LEN;
}

// ------------------------- lambda scalar -------------------------
__global__ void lambda_k_(const float* __restrict__ q1, const float* __restrict__ k1,
                          const float* __restrict__ q2, const float* __restrict__ k2,
                          float* __restrict__ out)
{
    int t = threadIdx.x;  // 32
    float a = q1[t] * k1[t];
    float b = q2[t] * k2[t];
#pragma unroll
    for (int o = 16; o; o >>= 1) {
        a += __shfl_xor_sync(0xffffffffu, a, o);
        b += __shfl_xor_sync(0xffffffffu, b, o);
    }
    if (t == 0) *out = expf(a) - expf(b) + LAMBDA_INIT;
}

// ------------------------- per (token, head) rmsnorm -------------------------
// Reference reshapes (b, NH, s, HD) memory directly as (b, s, NH*HD): keep
// [h][i][d] layout; o_w GEMM reads this buffer as [S_LEN][DM] row-major.
__global__ void attn_norm_k(const float* __restrict__ ao, const float* __restrict__ w,
                            float* __restrict__ outf)
{
    int i = blockIdx.x, h = blockIdx.y, d = threadIdx.x;  // 64 threads
    long long idx = ((long long)h * S_LEN + i) * HD + d;
    float v = ao[idx];
    float sq = v * v;
    __shared__ float sh[2];
#pragma unroll
    for (int o = 16; o; o >>= 1) sq += __shfl_xor_sync(0xffffffffu, sq, o);
    if ((d & 31) == 0) sh[d >> 5] = sq;
    __syncthreads();
    float tot = sh[0] + sh[1];
    outf[idx] = v * rsqrtf(tot / (float)HD + ATTN_EPS) * w[d];
}

// ------------------------- SwiGLU -------------------------
__global__ void swiglu_k(const float* __restrict__ uv, float* __restrict__ act)
{
    long long idx = (long long)blockIdx.x * blockDim.x + threadIdx.x;
    if (idx >= (long long)S_LEN * DFF) return;
    long long i = idx / DFF, j = idx % DFF;
    float u = uv[i * (2 * DFF) + j];
    float vg = uv[i * (2 * DFF) + DFF + j];
    act[idx] = u * (vg / (1.f + __expf(-vg)));
}

// ------------------------- host -------------------------
extern "C" void kernel_launch(void* const* d_in, const int* in_sizes, int n_in,
                              void* d_out, int out_size)
{
    const float* x    = (const float*)d_in[0];
    const float* fc   = (const float*)d_in[1];
    const float* fs   = (const float*)d_in[2];
    const float* n1w  = (const float*)d_in[3];
    const float* n2w  = (const float*)d_in[4];
    const float* kvdw = (const float*)d_in[5];
    const float* qdw  = (const float*)d_in[6];
    const float* kvnw = (const float*)d_in[7];
    const float* qnw  = (const float*)d_in[8];
    const float* kvuw = (const float*)d_in[9];
    const float* quw  = (const float*)d_in[10];
    const float* lq1  = (const float*)d_in[11];
    const float* lk1  = (const float*)d_in[12];
    const float* lq2  = (const float*)d_in[13];
    const float* lk2  = (const float*)d_in[14];
    const float* anw  = (const float*)d_in[15];
    const float* ow   = (const float*)d_in[16];
    const float* fiw  = (const float*)d_in[17];
    const float* fow  = (const float*)d_in[18];
    float* outp = (float*)d_out;

    float *xin, *ckv, *ckvn, *kvup, *cq, *cqn, *qf, *Q, *K, *V, *P, *gg, *ao, *af, *x2, *hb, *uv, *act, *lam;
    cudaGetSymbolAddress((void**)&xin,  g_xin);
    cudaGetSymbolAddress((void**)&ckv,  g_ckv);
    cudaGetSymbolAddress((void**)&ckvn, g_ckvn);
    cudaGetSymbolAddress((void**)&kvup, g_kvup);
    cudaGetSymbolAddress((void**)&cq,   g_cq);
    cudaGetSymbolAddress((void**)&cqn,  g_cqn);
    cudaGetSymbolAddress((void**)&qf,   g_qf);
    cudaGetSymbolAddress((void**)&Q,    g_Q);
    cudaGetSymbolAddress((void**)&K,    g_K);
    cudaGetSymbolAddress((void**)&V,    g_V);
    cudaGetSymbolAddress((void**)&P,    g_P);
    cudaGetSymbolAddress((void**)&gg,   g_g);
    cudaGetSymbolAddress((void**)&ao,   g_ao);
    cudaGetSymbolAddress((void**)&af,   g_af);
    cudaGetSymbolAddress((void**)&x2,   g_x2);
    cudaGetSymbolAddress((void**)&hb,   g_hb);
    cudaGetSymbolAddress((void**)&uv,   g_uv);
    cudaGetSymbolAddress((void**)&act,  g_act);
    cudaGetSymbolAddress((void**)&lam,  g_lambda);

    static bool attr_set = false;
    if (!attr_set) {
        cudaFuncSetAttribute(tgemm_k, cudaFuncAttributeMaxDynamicSharedMemorySize, SMEM_T);
        attr_set = true;
    }

    auto grid_for = [](int M, int N, int batch) {
        return dim3((unsigned)((N + TBN - 1) / TBN), (unsigned)(M / TBM), (unsigned)batch);
    };

    // 1. xin = rmsnorm(x, norm1_w)
    rmsnorm_k<<<S_LEN, 256>>>(x, n1w, xin, DM, DM, DM, EPS_RMS);
    // 2. ckv = xin @ kv_down_w^T  [1536, 288]
    tgemm_k<<<grid_for(S_LEN, KVCC + ROPE_, 1), 256, SMEM_T>>>(xin, kvdw, nullptr, ckv,
        S_LEN, KVCC + ROPE_, DM, 0, 0, 0);
    // 3. ckvn = rmsnorm(ckv[:, :256])
    rmsnorm_k<<<S_LEN, 256>>>(ckv, kvnw, ckvn, KVCC, KVCC + ROPE_, KVCC, EPS_RMS);
    // 4. kvup = ckvn @ kv_up_w^T  [1536, 2048]
    tgemm_k<<<grid_for(S_LEN, 2048, 1), 256, SMEM_T>>>(ckvn, kvuw, nullptr, kvup,
        S_LEN, 2048, KVCC, 0, 0, 0);
    // 5. cq = xin @ q_down_w^T [1536, 384]
    tgemm_k<<<grid_for(S_LEN, QCC, 1), 256, SMEM_T>>>(xin, qdw, nullptr, cq,
        S_LEN, QCC, DM, 0, 0, 0);
    // 6. cqn = rmsnorm(cq)
    rmsnorm_k<<<S_LEN, 256>>>(cq, qnw, cqn, QCC, QCC, QCC, EPS_RMS);
    // 7. qf = cqn @ q_up_w^T [1536, 1536]
    tgemm_k<<<grid_for(S_LEN, 1536, 1), 256, SMEM_T>>>(cqn, quw, nullptr, qf,
        S_LEN, 1536, QCC, 0, 0, 0);
    // 8. build Q/K/V with RoPE (Q/K padded to 64 cols)
    build_qkv_k<<<S_LEN, 128>>>(qf, kvup, ckv, fc, fs, Q, K, V);
    // 9. logits: P[h] = Q[h] @ K[h]^T, batched over 32 sub-heads, K=64 (padded)
    tgemm_k<<<grid_for(S_LEN, S_LEN, H2), 256, SMEM_T>>>(Q, K, nullptr, P,
        S_LEN, S_LEN, DQKP,
        (long long)S_LEN * DQKP, (long long)S_LEN * DQKP, (long long)S_LEN * S_LEN);
    // 10. lambda scalar
    lambda_k_<<<1, 32>>>(lq1, lk1, lq2, lk2, lam);
    // 11. softmax rows (register-resident, fused scale + mask)
    softmax2_k<<<H2 * S_LEN, 256>>>(P);
    // 12. column means of even sub-heads
    colmean_k<<<dim3((S_LEN + 255) / 256, NH), 256>>>(P, gg);
    // 13+14. fused differential combine + AV GEMM -> ao [h][i][d]
    av_k<<<dim3(S_LEN / AVM, NH), 256>>>(P, V, gg, lam, ao);
    // 15. per (token, head) rmsnorm -> af (same [h][i][d] layout)
    attn_norm_k<<<dim3(S_LEN, NH), 64>>>(ao, anw, af);
    // 16. x2 = x + af @ o_w^T
    tgemm_k<<<grid_for(S_LEN, DM, 1), 256, SMEM_T>>>(af, ow, x, x2,
        S_LEN, DM, DM, 0, 0, 0);
    // 17. hb = rmsnorm(x2, norm2_w)
    rmsnorm_k<<<S_LEN, 256>>>(x2, n2w, hb, DM, DM, DM, EPS_RMS);
    // 18. uv = hb @ ff_in_w^T [1536, 8192]
    tgemm_k<<<grid_for(S_LEN, 2 * DFF, 1), 256, SMEM_T>>>(hb, fiw, nullptr, uv,
        S_LEN, 2 * DFF, DM, 0, 0, 0);
    // 19. act = u * silu(vg)
    {
        long long tot = (long long)S_LEN * DFF;
        swiglu_k<<<(unsigned)((tot + 255) / 256), 256>>>(uv, act);
    }
    // 20. out = x2 + act @ ff_out_w^T
    tgemm_k<<<grid_for(S_LEN, DM, 1), 256, SMEM_T>>>(act, fow, x2, outp,
        S_LEN, DM, DFF, 0, 0, 0);
}

// round 5
// speedup vs baseline: 4.3303x; 1.0317x over previous
#include <cuda_runtime.h>
#include <math.h>

#define S_LEN 1536
#define DM    1024
#define NH    16
#define HD    64
#define H2    32
#define DQK   48
#define DQKP  64      /* padded */
#define KVCC  256
#define ROPE_ 32
#define QCC   384
#define DFF   4096
#define SPP   384
#define EPS_RMS 1.1920929e-07f
#define ATTN_EPS 1e-5f
#define SCALING 0.14433756729740643f  /* 48^-0.5 */
#define LAMBDA_INIT 0.2f

// ------------------------- device scratch -------------------------
__device__ float g_xin [S_LEN * DM];
__device__ float g_ckv [S_LEN * (KVCC + ROPE_)];
__device__ float g_ckvn[S_LEN * KVCC];
__device__ float g_kvup[S_LEN * 2048];
__device__ float g_cq  [S_LEN * QCC];
__device__ float g_cqn [S_LEN * QCC];
__device__ float g_qf  [S_LEN * 1536];
__device__ float g_Q   [(size_t)H2 * S_LEN * DQKP];
__device__ float g_K   [(size_t)H2 * S_LEN * DQKP];
__device__ float g_V   [(size_t)NH * S_LEN * HD];
__device__ float g_P   [(size_t)H2 * S_LEN * S_LEN];   // ~302 MB
__device__ float g_g   [NH * S_LEN];
__device__ float g_ao  [(size_t)NH * S_LEN * HD];
__device__ float g_af  [S_LEN * DM];
__device__ float g_x2  [S_LEN * DM];
__device__ float g_hb  [S_LEN * DM];
__device__ float g_uv  [(size_t)S_LEN * 2 * DFF];
__device__ float g_act [(size_t)S_LEN * DFF];
__device__ float g_lambda;

// ------------------------- helpers -------------------------
__device__ __forceinline__ unsigned f2tf32(float x) {
    unsigned r;
    asm("cvt.rna.tf32.f32 %0, %1;" : "=r"(r) : "f"(x));
    return r;
}
__device__ __forceinline__ void cpa16(float* smem_dst, const float* gsrc, bool pred) {
    unsigned a = (unsigned)__cvta_generic_to_shared(smem_dst);
    asm volatile("cp.async.ca.shared.global [%0], [%1], 16, %2;\n"
                 :: "r"(a), "l"(gsrc), "r"(pred ? 16 : 0));
}
__device__ __forceinline__ void cpa_commit() { asm volatile("cp.async.commit_group;\n"); }
template <int NG>
__device__ __forceinline__ void cpa_wait() { asm volatile("cp.async.wait_group %0;\n" :: "n"(NG)); }

#define MMA_TF32(d, a, b) \
    asm volatile( \
        "mma.sync.aligned.m16n8k8.row.col.f32.tf32.tf32.f32 " \
        "{%0,%1,%2,%3}, {%4,%5,%6,%7}, {%8,%9}, {%0,%1,%2,%3};" \
        : "+f"(d[0]), "+f"(d[1]), "+f"(d[2]), "+f"(d[3]) \
        : "r"(a[0]), "r"(a[1]), "r"(a[2]), "r"(a[3]), "r"(b[0]), "r"(b[1]))

#define TBK 32
#define ASTR 36

// ------------------------- BIG TF32 GEMM: 128x128 tiles -------------------------
// C[M,N] = A[M,K] * B^T, B [N,K] row-major. M%128==0, N%128==0, K%32==0.
#define GBM 128
#define GBN 128
#define SMEM_BIG (2 * (GBM + GBN) * ASTR * 4)

__global__ __launch_bounds__(256, 2)
void tgemm_big(const float* __restrict__ A, const float* __restrict__ B,
               float* __restrict__ C, int M, int N, int K,
               long long sA, long long sB, long long sC)
{
    extern __shared__ float sm[];
    float* AsB = sm;                      // [2][GBM*ASTR]
    float* BsB = sm + 2 * GBM * ASTR;     // [2][GBN*ASTR]

    A += (long long)blockIdx.z * sA;
    B += (long long)blockIdx.z * sB;
    C += (long long)blockIdx.z * sC;

    const int tid  = threadIdx.x;
    const int lane = tid & 31;
    const int warp = tid >> 5;
    const int wm   = warp >> 2;           // 0..1 -> 64-row slices
    const int wn   = warp & 3;            // 0..3 -> 32-col slices
    const int row0 = blockIdx.y * GBM;
    const int col0 = blockIdx.x * GBN;
    const int grp  = lane >> 2;
    const int tig  = lane & 3;

    const int nk = K / TBK;

    auto load_tiles = [&](int ki, int buf) {
        const float* Ab = A + (long long)row0 * K + ki * TBK;
        float* Ad = AsB + buf * GBM * ASTR;
#pragma unroll
        for (int it = 0; it < 4; it++) {
            int f4 = tid + it * 256;
            int r = f4 >> 3, c4 = f4 & 7;
            cpa16(Ad + r * ASTR + c4 * 4, Ab + (long long)r * K + c4 * 4, true);
        }
        const float* Bb = B + (long long)col0 * K + ki * TBK;
        float* Bd = BsB + buf * GBN * ASTR;
#pragma unroll
        for (int it = 0; it < 4; it++) {
            int f4 = tid + it * 256;
            int n = f4 >> 3, c4 = f4 & 7;
            cpa16(Bd + n * ASTR + c4 * 4, Bb + (long long)n * K + c4 * 4, true);
        }
    };

    float acc[4][4][4];
#pragma unroll
    for (int i = 0; i < 4; i++)
#pragma unroll
        for (int j = 0; j < 4; j++)
#pragma unroll
            for (int l = 0; l < 4; l++) acc[i][j][l] = 0.f;

    load_tiles(0, 0);
    cpa_commit();

    for (int i = 0; i < nk; i++) {
        int cur = i & 1;
        if (i + 1 < nk) { load_tiles(i + 1, cur ^ 1); cpa_commit(); cpa_wait<1>(); }
        else            { cpa_wait<0>(); }
        __syncthreads();

        const float* Ab = AsB + cur * GBM * ASTR;
        const float* Bb = BsB + cur * GBN * ASTR;
#pragma unroll
        for (int kk = 0; kk < TBK; kk += 8) {
            unsigned af[4][4], bf[4][2];
            int c = kk + tig;
#pragma unroll
            for (int mi = 0; mi < 4; mi++) {
                int r = wm * 64 + mi * 16 + grp;
                af[mi][0] = f2tf32(Ab[r * ASTR + c]);
                af[mi][1] = f2tf32(Ab[(r + 8) * ASTR + c]);
                af[mi][2] = f2tf32(Ab[r * ASTR + c + 4]);
                af[mi][3] = f2tf32(Ab[(r + 8) * ASTR + c + 4]);
            }
#pragma unroll
            for (int ni = 0; ni < 4; ni++) {
                int n = wn * 32 + ni * 8 + grp;
                bf[ni][0] = f2tf32(Bb[n * ASTR + c]);
                bf[ni][1] = f2tf32(Bb[n * ASTR + c + 4]);
            }
#pragma unroll
            for (int mi = 0; mi < 4; mi++)
#pragma unroll
                for (int ni = 0; ni < 4; ni++)
                    MMA_TF32(acc[mi][ni], af[mi], bf[ni]);
        }
        __syncthreads();
    }

#pragma unroll
    for (int mi = 0; mi < 4; mi++)
#pragma unroll
        for (int ni = 0; ni < 4; ni++)
#pragma unroll
            for (int h = 0; h < 2; h++) {
                int r = row0 + wm * 64 + mi * 16 + grp + h * 8;
                int cc = col0 + wn * 32 + ni * 8 + tig * 2;
                long long o = (long long)r * N + cc;
                C[o]     = acc[mi][ni][h * 2 + 0];
                C[o + 1] = acc[mi][ni][h * 2 + 1];
            }
}

// ------------------------- SMALL TF32 GEMM (128x64) -------------------------
// C[M,N] = A[M,K] * B^T (+ Res). N arbitrary (guarded per tile). M%128==0, K%32==0.
#define TBM 128
#define TBN 64
#define SMEM_T (2 * (TBM + TBN) * ASTR * 4)

__global__ __launch_bounds__(256, 2)
void tgemm_k(const float* __restrict__ A, const float* __restrict__ B,
             const float* __restrict__ Res, float* __restrict__ C,
             int M, int N, int K,
             long long sA, long long sB, long long sC)
{
    extern __shared__ float sm[];
    float* AsB = sm;
    float* BsB = sm + 2 * TBM * ASTR;

    A += (long long)blockIdx.z * sA;
    B += (long long)blockIdx.z * sB;
    C += (long long)blockIdx.z * sC;

    const int tid  = threadIdx.x;
    const int lane = tid & 31;
    const int warp = tid >> 5;
    const int wm   = warp >> 1;
    const int wn   = warp & 1;
    const int row0 = blockIdx.y * TBM;
    const int col0 = blockIdx.x * TBN;
    const int grp  = lane >> 2;
    const int tig  = lane & 3;

    const int nk = K / TBK;

    auto load_tiles = [&](int ki, int buf) {
        const float* Ab = A + (long long)row0 * K + ki * TBK;
        float* Ad = AsB + buf * TBM * ASTR;
#pragma unroll
        for (int it = 0; it < 4; it++) {
            int f4 = tid + it * 256;
            int r = f4 >> 3, c4 = f4 & 7;
            cpa16(Ad + r * ASTR + c4 * 4, Ab + (long long)r * K + c4 * 4, true);
        }
        float* Bd = BsB + buf * TBN * ASTR;
#pragma unroll
        for (int it = 0; it < 2; it++) {
            int f4 = tid + it * 256;
            int n = f4 >> 3, c4 = f4 & 7;
            bool p = (col0 + n) < N;
            const float* src = B + (long long)(p ? (col0 + n) : 0) * K + ki * TBK + c4 * 4;
            cpa16(Bd + n * ASTR + c4 * 4, src, p);
        }
    };

    float acc[2][4][4];
#pragma unroll
    for (int i = 0; i < 2; i++)
#pragma unroll
        for (int j = 0; j < 4; j++)
#pragma unroll
            for (int l = 0; l < 4; l++) acc[i][j][l] = 0.f;

    load_tiles(0, 0);
    cpa_commit();

    for (int i = 0; i < nk; i++) {
        int cur = i & 1;
        if (i + 1 < nk) { load_tiles(i + 1, cur ^ 1); cpa_commit(); cpa_wait<1>(); }
        else            { cpa_wait<0>(); }
        __syncthreads();

        const float* Ab = AsB + cur * TBM * ASTR;
        const float* Bb = BsB + cur * TBN * ASTR;
#pragma unroll
        for (int kk = 0; kk < TBK; kk += 8) {
            unsigned af[2][4], bf[4][2];
#pragma unroll
            for (int mi = 0; mi < 2; mi++) {
                int r = wm * 32 + mi * 16 + grp;
                int c = kk + tig;
                af[mi][0] = f2tf32(Ab[r * ASTR + c]);
                af[mi][1] = f2tf32(Ab[(r + 8) * ASTR + c]);
                af[mi][2] = f2tf32(Ab[r * ASTR + c + 4]);
                af[mi][3] = f2tf32(Ab[(r + 8) * ASTR + c + 4]);
            }
#pragma unroll
            for (int ni = 0; ni < 4; ni++) {
                int n = wn * 32 + ni * 8 + grp;
                int c = kk + tig;
                bf[ni][0] = f2tf32(Bb[n * ASTR + c]);
                bf[ni][1] = f2tf32(Bb[n * ASTR + c + 4]);
            }
#pragma unroll
            for (int mi = 0; mi < 2; mi++)
#pragma unroll
                for (int ni = 0; ni < 4; ni++)
                    MMA_TF32(acc[mi][ni], af[mi], bf[ni]);
        }
        __syncthreads();
    }

#pragma unroll
    for (int mi = 0; mi < 2; mi++)
#pragma unroll
        for (int ni = 0; ni < 4; ni++)
#pragma unroll
            for (int h = 0; h < 2; h++) {
                int r = row0 + wm * 32 + mi * 16 + grp + h * 8;
                int cc = col0 + wn * 32 + ni * 8 + tig * 2;
                if (cc < N) {
                    float v0 = acc[mi][ni][h * 2 + 0];
                    float v1 = acc[mi][ni][h * 2 + 1];
                    long long o = (long long)r * N + cc;
                    if (Res) { v0 += Res[o]; v1 += Res[o + 1]; }
                    C[o] = v0; C[o + 1] = v1;
                }
            }
}

// ------------------------- fused differential-combine + AV GEMM -------------------
#define AVM 64
#define BSTR 72

__global__ __launch_bounds__(256)
void av_k(const float* __restrict__ P, const float* __restrict__ V,
          const float* __restrict__ g, const float* __restrict__ lamp,
          float* __restrict__ O)
{
    __shared__ float As[AVM * ASTR];
    __shared__ float Bs[TBK * BSTR];

    const int h    = blockIdx.y;
    const int row0 = blockIdx.x * AVM;
    const int tid  = threadIdx.x;
    const int lane = tid & 31;
    const int warp = tid >> 5;
    const int wm   = warp >> 1;
    const int wn   = warp & 1;
    const int grp  = lane >> 2;
    const int tig  = lane & 3;

    const float lam = *lamp;
    const float* p1 = P + (long long)(2 * h) * S_LEN * S_LEN;
    const float* p2 = P + (long long)(2 * h + 1) * S_LEN * S_LEN;
    const float* Vh = V + (long long)h * S_LEN * HD;
    const float* gh = g + h * S_LEN;

    float acc[4][4];
#pragma unroll
    for (int j = 0; j < 4; j++)
#pragma unroll
        for (int l = 0; l < 4; l++) acc[j][l] = 0.f;

    for (int j0 = 0; j0 < S_LEN; j0 += TBK) {
#pragma unroll
        for (int it = 0; it < 2; it++) {
            int f4 = tid + it * 256;
            int k = f4 >> 4, c4 = f4 & 15;
            cpa16(&Bs[k * BSTR + c4 * 4], Vh + (long long)(j0 + k) * HD + c4 * 4, true);
        }
        cpa_commit();

#pragma unroll
        for (int it = 0; it < 2; it++) {
            int f4 = tid + it * 256;
            int r = f4 >> 3, c4 = f4 & 7;
            int i = row0 + r;
            int ip = i % SPP;
            long long off = (long long)i * S_LEN + j0 + c4 * 4;
            float4 a1 = *(const float4*)(p1 + off);
            float4 a2 = *(const float4*)(p2 + off);
            float out[4];
            int jb = j0 + c4 * 4;
#pragma unroll
            for (int e = 0; e < 4; e++) {
                int j = jb + e;
                float v1 = e == 0 ? a1.x : e == 1 ? a1.y : e == 2 ? a1.z : a1.w;
                float v2 = e == 0 ? a2.x : e == 1 ? a2.y : e == 2 ? a2.z : a2.w;
                out[e] = ((j % SPP) > ip) ? 0.f : (v1 - lam * v2 + lam * gh[j]);
            }
            float* dst = &As[r * ASTR + c4 * 4];
            dst[0] = out[0]; dst[1] = out[1]; dst[2] = out[2]; dst[3] = out[3];
        }
        cpa_wait<0>();
        __syncthreads();

#pragma unroll
        for (int kk = 0; kk < TBK; kk += 8) {
            unsigned af[4], bf[4][2];
            {
                int r = wm * 16 + grp;
                int c = kk + tig;
                af[0] = f2tf32(As[r * ASTR + c]);
                af[1] = f2tf32(As[(r + 8) * ASTR + c]);
                af[2] = f2tf32(As[r * ASTR + c + 4]);
                af[3] = f2tf32(As[(r + 8) * ASTR + c + 4]);
            }
#pragma unroll
            for (int ni = 0; ni < 4; ni++) {
                int n = wn * 32 + ni * 8 + grp;
                int c = kk + tig;
                bf[ni][0] = f2tf32(Bs[c * BSTR + n]);
                bf[ni][1] = f2tf32(Bs[(c + 4) * BSTR + n]);
            }
#pragma unroll
            for (int ni = 0; ni < 4; ni++)
                MMA_TF32(acc[ni], af, bf[ni]);
        }
        __syncthreads();
    }

#pragma unroll
    for (int ni = 0; ni < 4; ni++)
#pragma unroll
        for (int hh = 0; hh < 2; hh++) {
            int r = row0 + wm * 16 + grp + hh * 8;
            int cc = wn * 32 + ni * 8 + tig * 2;
            long long o = ((long long)h * S_LEN + r) * HD + cc;
            O[o]     = acc[ni][hh * 2 + 0];
            O[o + 1] = acc[ni][hh * 2 + 1];
        }
}

// ------------------------- rmsnorm -------------------------
__global__ void rmsnorm_k(const float* __restrict__ in, const float* __restrict__ w,
                          float* __restrict__ out, int cols, int in_ld, int out_ld, float eps)
{
    const long long row = blockIdx.x;
    const float* ip = in + row * in_ld;
    float* op = out + row * out_ld;

    float ss = 0.f;
    for (int j = threadIdx.x; j < cols; j += blockDim.x) {
        float v = ip[j];
        ss += v * v;
    }
    __shared__ float sh[32];
    int lane = threadIdx.x & 31, wid = threadIdx.x >> 5;
#pragma unroll
    for (int o = 16; o; o >>= 1) ss += __shfl_xor_sync(0xffffffffu, ss, o);
    if (lane == 0) sh[wid] = ss;
    __syncthreads();
    int nw = (blockDim.x + 31) >> 5;
    float tot = 0.f;
    if (threadIdx.x < nw) tot = sh[threadIdx.x];
    if (wid == 0) {
#pragma unroll
        for (int o = 16; o; o >>= 1) tot += __shfl_xor_sync(0xffffffffu, tot, o);
        if (lane == 0) sh[0] = tot;
    }
    __syncthreads();
    float inv = rsqrtf(sh[0] / (float)cols + eps);
    for (int j = threadIdx.x; j < cols; j += blockDim.x)
        op[j] = ip[j] * inv * w[j];
}

// ------------------------- build Q/K/V with RoPE (Q/K padded to 64) --------
__global__ void build_qkv_k(const float* __restrict__ qf, const float* __restrict__ kvup,
                            const float* __restrict__ ckv,
                            const float* __restrict__ fcos, const float* __restrict__ fsin,
                            float* __restrict__ Q, float* __restrict__ K, float* __restrict__ V)
{
    const int i = blockIdx.x;
    const int tid = threadIdx.x;              // 128
    __shared__ float cs[8], sn[8];
    int p = i >> 2;
    if (tid < 8) {
        if (p == 0) { cs[tid] = 1.f; sn[tid] = 0.f; }
        else { cs[tid] = fcos[(p - 1) * 8 + tid]; sn[tid] = fsin[(p - 1) * 8 + tid]; }
    }
    __syncthreads();

    const float* qrow = qf + (long long)i * 1536;
    const float* krow = kvup + (long long)i * 2048;
    const float* crow = ckv + (long long)i * (KVCC + ROPE_);

    for (int e = tid; e < H2 * DQKP; e += 128) {
        int h2 = e / DQKP, d = e % DQKP;
        int h = h2 >> 1, c = h2 & 1;
        float qv = 0.f, kv = 0.f;
        if (d < 32) {
            qv = qrow[h * 96 + c * 32 + d];
            kv = krow[h * 128 + c * 32 + d];
        } else if (d < DQK) {
            int ee = d - 32;
            int f = ee >> 1;
            float q0 = qrow[h * 96 + 64 + c * 16 + 2 * f];
            float q1 = qrow[h * 96 + 64 + c * 16 + 2 * f + 1];
            float k0 = crow[KVCC + c * 16 + 2 * f];
            float k1 = crow[KVCC + c * 16 + 2 * f + 1];
            float C = cs[f], Sv = sn[f];
            if ((ee & 1) == 0) { qv = q0 * C - q1 * Sv; kv = k0 * C - k1 * Sv; }
            else               { qv = q0 * Sv + q1 * C; kv = k0 * Sv + k1 * C; }
        }
        Q[(long long)h2 * S_LEN * DQKP + (long long)i * DQKP + d] = qv;
        K[(long long)h2 * S_LEN * DQKP + (long long)i * DQKP + d] = kv;
    }
    for (int e = tid; e < NH * HD; e += 128) {
        int h = e >> 6, d = e & 63;
        V[(long long)h * S_LEN * HD + (long long)i * HD + d] = krow[h * 128 + 64 + d];
    }
}

// ------------------------- register softmax -------------------------
__global__ __launch_bounds__(256)
void softmax2_k(float* __restrict__ P)
{
    const long long rowi = blockIdx.x;
    const int r = (int)(rowi % S_LEN);
    float* row = P + rowi * S_LEN;
    const int rp = r % SPP;
    const int tid = threadIdx.x;

    __shared__ float sh[32];
    int lane = tid & 31, wid = tid >> 5;

    float v[6];
    bool msk[6];
#pragma unroll
    for (int l = 0; l < 6; l++) {
        int j = tid + l * 256;
        msk[l] = (j % SPP) > rp;
        v[l] = msk[l] ? -3.4e38f : row[j] * SCALING;
    }
    float mx = v[0];
#pragma unroll
    for (int l = 1; l < 6; l++) mx = fmaxf(mx, v[l]);
#pragma unroll
    for (int o = 16; o; o >>= 1) mx = fmaxf(mx, __shfl_xor_sync(0xffffffffu, mx, o));
    if (lane == 0) sh[wid] = mx;
    __syncthreads();
    float gmx = sh[lane & 7];
#pragma unroll
    for (int o = 4; o; o >>= 1) gmx = fmaxf(gmx, __shfl_xor_sync(0xffffffffu, gmx, o));

    float sum = 0.f;
#pragma unroll
    for (int l = 0; l < 6; l++) {
        float e = msk[l] ? 0.f : __expf(v[l] - gmx);
        v[l] = e;
        sum += e;
    }
#pragma unroll
    for (int o = 16; o; o >>= 1) sum += __shfl_xor_sync(0xffffffffu, sum, o);
    __syncthreads();
    if (lane == 0) sh[wid] = sum;
    __syncthreads();
    float gs = sh[lane & 7];
#pragma unroll
    for (int o = 4; o; o >>= 1) gs += __shfl_xor_sync(0xffffffffu, gs, o);
    float inv = 1.f / gs;

#pragma unroll
    for (int l = 0; l < 6; l++)
        row[tid + l * 256] = v[l] * inv;
}

// ------------------------- column mean of even sub-heads -------------------------
__global__ void colmean_k(const float* __restrict__ P, float* __restrict__ g)
{
    int j = blockIdx.x * blockDim.x + threadIdx.x;
    int h = blockIdx.y;
    if (j >= S_LEN) return;
    const float* base = P + (long long)(2 * h) * S_LEN * S_LEN + j;
    float s = 0.f;
    for (int i = 0; i < S_LEN; i++) s += base[(long long)i * S_LEN];
    g[h * S_LEN + j] = s / (float)S_LEN;
}

// ------------------------- lambda scalar -------------------------
__global__ void lambda_k_(const float* __restrict__ q1, const float* __restrict__ k1,
                          const float* __restrict__ q2, const float* __restrict__ k2,
                          float* __restrict__ out)
{
    int t = threadIdx.x;
    float a = q1[t] * k1[t];
    float b = q2[t] * k2[t];
#pragma unroll
    for (int o = 16; o; o >>= 1) {
        a += __shfl_xor_sync(0xffffffffu, a, o);
        b += __shfl_xor_sync(0xffffffffu, b, o);
    }
    if (t == 0) *out = expf(a) - expf(b) + LAMBDA_INIT;
}

// ------------------------- per (token, head) rmsnorm -------------------------
__global__ void attn_norm_k(const float* __restrict__ ao, const float* __restrict__ w,
                            float* __restrict__ outf)
{
    int i = blockIdx.x, h = blockIdx.y, d = threadIdx.x;
    long long idx = ((long long)h * S_LEN + i) * HD + d;
    float v = ao[idx];
    float sq = v * v;
    __shared__ float sh[2];
#pragma unroll
    for (int o = 16; o; o >>= 1) sq += __shfl_xor_sync(0xffffffffu, sq, o);
    if ((d & 31) == 0) sh[d >> 5] = sq;
    __syncthreads();
    float tot = sh[0] + sh[1];
    outf[idx] = v * rsqrtf(tot / (float)HD + ATTN_EPS) * w[d];
}

// ------------------------- SwiGLU -------------------------
__global__ void swiglu_k(const float* __restrict__ uv, float* __restrict__ act)
{
    long long idx = (long long)blockIdx.x * blockDim.x + threadIdx.x;
    if (idx >= (long long)S_LEN * DFF) return;
    long long i = idx / DFF, j = idx % DFF;
    float u = uv[i * (2 * DFF) + j];
    float vg = uv[i * (2 * DFF) + DFF + j];
    act[idx] = u * (vg / (1.f + __expf(-vg)));
}

// ------------------------- host -------------------------
extern "C" void kernel_launch(void* const* d_in, const int* in_sizes, int n_in,
                              void* d_out, int out_size)
{
    const float* x    = (const float*)d_in[0];
    const float* fc   = (const float*)d_in[1];
    const float* fs   = (const float*)d_in[2];
    const float* n1w  = (const float*)d_in[3];
    const float* n2w  = (const float*)d_in[4];
    const float* kvdw = (const float*)d_in[5];
    const float* qdw  = (const float*)d_in[6];
    const float* kvnw = (const float*)d_in[7];
    const float* qnw  = (const float*)d_in[8];
    const float* kvuw = (const float*)d_in[9];
    const float* quw  = (const float*)d_in[10];
    const float* lq1  = (const float*)d_in[11];
    const float* lk1  = (const float*)d_in[12];
    const float* lq2  = (const float*)d_in[13];
    const float* lk2  = (const float*)d_in[14];
    const float* anw  = (const float*)d_in[15];
    const float* ow   = (const float*)d_in[16];
    const float* fiw  = (const float*)d_in[17];
    const float* fow  = (const float*)d_in[18];
    float* outp = (float*)d_out;

    float *xin, *ckv, *ckvn, *kvup, *cq, *cqn, *qf, *Q, *K, *V, *P, *gg, *ao, *af, *x2, *hb, *uv, *act, *lam;
    cudaGetSymbolAddress((void**)&xin,  g_xin);
    cudaGetSymbolAddress((void**)&ckv,  g_ckv);
    cudaGetSymbolAddress((void**)&ckvn, g_ckvn);
    cudaGetSymbolAddress((void**)&kvup, g_kvup);
    cudaGetSymbolAddress((void**)&cq,   g_cq);
    cudaGetSymbolAddress((void**)&cqn,  g_cqn);
    cudaGetSymbolAddress((void**)&qf,   g_qf);
    cudaGetSymbolAddress((void**)&Q,    g_Q);
    cudaGetSymbolAddress((void**)&K,    g_K);
    cudaGetSymbolAddress((void**)&V,    g_V);
    cudaGetSymbolAddress((void**)&P,    g_P);
    cudaGetSymbolAddress((void**)&gg,   g_g);
    cudaGetSymbolAddress((void**)&ao,   g_ao);
    cudaGetSymbolAddress((void**)&af,   g_af);
    cudaGetSymbolAddress((void**)&x2,   g_x2);
    cudaGetSymbolAddress((void**)&hb,   g_hb);
    cudaGetSymbolAddress((void**)&uv,   g_uv);
    cudaGetSymbolAddress((void**)&act,  g_act);
    cudaGetSymbolAddress((void**)&lam,  g_lambda);

    static bool attr_set = false;
    if (!attr_set) {
        cudaFuncSetAttribute(tgemm_k,   cudaFuncAttributeMaxDynamicSharedMemorySize, SMEM_T);
        cudaFuncSetAttribute(tgemm_big, cudaFuncAttributeMaxDynamicSharedMemorySize, SMEM_BIG);
        attr_set = true;
    }

    auto grid_sm = [](int M, int N, int batch) {
        return dim3((unsigned)((N + TBN - 1) / TBN), (unsigned)(M / TBM), (unsigned)batch);
    };
    auto grid_bg = [](int M, int N, int batch) {
        return dim3((unsigned)(N / GBN), (unsigned)(M / GBM), (unsigned)batch);
    };

    // 1. xin = rmsnorm(x)
    rmsnorm_k<<<S_LEN, 256>>>(x, n1w, xin, DM, DM, DM, EPS_RMS);
    // 2. ckv = xin @ kv_down_w^T [1536, 288]
    tgemm_k<<<grid_sm(S_LEN, KVCC + ROPE_, 1), 256, SMEM_T>>>(xin, kvdw, nullptr, ckv,
        S_LEN, KVCC + ROPE_, DM, 0, 0, 0);
    // 3. ckvn = rmsnorm(ckv[:, :256])
    rmsnorm_k<<<S_LEN, 256>>>(ckv, kvnw, ckvn, KVCC, KVCC + ROPE_, KVCC, EPS_RMS);
    // 4. kvup = ckvn @ kv_up_w^T [1536, 2048]
    tgemm_big<<<grid_bg(S_LEN, 2048, 1), 256, SMEM_BIG>>>(ckvn, kvuw, kvup,
        S_LEN, 2048, KVCC, 0, 0, 0);
    // 5. cq = xin @ q_down_w^T [1536, 384]
    tgemm_k<<<grid_sm(S_LEN, QCC, 1), 256, SMEM_T>>>(xin, qdw, nullptr, cq,
        S_LEN, QCC, DM, 0, 0, 0);
    // 6. cqn = rmsnorm(cq)
    rmsnorm_k<<<S_LEN, 256>>>(cq, qnw, cqn, QCC, QCC, QCC, EPS_RMS);
    // 7. qf = cqn @ q_up_w^T [1536, 1536]
    tgemm_big<<<grid_bg(S_LEN, 1536, 1), 256, SMEM_BIG>>>(cqn, quw, qf,
        S_LEN, 1536, QCC, 0, 0, 0);
    // 8. build Q/K/V with RoPE
    build_qkv_k<<<S_LEN, 128>>>(qf, kvup, ckv, fc, fs, Q, K, V);
    // 9. logits: P[h] = Q[h] @ K[h]^T, 32 sub-heads, K=64 (padded)
    tgemm_big<<<grid_bg(S_LEN, S_LEN, H2), 256, SMEM_BIG>>>(Q, K, P,
        S_LEN, S_LEN, DQKP,
        (long long)S_LEN * DQKP, (long long)S_LEN * DQKP, (long long)S_LEN * S_LEN);
    // 10. lambda scalar
    lambda_k_<<<1, 32>>>(lq1, lk1, lq2, lk2, lam);
    // 11. softmax
    softmax2_k<<<H2 * S_LEN, 256>>>(P);
    // 12. column means
    colmean_k<<<dim3((S_LEN + 255) / 256, NH), 256>>>(P, gg);
    // 13+14. fused differential combine + AV
    av_k<<<dim3(S_LEN / AVM, NH), 256>>>(P, V, gg, lam, ao);
    // 15. attn rmsnorm
    attn_norm_k<<<dim3(S_LEN, NH), 64>>>(ao, anw, af);
    // 16. x2 = x + af @ o_w^T
    tgemm_k<<<grid_sm(S_LEN, DM, 1), 256, SMEM_T>>>(af, ow, x, x2,
        S_LEN, DM, DM, 0, 0, 0);
    // 17. hb = rmsnorm(x2)
    rmsnorm_k<<<S_LEN, 256>>>(x2, n2w, hb, DM, DM, DM, EPS_RMS);
    // 18. uv = hb @ ff_in_w^T [1536, 8192]
    tgemm_big<<<grid_bg(S_LEN, 2 * DFF, 1), 256, SMEM_BIG>>>(hb, fiw, uv,
        S_LEN, 2 * DFF, DM, 0, 0, 0);
    // 19. act = u * silu(vg)
    {
        long long tot = (long long)S_LEN * DFF;
        swiglu_k<<<(unsigned)((tot + 255) / 256), 256>>>(uv, act);
    }
    // 20. out = x2 + act @ ff_out_w^T
    tgemm_k<<<grid_sm(S_LEN, DM, 1), 256, SMEM_T>>>(act, fow, x2, outp,
        S_LEN, DM, DFF, 0, 0, 0);
}

// round 7
// speedup vs baseline: 4.5049x; 1.0403x over previous
#include <cuda_runtime.h>
#include <math.h>
#include <stdint.h>

#define S_LEN 1536
#define DM    1024
#define NH    16
#define HD    64
#define H2    32
#define DQK   48
#define DQKP  64
#define KVCC  256
#define ROPE_ 32
#define QCC   384
#define DFF   4096
#define SPP   384
#define EPS_RMS 1.1920929e-07f
#define ATTN_EPS 1e-5f
#define SCALING 0.14433756729740643f
#define LAMBDA_INIT 0.2f

// ------------------------- device scratch -------------------------
__device__ float g_xin [S_LEN * DM];
__device__ float g_ckv [S_LEN * (KVCC + ROPE_)];
__device__ float g_ckvn[S_LEN * KVCC];
__device__ float g_kvup[S_LEN * 2048];
__device__ float g_cq  [S_LEN * QCC];
__device__ float g_cqn [S_LEN * QCC];
__device__ float g_qf  [S_LEN * 1536];
__device__ float g_Q   [(size_t)H2 * S_LEN * DQKP];
__device__ float g_K   [(size_t)H2 * S_LEN * DQKP];
__device__ float g_V   [(size_t)NH * S_LEN * HD];
__device__ float g_P   [(size_t)H2 * S_LEN * S_LEN];
__device__ float g_g   [NH * S_LEN];
__device__ float g_ao  [(size_t)NH * S_LEN * HD];
__device__ float g_af  [S_LEN * DM];
__device__ float g_x2  [S_LEN * DM];
__device__ float g_hb  [S_LEN * DM];
__device__ float g_uv  [(size_t)S_LEN * 2 * DFF];
__device__ float g_act [(size_t)S_LEN * DFF];
__device__ float g_lambda;
// tf32-pre-rounded weight copies
__device__ float g_kvdw_r[(KVCC + ROPE_) * DM];
__device__ float g_qdw_r [QCC * DM];
__device__ float g_kvuw_r[2048 * KVCC];
__device__ float g_quw_r [1536 * QCC];
__device__ float g_ow_r  [(size_t)DM * DM];
__device__ float g_fiw_r [(size_t)2 * DFF * DM];
__device__ float g_fow_r [(size_t)DM * DFF];

// ------------------------- helpers -------------------------
__device__ __forceinline__ unsigned f2tf32(float x) {
    unsigned r;
    asm("cvt.rna.tf32.f32 %0, %1;" : "=r"(r) : "f"(x));
    return r;
}
__device__ __forceinline__ float roundtf(float x) { return __uint_as_float(f2tf32(x)); }

__device__ __forceinline__ void cpa16(float* smem_dst, const float* gsrc, bool pred) {
    unsigned a = (unsigned)__cvta_generic_to_shared(smem_dst);
    asm volatile("cp.async.ca.shared.global [%0], [%1], 16, %2;\n"
                 :: "r"(a), "l"(gsrc), "r"(pred ? 16 : 0));
}
__device__ __forceinline__ void cpa_commit() { asm volatile("cp.async.commit_group;\n"); }
template <int NG>
__device__ __forceinline__ void cpa_wait() { asm volatile("cp.async.wait_group %0;\n" :: "n"(NG)); }

#define MMA_TF32(d, a, b) \
    asm volatile( \
        "mma.sync.aligned.m16n8k8.row.col.f32.tf32.tf32.f32 " \
        "{%0,%1,%2,%3}, {%4,%5,%6,%7}, {%8,%9}, {%0,%1,%2,%3};" \
        : "+f"(d[0]), "+f"(d[1]), "+f"(d[2]), "+f"(d[3]) \
        : "r"(a[0]), "r"(a[1]), "r"(a[2]), "r"(a[3]), "r"(b[0]), "r"(b[1]))

#define TBK 32
#define ASTR 36

// ------------------------- BIG TF32 GEMM: 128x128 tiles (+Res) ----------------
// Inputs MUST be tf32-pre-rounded. C = A*B^T (+Res). M%128==0, N%128==0, K%32==0.
#define GBM 128
#define GBN 128
#define SMEM_BIG (2 * (GBM + GBN) * ASTR * 4)

__global__ __launch_bounds__(256, 2)
void tgemm_big(const float* __restrict__ A, const float* __restrict__ B,
               const float* __restrict__ Res, float* __restrict__ C,
               int M, int N, int K,
               long long sA, long long sB, long long sC)
{
    extern __shared__ float sm[];
    float* AsB = sm;
    float* BsB = sm + 2 * GBM * ASTR;

    A += (long long)blockIdx.z * sA;
    B += (long long)blockIdx.z * sB;
    C += (long long)blockIdx.z * sC;

    const int tid  = threadIdx.x;
    const int lane = tid & 31;
    const int warp = tid >> 5;
    const int wm   = warp >> 2;
    const int wn   = warp & 3;
    const int row0 = blockIdx.y * GBM;
    const int col0 = blockIdx.x * GBN;
    const int grp  = lane >> 2;
    const int tig  = lane & 3;

    const int nk = K / TBK;

    auto load_tiles = [&](int ki, int buf) {
        const float* Ab = A + (long long)row0 * K + ki * TBK;
        float* Ad = AsB + buf * GBM * ASTR;
#pragma unroll
        for (int it = 0; it < 4; it++) {
            int f4 = tid + it * 256;
            int r = f4 >> 3, c4 = f4 & 7;
            cpa16(Ad + r * ASTR + c4 * 4, Ab + (long long)r * K + c4 * 4, true);
        }
        const float* Bb = B + (long long)col0 * K + ki * TBK;
        float* Bd = BsB + buf * GBN * ASTR;
#pragma unroll
        for (int it = 0; it < 4; it++) {
            int f4 = tid + it * 256;
            int n = f4 >> 3, c4 = f4 & 7;
            cpa16(Bd + n * ASTR + c4 * 4, Bb + (long long)n * K + c4 * 4, true);
        }
    };

    float acc[4][4][4];
#pragma unroll
    for (int i = 0; i < 4; i++)
#pragma unroll
        for (int j = 0; j < 4; j++)
#pragma unroll
            for (int l = 0; l < 4; l++) acc[i][j][l] = 0.f;

    load_tiles(0, 0);
    cpa_commit();

    for (int i = 0; i < nk; i++) {
        int cur = i & 1;
        if (i + 1 < nk) { load_tiles(i + 1, cur ^ 1); cpa_commit(); cpa_wait<1>(); }
        else            { cpa_wait<0>(); }
        __syncthreads();

        const float* Ab = AsB + cur * GBM * ASTR;
        const float* Bb = BsB + cur * GBN * ASTR;
#pragma unroll
        for (int kk = 0; kk < TBK; kk += 8) {
            unsigned af[4][4], bf[4][2];
            int c = kk + tig;
#pragma unroll
            for (int mi = 0; mi < 4; mi++) {
                int r = wm * 64 + mi * 16 + grp;
                af[mi][0] = __float_as_uint(Ab[r * ASTR + c]);
                af[mi][1] = __float_as_uint(Ab[(r + 8) * ASTR + c]);
                af[mi][2] = __float_as_uint(Ab[r * ASTR + c + 4]);
                af[mi][3] = __float_as_uint(Ab[(r + 8) * ASTR + c + 4]);
            }
#pragma unroll
            for (int ni = 0; ni < 4; ni++) {
                int n = wn * 32 + ni * 8 + grp;
                bf[ni][0] = __float_as_uint(Bb[n * ASTR + c]);
                bf[ni][1] = __float_as_uint(Bb[n * ASTR + c + 4]);
            }
#pragma unroll
            for (int mi = 0; mi < 4; mi++)
#pragma unroll
                for (int ni = 0; ni < 4; ni++)
                    MMA_TF32(acc[mi][ni], af[mi], bf[ni]);
        }
        __syncthreads();
    }

#pragma unroll
    for (int mi = 0; mi < 4; mi++)
#pragma unroll
        for (int ni = 0; ni < 4; ni++)
#pragma unroll
            for (int h = 0; h < 2; h++) {
                int r = row0 + wm * 64 + mi * 16 + grp + h * 8;
                int cc = col0 + wn * 32 + ni * 8 + tig * 2;
                long long o = (long long)r * N + cc;
                float v0 = acc[mi][ni][h * 2 + 0];
                float v1 = acc[mi][ni][h * 2 + 1];
                if (Res) { v0 += Res[o]; v1 += Res[o + 1]; }
                C[o]     = v0;
                C[o + 1] = v1;
            }
}

// ------------------------- SMALL TF32 GEMM (128x64), pre-rounded inputs --------
#define TBM 128
#define TBN 64
#define SMEM_T (2 * (TBM + TBN) * ASTR * 4)

__global__ __launch_bounds__(256, 2)
void tgemm_k(const float* __restrict__ A, const float* __restrict__ B,
             const float* __restrict__ Res, float* __restrict__ C,
             int M, int N, int K,
             long long sA, long long sB, long long sC)
{
    extern __shared__ float sm[];
    float* AsB = sm;
    float* BsB = sm + 2 * TBM * ASTR;

    A += (long long)blockIdx.z * sA;
    B += (long long)blockIdx.z * sB;
    C += (long long)blockIdx.z * sC;

    const int tid  = threadIdx.x;
    const int lane = tid & 31;
    const int warp = tid >> 5;
    const int wm   = warp >> 1;
    const int wn   = warp & 1;
    const int row0 = blockIdx.y * TBM;
    const int col0 = blockIdx.x * TBN;
    const int grp  = lane >> 2;
    const int tig  = lane & 3;

    const int nk = K / TBK;

    auto load_tiles = [&](int ki, int buf) {
        const float* Ab = A + (long long)row0 * K + ki * TBK;
        float* Ad = AsB + buf * TBM * ASTR;
#pragma unroll
        for (int it = 0; it < 4; it++) {
            int f4 = tid + it * 256;
            int r = f4 >> 3, c4 = f4 & 7;
            cpa16(Ad + r * ASTR + c4 * 4, Ab + (long long)r * K + c4 * 4, true);
        }
        float* Bd = BsB + buf * TBN * ASTR;
#pragma unroll
        for (int it = 0; it < 2; it++) {
            int f4 = tid + it * 256;
            int n = f4 >> 3, c4 = f4 & 7;
            bool p = (col0 + n) < N;
            const float* src = B + (long long)(p ? (col0 + n) : 0) * K + ki * TBK + c4 * 4;
            cpa16(Bd + n * ASTR + c4 * 4, src, p);
        }
    };

    float acc[2][4][4];
#pragma unroll
    for (int i = 0; i < 2; i++)
#pragma unroll
        for (int j = 0; j < 4; j++)
#pragma unroll
            for (int l = 0; l < 4; l++) acc[i][j][l] = 0.f;

    load_tiles(0, 0);
    cpa_commit();

    for (int i = 0; i < nk; i++) {
        int cur = i & 1;
        if (i + 1 < nk) { load_tiles(i + 1, cur ^ 1); cpa_commit(); cpa_wait<1>(); }
        else            { cpa_wait<0>(); }
        __syncthreads();

        const float* Ab = AsB + cur * TBM * ASTR;
        const float* Bb = BsB + cur * TBN * ASTR;
#pragma unroll
        for (int kk = 0; kk < TBK; kk += 8) {
            unsigned af[2][4], bf[4][2];
#pragma unroll
            for (int mi = 0; mi < 2; mi++) {
                int r = wm * 32 + mi * 16 + grp;
                int c = kk + tig;
                af[mi][0] = __float_as_uint(Ab[r * ASTR + c]);
                af[mi][1] = __float_as_uint(Ab[(r + 8) * ASTR + c]);
                af[mi][2] = __float_as_uint(Ab[r * ASTR + c + 4]);
                af[mi][3] = __float_as_uint(Ab[(r + 8) * ASTR + c + 4]);
            }
#pragma unroll
            for (int ni = 0; ni < 4; ni++) {
                int n = wn * 32 + ni * 8 + grp;
                int c = kk + tig;
                bf[ni][0] = __float_as_uint(Bb[n * ASTR + c]);
                bf[ni][1] = __float_as_uint(Bb[n * ASTR + c + 4]);
            }
#pragma unroll
            for (int mi = 0; mi < 2; mi++)
#pragma unroll
                for (int ni = 0; ni < 4; ni++)
                    MMA_TF32(acc[mi][ni], af[mi], bf[ni]);
        }
        __syncthreads();
    }

#pragma unroll
    for (int mi = 0; mi < 2; mi++)
#pragma unroll
        for (int ni = 0; ni < 4; ni++)
#pragma unroll
            for (int h = 0; h < 2; h++) {
                int r = row0 + wm * 32 + mi * 16 + grp + h * 8;
                int cc = col0 + wn * 32 + ni * 8 + tig * 2;
                if (cc < N) {
                    float v0 = acc[mi][ni][h * 2 + 0];
                    float v1 = acc[mi][ni][h * 2 + 1];
                    long long o = (long long)r * N + cc;
                    if (Res) { v0 += Res[o]; v1 += Res[o + 1]; }
                    C[o] = v0; C[o + 1] = v1;
                }
            }
}

// ------------------------- fused differential-combine + AV GEMM -------------------
#define AVM 64
#define BSTR 72

__global__ __launch_bounds__(256)
void av_k(const float* __restrict__ P, const float* __restrict__ V,
          const float* __restrict__ g, const float* __restrict__ lamp,
          float* __restrict__ O)
{
    __shared__ float As[AVM * ASTR];
    __shared__ float Bs[TBK * BSTR];

    const int h    = blockIdx.y;
    const int row0 = blockIdx.x * AVM;
    const int tid  = threadIdx.x;
    const int lane = tid & 31;
    const int warp = tid >> 5;
    const int wm   = warp >> 1;
    const int wn   = warp & 1;
    const int grp  = lane >> 2;
    const int tig  = lane & 3;

    const float lam = *lamp;
    const float* p1 = P + (long long)(2 * h) * S_LEN * S_LEN;
    const float* p2 = P + (long long)(2 * h + 1) * S_LEN * S_LEN;
    const float* Vh = V + (long long)h * S_LEN * HD;
    const float* gh = g + h * S_LEN;

    float acc[4][4];
#pragma unroll
    for (int j = 0; j < 4; j++)
#pragma unroll
        for (int l = 0; l < 4; l++) acc[j][l] = 0.f;

    for (int j0 = 0; j0 < S_LEN; j0 += TBK) {
#pragma unroll
        for (int it = 0; it < 2; it++) {
            int f4 = tid + it * 256;
            int k = f4 >> 4, c4 = f4 & 15;
            cpa16(&Bs[k * BSTR + c4 * 4], Vh + (long long)(j0 + k) * HD + c4 * 4, true);
        }
        cpa_commit();

#pragma unroll
        for (int it = 0; it < 2; it++) {
            int f4 = tid + it * 256;
            int r = f4 >> 3, c4 = f4 & 7;
            int i = row0 + r;
            int ip = i % SPP;
            long long off = (long long)i * S_LEN + j0 + c4 * 4;
            float4 a1 = *(const float4*)(p1 + off);
            float4 a2 = *(const float4*)(p2 + off);
            float out[4];
            int jb = j0 + c4 * 4;
#pragma unroll
            for (int e = 0; e < 4; e++) {
                int j = jb + e;
                float v1 = e == 0 ? a1.x : e == 1 ? a1.y : e == 2 ? a1.z : a1.w;
                float v2 = e == 0 ? a2.x : e == 1 ? a2.y : e == 2 ? a2.z : a2.w;
                out[e] = ((j % SPP) > ip) ? 0.f : roundtf(v1 - lam * v2 + lam * gh[j]);
            }
            float* dst = &As[r * ASTR + c4 * 4];
            dst[0] = out[0]; dst[1] = out[1]; dst[2] = out[2]; dst[3] = out[3];
        }
        cpa_wait<0>();
        __syncthreads();

#pragma unroll
        for (int kk = 0; kk < TBK; kk += 8) {
            unsigned af[4], bf[4][2];
            {
                int r = wm * 16 + grp;
                int c = kk + tig;
                af[0] = __float_as_uint(As[r * ASTR + c]);
                af[1] = __float_as_uint(As[(r + 8) * ASTR + c]);
                af[2] = __float_as_uint(As[r * ASTR + c + 4]);
                af[3] = __float_as_uint(As[(r + 8) * ASTR + c + 4]);
            }
#pragma unroll
            for (int ni = 0; ni < 4; ni++) {
                int n = wn * 32 + ni * 8 + grp;
                int c = kk + tig;
                bf[ni][0] = __float_as_uint(Bs[c * BSTR + n]);
                bf[ni][1] = __float_as_uint(Bs[(c + 4) * BSTR + n]);
            }
#pragma unroll
            for (int ni = 0; ni < 4; ni++)
                MMA_TF32(acc[ni], af, bf[ni]);
        }
        __syncthreads();
    }

#pragma unroll
    for (int ni = 0; ni < 4; ni++)
#pragma unroll
        for (int hh = 0; hh < 2; hh++) {
            int r = row0 + wm * 16 + grp + hh * 8;
            int cc = wn * 32 + ni * 8 + tig * 2;
            long long o = ((long long)h * S_LEN + r) * HD + cc;
            O[o]     = acc[ni][hh * 2 + 0];
            O[o + 1] = acc[ni][hh * 2 + 1];
        }
}

// ------------------------- rmsnorm (optional tf32-rounded output) ----------
__global__ void rmsnorm_k(const float* __restrict__ in, const float* __restrict__ w,
                          float* __restrict__ out, int cols, int in_ld, int out_ld,
                          float eps, int round_out)
{
    const long long row = blockIdx.x;
    const float* ip = in + row * in_ld;
    float* op = out + row * out_ld;

    float ss = 0.f;
    for (int j = threadIdx.x; j < cols; j += blockDim.x) {
        float v = ip[j];
        ss += v * v;
    }
    __shared__ float sh[32];
    int lane = threadIdx.x & 31, wid = threadIdx.x >> 5;
#pragma unroll
    for (int o = 16; o; o >>= 1) ss += __shfl_xor_sync(0xffffffffu, ss, o);
    if (lane == 0) sh[wid] = ss;
    __syncthreads();
    int nw = (blockDim.x + 31) >> 5;
    float tot = 0.f;
    if (threadIdx.x < nw) tot = sh[threadIdx.x];
    if (wid == 0) {
#pragma unroll
        for (int o = 16; o; o >>= 1) tot += __shfl_xor_sync(0xffffffffu, tot, o);
        if (lane == 0) sh[0] = tot;
    }
    __syncthreads();
    float inv = rsqrtf(sh[0] / (float)cols + eps);
    for (int j = threadIdx.x; j < cols; j += blockDim.x) {
        float v = ip[j] * inv * w[j];
        op[j] = round_out ? roundtf(v) : v;
    }
}

// ------------------------- build Q/K/V with RoPE (rounded, Q/K padded) ---------
__global__ void build_qkv_k(const float* __restrict__ qf, const float* __restrict__ kvup,
                            const float* __restrict__ ckv,
                            const float* __restrict__ fcos, const float* __restrict__ fsin,
                            float* __restrict__ Q, float* __restrict__ K, float* __restrict__ V)
{
    const int i = blockIdx.x;
    const int tid = threadIdx.x;              // 128
    __shared__ float cs[8], sn[8];
    int p = i >> 2;
    if (tid < 8) {
        if (p == 0) { cs[tid] = 1.f; sn[tid] = 0.f; }
        else { cs[tid] = fcos[(p - 1) * 8 + tid]; sn[tid] = fsin[(p - 1) * 8 + tid]; }
    }
    __syncthreads();

    const float* qrow = qf + (long long)i * 1536;
    const float* krow = kvup + (long long)i * 2048;
    const float* crow = ckv + (long long)i * (KVCC + ROPE_);

    for (int e = tid; e < H2 * DQKP; e += 128) {
        int h2 = e / DQKP, d = e % DQKP;
        int h = h2 >> 1, c = h2 & 1;
        float qv = 0.f, kv = 0.f;
        if (d < 32) {
            qv = qrow[h * 96 + c * 32 + d];
            kv = krow[h * 128 + c * 32 + d];
        } else if (d < DQK) {
            int ee = d - 32;
            int f = ee >> 1;
            float q0 = qrow[h * 96 + 64 + c * 16 + 2 * f];
            float q1 = qrow[h * 96 + 64 + c * 16 + 2 * f + 1];
            float k0 = crow[KVCC + c * 16 + 2 * f];
            float k1 = crow[KVCC + c * 16 + 2 * f + 1];
            float C = cs[f], Sv = sn[f];
            if ((ee & 1) == 0) { qv = q0 * C - q1 * Sv; kv = k0 * C - k1 * Sv; }
            else               { qv = q0 * Sv + q1 * C; kv = k0 * Sv + k1 * C; }
        }
        Q[(long long)h2 * S_LEN * DQKP + (long long)i * DQKP + d] = roundtf(qv);
        K[(long long)h2 * S_LEN * DQKP + (long long)i * DQKP + d] = roundtf(kv);
    }
    for (int e = tid; e < NH * HD; e += 128) {
        int h = e >> 6, d = e & 63;
        V[(long long)h * S_LEN * HD + (long long)i * HD + d] = roundtf(krow[h * 128 + 64 + d]);
    }
}

// ------------------------- register softmax (tf32-rounded output) --------------
__global__ __launch_bounds__(256)
void softmax2_k(float* __restrict__ P)
{
    const long long rowi = blockIdx.x;
    const int r = (int)(rowi % S_LEN);
    float* row = P + rowi * S_LEN;
    const int rp = r % SPP;
    const int tid = threadIdx.x;

    __shared__ float sh[32];
    int lane = tid & 31, wid = tid >> 5;

    float v[6];
    bool msk[6];
#pragma unroll
    for (int l = 0; l < 6; l++) {
        int j = tid + l * 256;
        msk[l] = (j % SPP) > rp;
        v[l] = msk[l] ? -3.4e38f : row[j] * SCALING;
    }
    float mx = v[0];
#pragma unroll
    for (int l = 1; l < 6; l++) mx = fmaxf(mx, v[l]);
#pragma unroll
    for (int o = 16; o; o >>= 1) mx = fmaxf(mx, __shfl_xor_sync(0xffffffffu, mx, o));
    if (lane == 0) sh[wid] = mx;
    __syncthreads();
    float gmx = sh[lane & 7];
#pragma unroll
    for (int o = 4; o; o >>= 1) gmx = fmaxf(gmx, __shfl_xor_sync(0xffffffffu, gmx, o));

    float sum = 0.f;
#pragma unroll
    for (int l = 0; l < 6; l++) {
        float e = msk[l] ? 0.f : __expf(v[l] - gmx);
        v[l] = e;
        sum += e;
    }
#pragma unroll
    for (int o = 16; o; o >>= 1) sum += __shfl_xor_sync(0xffffffffu, sum, o);
    __syncthreads();
    if (lane == 0) sh[wid] = sum;
    __syncthreads();
    float gs = sh[lane & 7];
#pragma unroll
    for (int o = 4; o; o >>= 1) gs += __shfl_xor_sync(0xffffffffu, gs, o);
    float inv = 1.f / gs;

#pragma unroll
    for (int l = 0; l < 6; l++)
        row[tid + l * 256] = roundtf(v[l] * inv);
}

// ------------------------- column mean of even sub-heads -------------------------
__global__ void colmean_k(const float* __restrict__ P, float* __restrict__ g)
{
    int j = blockIdx.x * blockDim.x + threadIdx.x;
    int h = blockIdx.y;
    if (j >= S_LEN) return;
    const float* base = P + (long long)(2 * h) * S_LEN * S_LEN + j;
    float s = 0.f;
    for (int i = 0; i < S_LEN; i++) s += base[(long long)i * S_LEN];
    g[h * S_LEN + j] = s / (float)S_LEN;
}

// ------------------------- lambda scalar -------------------------
__global__ void lambda_k_(const float* __restrict__ q1, const float* __restrict__ k1,
                          const float* __restrict__ q2, const float* __restrict__ k2,
                          float* __restrict__ out)
{
    int t = threadIdx.x;
    float a = q1[t] * k1[t];
    float b = q2[t] * k2[t];
#pragma unroll
    for (int o = 16; o; o >>= 1) {
        a += __shfl_xor_sync(0xffffffffu, a, o);
        b += __shfl_xor_sync(0xffffffffu, b, o);
    }
    if (t == 0) *out = expf(a) - expf(b) + LAMBDA_INIT;
}

// ------------------------- per (token, head) rmsnorm (rounded) -----------------
__global__ void attn_norm_k(const float* __restrict__ ao, const float* __restrict__ w,
                            float* __restrict__ outf)
{
    int i = blockIdx.x, h = blockIdx.y, d = threadIdx.x;
    long long idx = ((long long)h * S_LEN + i) * HD + d;
    float v = ao[idx];
    float sq = v * v;
    __shared__ float sh[2];
#pragma unroll
    for (int o = 16; o; o >>= 1) sq += __shfl_xor_sync(0xffffffffu, sq, o);
    if ((d & 31) == 0) sh[d >> 5] = sq;
    __syncthreads();
    float tot = sh[0] + sh[1];
    outf[idx] = roundtf(v * rsqrtf(tot / (float)HD + ATTN_EPS) * w[d]);
}

// ------------------------- SwiGLU (rounded output) -------------------------
__global__ void swiglu_k(const float* __restrict__ uv, float* __restrict__ act)
{
    long long idx = (long long)blockIdx.x * blockDim.x + threadIdx.x;
    if (idx >= (long long)S_LEN * DFF) return;
    long long i = idx / DFF, j = idx % DFF;
    float u = uv[i * (2 * DFF) + j];
    float vg = uv[i * (2 * DFF) + DFF + j];
    act[idx] = roundtf(u * (vg / (1.f + __expf(-vg))));
}

// ------------------------- tf32 pre-round (grid-stride) -------------------------
__global__ void cvt_tf32_k(const float* __restrict__ in, float* __restrict__ out, int n)
{
    int i = blockIdx.x * blockDim.x + threadIdx.x;
    int stride = gridDim.x * blockDim.x;
    for (; i < n; i += stride) out[i] = roundtf(in[i]);
}

// ------------------------- host -------------------------
extern "C" void kernel_launch(void* const* d_in, const int* in_sizes, int n_in,
                              void* d_out, int out_size)
{
    const float* x    = (const float*)d_in[0];
    const float* fc   = (const float*)d_in[1];
    const float* fs   = (const float*)d_in[2];
    const float* n1w  = (const float*)d_in[3];
    const float* n2w  = (const float*)d_in[4];
    const float* kvdw = (const float*)d_in[5];
    const float* qdw  = (const float*)d_in[6];
    const float* kvnw = (const float*)d_in[7];
    const float* qnw  = (const float*)d_in[8];
    const float* kvuw = (const float*)d_in[9];
    const float* quw  = (const float*)d_in[10];
    const float* lq1  = (const float*)d_in[11];
    const float* lk1  = (const float*)d_in[12];
    const float* lq2  = (const float*)d_in[13];
    const float* lk2  = (const float*)d_in[14];
    const float* anw  = (const float*)d_in[15];
    const float* ow   = (const float*)d_in[16];
    const float* fiw  = (const float*)d_in[17];
    const float* fow  = (const float*)d_in[18];
    float* outp = (float*)d_out;

    float *xin, *ckv, *ckvn, *kvup, *cq, *cqn, *qf, *Q, *K, *V, *P, *gg, *ao, *af, *x2, *hb, *uv, *act, *lam;
    float *kvdw_r, *qdw_r, *kvuw_r, *quw_r, *ow_r, *fiw_r, *fow_r;
    cudaGetSymbolAddress((void**)&xin,  g_xin);
    cudaGetSymbolAddress((void**)&ckv,  g_ckv);
    cudaGetSymbolAddress((void**)&ckvn, g_ckvn);
    cudaGetSymbolAddress((void**)&kvup, g_kvup);
    cudaGetSymbolAddress((void**)&cq,   g_cq);
    cudaGetSymbolAddress((void**)&cqn,  g_cqn);
    cudaGetSymbolAddress((void**)&qf,   g_qf);
    cudaGetSymbolAddress((void**)&Q,    g_Q);
    cudaGetSymbolAddress((void**)&K,    g_K);
    cudaGetSymbolAddress((void**)&V,    g_V);
    cudaGetSymbolAddress((void**)&P,    g_P);
    cudaGetSymbolAddress((void**)&gg,   g_g);
    cudaGetSymbolAddress((void**)&ao,   g_ao);
    cudaGetSymbolAddress((void**)&af,   g_af);
    cudaGetSymbolAddress((void**)&x2,   g_x2);
    cudaGetSymbolAddress((void**)&hb,   g_hb);
    cudaGetSymbolAddress((void**)&uv,   g_uv);
    cudaGetSymbolAddress((void**)&act,  g_act);
    cudaGetSymbolAddress((void**)&lam,  g_lambda);
    cudaGetSymbolAddress((void**)&kvdw_r, g_kvdw_r);
    cudaGetSymbolAddress((void**)&qdw_r,  g_qdw_r);
    cudaGetSymbolAddress((void**)&kvuw_r, g_kvuw_r);
    cudaGetSymbolAddress((void**)&quw_r,  g_quw_r);
    cudaGetSymbolAddress((void**)&ow_r,   g_ow_r);
    cudaGetSymbolAddress((void**)&fiw_r,  g_fiw_r);
    cudaGetSymbolAddress((void**)&fow_r,  g_fow_r);

    static bool attr_set = false;
    if (!attr_set) {
        cudaFuncSetAttribute(tgemm_k,   cudaFuncAttributeMaxDynamicSharedMemorySize, SMEM_T);
        cudaFuncSetAttribute(tgemm_big, cudaFuncAttributeMaxDynamicSharedMemorySize, SMEM_BIG);
        attr_set = true;
    }

    auto grid_sm = [](int M, int N, int batch) {
        return dim3((unsigned)((N + TBN - 1) / TBN), (unsigned)(M / TBM), (unsigned)batch);
    };
    auto grid_bg = [](int M, int N, int batch) {
        return dim3((unsigned)(N / GBN), (unsigned)(M / GBM), (unsigned)batch);
    };

    // 0. pre-round all weights to tf32
    cvt_tf32_k<<<512,  256>>>(kvdw, kvdw_r, (KVCC + ROPE_) * DM);
    cvt_tf32_k<<<512,  256>>>(qdw,  qdw_r,  QCC * DM);
    cvt_tf32_k<<<512,  256>>>(kvuw, kvuw_r, 2048 * KVCC);
    cvt_tf32_k<<<512,  256>>>(quw,  quw_r,  1536 * QCC);
    cvt_tf32_k<<<1024, 256>>>(ow,   ow_r,   DM * DM);
    cvt_tf32_k<<<2048, 256>>>(fiw,  fiw_r,  2 * DFF * DM);
    cvt_tf32_k<<<2048, 256>>>(fow,  fow_r,  DM * DFF);

    // 1. xin = rmsnorm(x) (rounded)
    rmsnorm_k<<<S_LEN, 256>>>(x, n1w, xin, DM, DM, DM, EPS_RMS, 1);
    // 2. ckv = xin @ kv_down_w^T [1536, 288]
    tgemm_k<<<grid_sm(S_LEN, KVCC + ROPE_, 1), 256, SMEM_T>>>(xin, kvdw_r, nullptr, ckv,
        S_LEN, KVCC + ROPE_, DM, 0, 0, 0);
    // 3. ckvn = rmsnorm(ckv[:, :256]) (rounded)
    rmsnorm_k<<<S_LEN, 256>>>(ckv, kvnw, ckvn, KVCC, KVCC + ROPE_, KVCC, EPS_RMS, 1);
    // 4. kvup = ckvn @ kv_up_w^T [1536, 2048]
    tgemm_big<<<grid_bg(S_LEN, 2048, 1), 256, SMEM_BIG>>>(ckvn, kvuw_r, nullptr, kvup,
        S_LEN, 2048, KVCC, 0, 0, 0);
    // 5. cq = xin @ q_down_w^T [1536, 384]
    tgemm_k<<<grid_sm(S_LEN, QCC, 1), 256, SMEM_T>>>(xin, qdw_r, nullptr, cq,
        S_LEN, QCC, DM, 0, 0, 0);
    // 6. cqn = rmsnorm(cq) (rounded)
    rmsnorm_k<<<S_LEN, 256>>>(cq, qnw, cqn, QCC, QCC, QCC, EPS_RMS, 1);
    // 7. qf = cqn @ q_up_w^T [1536, 1536]
    tgemm_big<<<grid_bg(S_LEN, 1536, 1), 256, SMEM_BIG>>>(cqn, quw_r, nullptr, qf,
        S_LEN, 1536, QCC, 0, 0, 0);
    // 8. build Q/K/V with RoPE (rounded)
    build_qkv_k<<<S_LEN, 128>>>(qf, kvup, ckv, fc, fs, Q, K, V);
    // 9. logits: P[h] = Q[h] @ K[h]^T, 32 sub-heads, K=64
    tgemm_big<<<grid_bg(S_LEN, S_LEN, H2), 256, SMEM_BIG>>>(Q, K, nullptr, P,
        S_LEN, S_LEN, DQKP,
        (long long)S_LEN * DQKP, (long long)S_LEN * DQKP, (long long)S_LEN * S_LEN);
    // 10. lambda
    lambda_k_<<<1, 32>>>(lq1, lk1, lq2, lk2, lam);
    // 11. softmax (rounded output)
    softmax2_k<<<H2 * S_LEN, 256>>>(P);
    // 12. column means
    colmean_k<<<dim3((S_LEN + 255) / 256, NH), 256>>>(P, gg);
    // 13+14. fused combine + AV
    av_k<<<dim3(S_LEN / AVM, NH), 256>>>(P, V, gg, lam, ao);
    // 15. attn rmsnorm (rounded)
    attn_norm_k<<<dim3(S_LEN, NH), 64>>>(ao, anw, af);
    // 16. x2 = x + af @ o_w^T
    tgemm_big<<<grid_bg(S_LEN, DM, 1), 256, SMEM_BIG>>>(af, ow_r, x, x2,
        S_LEN, DM, DM, 0, 0, 0);
    // 17. hb = rmsnorm(x2) (rounded)
    rmsnorm_k<<<S_LEN, 256>>>(x2, n2w, hb, DM, DM, DM, EPS_RMS, 1);
    // 18. uv = hb @ ff_in_w^T [1536, 8192]
    tgemm_big<<<grid_bg(S_LEN, 2 * DFF, 1), 256, SMEM_BIG>>>(hb, fiw_r, nullptr, uv,
        S_LEN, 2 * DFF, DM, 0, 0, 0);
    // 19. act = u * silu(vg) (rounded)
    {
        long long tot = (long long)S_LEN * DFF;
        swiglu_k<<<(unsigned)((tot + 255) / 256), 256>>>(uv, act);
    }
    // 20. out = x2 + act @ ff_out_w^T
    tgemm_big<<<grid_bg(S_LEN, DM, 1), 256, SMEM_BIG>>>(act, fow_r, x2, outp,
        S_LEN, DM, DFF, 0, 0, 0);
}

// round 8
// speedup vs baseline: 5.9541x; 1.3217x over previous
#include <cuda_runtime.h>
#include <cuda_fp16.h>
#include <math.h>
#include <stdint.h>

#define S_LEN 1536
#define DM    1024
#define NH    16
#define HD    64
#define H2    32
#define DQK   48
#define DQKP  64
#define KVCC  256
#define ROPE_ 32
#define QCC   384
#define DFF   4096
#define SPP   384
#define EPS_RMS 1.1920929e-07f
#define ATTN_EPS 1e-5f
#define SCALING 0.14433756729740643f
#define LAMBDA_INIT 0.2f

// ------------------------- device scratch -------------------------
__device__ __half g_xin [S_LEN * DM];
__device__ float  g_ckv [S_LEN * 384];            // stride 384 (padded N)
__device__ __half g_ckvn[S_LEN * KVCC];
__device__ __half g_kvup[S_LEN * 2048];
__device__ float  g_cq  [S_LEN * QCC];
__device__ __half g_cqn [S_LEN * QCC];
__device__ __half g_qf  [S_LEN * 1536];
__device__ __half g_Q   [(size_t)H2 * S_LEN * DQKP];
__device__ __half g_K   [(size_t)H2 * S_LEN * DQKP];
__device__ __half g_V   [(size_t)NH * S_LEN * HD];
__device__ float  g_P   [(size_t)H2 * S_LEN * S_LEN];   // logits fp32, ~302MB
__device__ __half g_Ph  [(size_t)H2 * S_LEN * S_LEN];   // probs fp16, ~151MB
__device__ float  g_g   [NH * S_LEN];
__device__ float  g_ao  [(size_t)NH * S_LEN * HD];
__device__ __half g_af  [S_LEN * DM];
__device__ float  g_x2  [S_LEN * DM];
__device__ __half g_hb  [S_LEN * DM];
__device__ __half g_uv  [(size_t)S_LEN * 2 * DFF];
__device__ __half g_act [(size_t)S_LEN * DFF];
__device__ float  g_lambda;
// fp16 weight copies
__device__ __half g_kvdw_h[384 * DM];             // padded 288 -> 384 rows
__device__ __half g_qdw_h [QCC * DM];
__device__ __half g_kvuw_h[2048 * KVCC];
__device__ __half g_quw_h [1536 * QCC];
__device__ __half g_ow_h  [(size_t)DM * DM];
__device__ __half g_fiw_h [(size_t)2 * DFF * DM];
__device__ __half g_fow_h [(size_t)DM * DFF];

// ------------------------- helpers -------------------------
__device__ __forceinline__ void cpa16(void* smem_dst, const void* gsrc) {
    unsigned a = (unsigned)__cvta_generic_to_shared(smem_dst);
    asm volatile("cp.async.ca.shared.global [%0], [%1], 16;\n" :: "r"(a), "l"(gsrc));
}
__device__ __forceinline__ void cpa_commit() { asm volatile("cp.async.commit_group;\n"); }
template <int NG>
__device__ __forceinline__ void cpa_wait() { asm volatile("cp.async.wait_group %0;\n" :: "n"(NG)); }

#define LDM_X4(a0,a1,a2,a3,p) \
    asm volatile("ldmatrix.sync.aligned.m8n8.x4.shared.b16 {%0,%1,%2,%3}, [%4];" \
        : "=r"(a0), "=r"(a1), "=r"(a2), "=r"(a3) \
        : "r"((unsigned)__cvta_generic_to_shared(p)))
#define LDM_X2(b0,b1,p) \
    asm volatile("ldmatrix.sync.aligned.m8n8.x2.shared.b16 {%0,%1}, [%2];" \
        : "=r"(b0), "=r"(b1) \
        : "r"((unsigned)__cvta_generic_to_shared(p)))
#define LDM_X2T(b0,b1,p) \
    asm volatile("ldmatrix.sync.aligned.m8n8.x2.trans.shared.b16 {%0,%1}, [%2];" \
        : "=r"(b0), "=r"(b1) \
        : "r"((unsigned)__cvta_generic_to_shared(p)))
#define MMA_F16(d, a, b) \
    asm volatile( \
        "mma.sync.aligned.m16n8k16.row.col.f32.f16.f16.f32 " \
        "{%0,%1,%2,%3}, {%4,%5,%6,%7}, {%8,%9}, {%0,%1,%2,%3};" \
        : "+f"(d[0]), "+f"(d[1]), "+f"(d[2]), "+f"(d[3]) \
        : "r"(a[0]), "r"(a[1]), "r"(a[2]), "r"(a[3]), "r"(b[0]), "r"(b[1]))

#define HSTR 40    /* halves; 80B row stride -> conflict-free ldmatrix */
#define GBK  32

// ------------------------- FP16 GEMM: 128x128 tiles, C = A*B^T (+Res) ----------
// A[M,K], B[N,K] row-major __half. M%128==0, N%128==0, K%32==0. Batched via z.
#define SMEM_H (2 * 2 * 128 * HSTR * 2)   /* 2 bufs x (A+B) x 128 rows x HSTR halves x 2B */

template <bool HALF_OUT>
__global__ __launch_bounds__(256, 2)
void hgemm(const __half* __restrict__ A, const __half* __restrict__ B,
           const float* __restrict__ Res, void* __restrict__ Cv,
           int M, int N, int K, long long sA, long long sB, long long sC)
{
    extern __shared__ __half hsm[];
    __half* AsB = hsm;                   // [2][128*HSTR]
    __half* BsB = hsm + 2 * 128 * HSTR;  // [2][128*HSTR]

    A += (long long)blockIdx.z * sA;
    B += (long long)blockIdx.z * sB;
    float*  Cf = (float*)Cv  + (long long)blockIdx.z * sC;
    __half* Ch = (__half*)Cv + (long long)blockIdx.z * sC;

    const int tid  = threadIdx.x;
    const int lane = tid & 31;
    const int warp = tid >> 5;
    const int wm   = warp >> 2;          // 0..1 (64 rows)
    const int wn   = warp & 3;           // 0..3 (32 cols)
    const int row0 = blockIdx.y * 128;
    const int col0 = blockIdx.x * 128;
    const int grp  = lane >> 2;
    const int tig  = lane & 3;

    const int nk = K / GBK;

    auto load_tiles = [&](int ki, int buf) {
        const __half* Ag = A + (long long)row0 * K + ki * GBK;
        __half* Ad = AsB + buf * 128 * HSTR;
#pragma unroll
        for (int it = 0; it < 2; it++) {
            int f = tid + it * 256;
            int r = f >> 2, c8 = (f & 3) * 8;
            cpa16(Ad + r * HSTR + c8, Ag + (long long)r * K + c8);
        }
        const __half* Bg = B + (long long)col0 * K + ki * GBK;
        __half* Bd = BsB + buf * 128 * HSTR;
#pragma unroll
        for (int it = 0; it < 2; it++) {
            int f = tid + it * 256;
            int r = f >> 2, c8 = (f & 3) * 8;
            cpa16(Bd + r * HSTR + c8, Bg + (long long)r * K + c8);
        }
    };

    float acc[4][4][4];
#pragma unroll
    for (int i = 0; i < 4; i++)
#pragma unroll
        for (int j = 0; j < 4; j++)
#pragma unroll
            for (int l = 0; l < 4; l++) acc[i][j][l] = 0.f;

    load_tiles(0, 0);
    cpa_commit();

    const int arow = (lane & 15);
    const int asel = (lane >> 4) * 8;
    const int brow = (lane & 7);
    const int bsel = ((lane >> 3) & 1) * 8;

    for (int i = 0; i < nk; i++) {
        int cur = i & 1;
        if (i + 1 < nk) { load_tiles(i + 1, cur ^ 1); cpa_commit(); cpa_wait<1>(); }
        else            { cpa_wait<0>(); }
        __syncthreads();

        const __half* Ab = AsB + cur * 128 * HSTR;
        const __half* Bb = BsB + cur * 128 * HSTR;
#pragma unroll
        for (int kc = 0; kc < 2; kc++) {
            unsigned a[4][4], b[4][2];
            int acol = kc * 16 + asel;
            int bcol = kc * 16 + bsel;
#pragma unroll
            for (int mi = 0; mi < 4; mi++) {
                const __half* p = Ab + (wm * 64 + mi * 16 + arow) * HSTR + acol;
                LDM_X4(a[mi][0], a[mi][1], a[mi][2], a[mi][3], p);
            }
#pragma unroll
            for (int ni = 0; ni < 4; ni++) {
                const __half* p = Bb + (wn * 32 + ni * 8 + brow) * HSTR + bcol;
                LDM_X2(b[ni][0], b[ni][1], p);
            }
#pragma unroll
            for (int mi = 0; mi < 4; mi++)
#pragma unroll
                for (int ni = 0; ni < 4; ni++)
                    MMA_F16(acc[mi][ni], a[mi], b[ni]);
        }
        __syncthreads();
    }

#pragma unroll
    for (int mi = 0; mi < 4; mi++)
#pragma unroll
        for (int ni = 0; ni < 4; ni++)
#pragma unroll
            for (int h = 0; h < 2; h++) {
                int r = row0 + wm * 64 + mi * 16 + grp + h * 8;
                int cc = col0 + wn * 32 + ni * 8 + tig * 2;
                long long o = (long long)r * N + cc;
                float v0 = acc[mi][ni][h * 2 + 0];
                float v1 = acc[mi][ni][h * 2 + 1];
                if (HALF_OUT) {
                    *(__half2*)(Ch + o) = __floats2half2_rn(v0, v1);
                } else {
                    if (Res) { v0 += Res[o]; v1 += Res[o + 1]; }
                    Cf[o] = v0; Cf[o + 1] = v1;
                }
            }
}

// ------------------------- fused differential-combine + AV GEMM (fp16) ---------
#define AVM 64
#define VSTR 72

__global__ __launch_bounds__(256)
void av_k(const __half* __restrict__ Ph, const __half* __restrict__ V,
          const float* __restrict__ g, const float* __restrict__ lamp,
          float* __restrict__ O)
{
    __shared__ __half As[AVM * HSTR];    // 64 x 32 diff tile
    __shared__ __half Bs[GBK * VSTR];    // 32 x 64 V tile [k][n]

    const int h    = blockIdx.y;
    const int row0 = blockIdx.x * AVM;
    const int tid  = threadIdx.x;
    const int lane = tid & 31;
    const int warp = tid >> 5;
    const int wm   = warp >> 1;          // 0..3 (16 rows)
    const int wn   = warp & 1;           // 0..1 (32 cols)
    const int grp  = lane >> 2;
    const int tig  = lane & 3;

    const float lam = *lamp;
    const __half* p1 = Ph + (long long)(2 * h) * S_LEN * S_LEN;
    const __half* p2 = Ph + (long long)(2 * h + 1) * S_LEN * S_LEN;
    const __half* Vh = V + (long long)h * S_LEN * HD;
    const float*  gh = g + h * S_LEN;

    float acc[4][4];
#pragma unroll
    for (int j = 0; j < 4; j++)
#pragma unroll
        for (int l = 0; l < 4; l++) acc[j][l] = 0.f;

    const int dr  = tid >> 2;            // 0..63
    const int dc8 = (tid & 3) * 8;
    const int ip  = (row0 + dr) % SPP;

    for (int j0 = 0; j0 < S_LEN; j0 += GBK) {
        // V tile: 32 rows x 64 halves, 1 chunk of 8 per thread
        {
            int kk = tid >> 3, c8 = (tid & 7) * 8;
            cpa16(Bs + kk * VSTR + c8, Vh + (long long)(j0 + kk) * HD + c8);
        }
        cpa_commit();

        // diff tile: 1 chunk of 8 per thread
        {
            long long off = (long long)(row0 + dr) * S_LEN + j0 + dc8;
            const __half* q1 = p1 + off;
            const __half* q2 = p2 + off;
            uint4 u1 = *(const uint4*)q1;
            uint4 u2 = *(const uint4*)q2;
            const __half2* h1 = (const __half2*)&u1;
            const __half2* h2 = (const __half2*)&u2;
            __half outh[8];
            int jb = j0 + dc8;
#pragma unroll
            for (int e = 0; e < 4; e++) {
                float2 f1 = __half22float2(h1[e]);
                float2 f2 = __half22float2(h2[e]);
                int ja = jb + 2 * e, jbb = ja + 1;
                float o0 = ((ja  % SPP) > ip) ? 0.f : (f1.x - lam * f2.x + lam * gh[ja]);
                float o1 = ((jbb % SPP) > ip) ? 0.f : (f1.y - lam * f2.y + lam * gh[jbb]);
                outh[2 * e]     = __float2half_rn(o0);
                outh[2 * e + 1] = __float2half_rn(o1);
            }
            *(uint4*)(As + dr * HSTR + dc8) = *(uint4*)outh;
        }
        cpa_wait<0>();
        __syncthreads();

#pragma unroll
        for (int kc = 0; kc < 2; kc++) {
            unsigned a[4], b[4][2];
            {
                const __half* p = As + (wm * 16 + (lane & 15)) * HSTR
                                     + kc * 16 + (lane >> 4) * 8;
                LDM_X4(a[0], a[1], a[2], a[3], p);
            }
#pragma unroll
            for (int ni = 0; ni < 4; ni++) {
                int krow = kc * 16 + ((lane >> 3) & 1) * 8 + (lane & 7);
                int ncol = wn * 32 + ni * 8;
                const __half* p = Bs + krow * VSTR + ncol;
                LDM_X2T(b[ni][0], b[ni][1], p);
            }
#pragma unroll
            for (int ni = 0; ni < 4; ni++)
                MMA_F16(acc[ni], a, b[ni]);
        }
        __syncthreads();
    }

#pragma unroll
    for (int ni = 0; ni < 4; ni++)
#pragma unroll
        for (int hh = 0; hh < 2; hh++) {
            int r = row0 + wm * 16 + grp + hh * 8;
            int cc = wn * 32 + ni * 8 + tig * 2;
            long long o = ((long long)h * S_LEN + r) * HD + cc;
            O[o]     = acc[ni][hh * 2 + 0];
            O[o + 1] = acc[ni][hh * 2 + 1];
        }
}

// ------------------------- rmsnorm: fp32 in -> fp16 out -------------------------
__global__ void rmsnorm_h(const float* __restrict__ in, const float* __restrict__ w,
                          __half* __restrict__ out, int cols, int in_ld, int out_ld,
                          float eps)
{
    const long long row = blockIdx.x;
    const float* ip = in + row * in_ld;
    __half* op = out + row * out_ld;

    float ss = 0.f;
    for (int j = threadIdx.x; j < cols; j += blockDim.x) {
        float v = ip[j];
        ss += v * v;
    }
    __shared__ float sh[32];
    int lane = threadIdx.x & 31, wid = threadIdx.x >> 5;
#pragma unroll
    for (int o = 16; o; o >>= 1) ss += __shfl_xor_sync(0xffffffffu, ss, o);
    if (lane == 0) sh[wid] = ss;
    __syncthreads();
    int nw = (blockDim.x + 31) >> 5;
    float tot = 0.f;
    if (threadIdx.x < nw) tot = sh[threadIdx.x];
    if (wid == 0) {
#pragma unroll
        for (int o = 16; o; o >>= 1) tot += __shfl_xor_sync(0xffffffffu, tot, o);
        if (lane == 0) sh[0] = tot;
    }
    __syncthreads();
    float inv = rsqrtf(sh[0] / (float)cols + eps);
    for (int j = threadIdx.x; j < cols; j += blockDim.x)
        op[j] = __float2half_rn(ip[j] * inv * w[j]);
}

// ------------------------- build Q/K/V with RoPE (fp16 out) --------------------
__global__ void build_qkv_k(const __half* __restrict__ qf, const __half* __restrict__ kvup,
                            const float* __restrict__ ckv,
                            const float* __restrict__ fcos, const float* __restrict__ fsin,
                            __half* __restrict__ Q, __half* __restrict__ K,
                            __half* __restrict__ V)
{
    const int i = blockIdx.x;
    const int tid = threadIdx.x;              // 128
    __shared__ float cs[8], sn[8];
    int p = i >> 2;
    if (tid < 8) {
        if (p == 0) { cs[tid] = 1.f; sn[tid] = 0.f; }
        else { cs[tid] = fcos[(p - 1) * 8 + tid]; sn[tid] = fsin[(p - 1) * 8 + tid]; }
    }
    __syncthreads();

    const __half* qrow = qf + (long long)i * 1536;
    const __half* krow = kvup + (long long)i * 2048;
    const float*  crow = ckv + (long long)i * 384;

    for (int e = tid; e < H2 * DQKP; e += 128) {
        int h2 = e / DQKP, d = e % DQKP;
        int h = h2 >> 1, c = h2 & 1;
        float qv = 0.f, kv = 0.f;
        if (d < 32) {
            qv = __half2float(qrow[h * 96 + c * 32 + d]);
            kv = __half2float(krow[h * 128 + c * 32 + d]);
        } else if (d < DQK) {
            int ee = d - 32;
            int f = ee >> 1;
            float q0 = __half2float(qrow[h * 96 + 64 + c * 16 + 2 * f]);
            float q1 = __half2float(qrow[h * 96 + 64 + c * 16 + 2 * f + 1]);
            float k0 = crow[KVCC + c * 16 + 2 * f];
            float k1 = crow[KVCC + c * 16 + 2 * f + 1];
            float C = cs[f], Sv = sn[f];
            if ((ee & 1) == 0) { qv = q0 * C - q1 * Sv; kv = k0 * C - k1 * Sv; }
            else               { qv = q0 * Sv + q1 * C; kv = k0 * Sv + k1 * C; }
        }
        Q[(long long)h2 * S_LEN * DQKP + (long long)i * DQKP + d] = __float2half_rn(qv);
        K[(long long)h2 * S_LEN * DQKP + (long long)i * DQKP + d] = __float2half_rn(kv);
    }
    for (int e = tid; e < NH * HD; e += 128) {
        int h = e >> 6, d = e & 63;
        V[(long long)h * S_LEN * HD + (long long)i * HD + d] = krow[h * 128 + 64 + d];
    }
}

// ------------------------- register softmax: fp32 logits -> fp16 probs ---------
__global__ __launch_bounds__(256)
void softmax2_k(const float* __restrict__ P, __half* __restrict__ Ph)
{
    const long long rowi = blockIdx.x;
    const int r = (int)(rowi % S_LEN);
    const float* row = P + rowi * S_LEN;
    __half* orow = Ph + rowi * S_LEN;
    const int rp = r % SPP;
    const int tid = threadIdx.x;

    __shared__ float sh[32];
    int lane = tid & 31, wid = tid >> 5;

    float v[6];
    bool msk[6];
#pragma unroll
    for (int l = 0; l < 6; l++) {
        int j = tid + l * 256;
        msk[l] = (j % SPP) > rp;
        v[l] = msk[l] ? -3.4e38f : row[j] * SCALING;
    }
    float mx = v[0];
#pragma unroll
    for (int l = 1; l < 6; l++) mx = fmaxf(mx, v[l]);
#pragma unroll
    for (int o = 16; o; o >>= 1) mx = fmaxf(mx, __shfl_xor_sync(0xffffffffu, mx, o));
    if (lane == 0) sh[wid] = mx;
    __syncthreads();
    float gmx = sh[lane & 7];
#pragma unroll
    for (int o = 4; o; o >>= 1) gmx = fmaxf(gmx, __shfl_xor_sync(0xffffffffu, gmx, o));

    float sum = 0.f;
#pragma unroll
    for (int l = 0; l < 6; l++) {
        float e = msk[l] ? 0.f : __expf(v[l] - gmx);
        v[l] = e;
        sum += e;
    }
#pragma unroll
    for (int o = 16; o; o >>= 1) sum += __shfl_xor_sync(0xffffffffu, sum, o);
    __syncthreads();
    if (lane == 0) sh[wid] = sum;
    __syncthreads();
    float gs = sh[lane & 7];
#pragma unroll
    for (int o = 4; o; o >>= 1) gs += __shfl_xor_sync(0xffffffffu, gs, o);
    float inv = 1.f / gs;

#pragma unroll
    for (int l = 0; l < 6; l++)
        orow[tid + l * 256] = __float2half_rn(v[l] * inv);
}

// ------------------------- column mean of even sub-heads (fp16 in) -------------
__global__ void colmean_k(const __half* __restrict__ Ph, float* __restrict__ g)
{
    int j = blockIdx.x * blockDim.x + threadIdx.x;
    int h = blockIdx.y;
    if (j >= S_LEN) return;
    const __half* base = Ph + (long long)(2 * h) * S_LEN * S_LEN + j;
    float s = 0.f;
    for (int i = 0; i < S_LEN; i++) s += __half2float(base[(long long)i * S_LEN]);
    g[h * S_LEN + j] = s / (float)S_LEN;
}

// ------------------------- lambda scalar -------------------------
__global__ void lambda_k_(const float* __restrict__ q1, const float* __restrict__ k1,
                          const float* __restrict__ q2, const float* __restrict__ k2,
                          float* __restrict__ out)
{
    int t = threadIdx.x;
    float a = q1[t] * k1[t];
    float b = q2[t] * k2[t];
#pragma unroll
    for (int o = 16; o; o >>= 1) {
        a += __shfl_xor_sync(0xffffffffu, a, o);
        b += __shfl_xor_sync(0xffffffffu, b, o);
    }
    if (t == 0) *out = expf(a) - expf(b) + LAMBDA_INIT;
}

// ------------------------- per (token, head) rmsnorm: fp32 -> fp16 -------------
__global__ void attn_norm_k(const float* __restrict__ ao, const float* __restrict__ w,
                            __half* __restrict__ outf)
{
    int i = blockIdx.x, h = blockIdx.y, d = threadIdx.x;
    long long idx = ((long long)h * S_LEN + i) * HD + d;
    float v = ao[idx];
    float sq = v * v;
    __shared__ float sh[2];
#pragma unroll
    for (int o = 16; o; o >>= 1) sq += __shfl_xor_sync(0xffffffffu, sq, o);
    if ((d & 31) == 0) sh[d >> 5] = sq;
    __syncthreads();
    float tot = sh[0] + sh[1];
    outf[idx] = __float2half_rn(v * rsqrtf(tot / (float)HD + ATTN_EPS) * w[d]);
}

// ------------------------- SwiGLU: fp16 in -> fp16 out -------------------------
__global__ void swiglu_k(const __half* __restrict__ uv, __half* __restrict__ act)
{
    long long idx = (long long)blockIdx.x * blockDim.x + threadIdx.x;
    if (idx >= (long long)S_LEN * DFF) return;
    long long i = idx / DFF, j = idx % DFF;
    float u  = __half2float(uv[i * (2 * DFF) + j]);
    float vg = __half2float(uv[i * (2 * DFF) + DFF + j]);
    act[idx] = __float2half_rn(u * (vg / (1.f + __expf(-vg))));
}

// ------------------------- fp32 -> fp16 weight convert (vectorized) ------------
__global__ void cvt_h_k(const float* __restrict__ in, __half* __restrict__ out, int n)
{
    int i = (blockIdx.x * blockDim.x + threadIdx.x) * 4;
    int stride = gridDim.x * blockDim.x * 4;
    for (; i < n; i += stride) {
        float4 v = *(const float4*)(in + i);
        *(__half2*)(out + i)     = __floats2half2_rn(v.x, v.y);
        *(__half2*)(out + i + 2) = __floats2half2_rn(v.z, v.w);
    }
}
__global__ void zero_h_k(__half* __restrict__ p, int n)
{
    int i = blockIdx.x * blockDim.x + threadIdx.x;
    if (i < n) p[i] = __float2half(0.f);
}

// ------------------------- host -------------------------
extern "C" void kernel_launch(void* const* d_in, const int* in_sizes, int n_in,
                              void* d_out, int out_size)
{
    const float* x    = (const float*)d_in[0];
    const float* fc   = (const float*)d_in[1];
    const float* fs   = (const float*)d_in[2];
    const float* n1w  = (const float*)d_in[3];
    const float* n2w  = (const float*)d_in[4];
    const float* kvdw = (const float*)d_in[5];
    const float* qdw  = (const float*)d_in[6];
    const float* kvnw = (const float*)d_in[7];
    const float* qnw  = (const float*)d_in[8];
    const float* kvuw = (const float*)d_in[9];
    const float* quw  = (const float*)d_in[10];
    const float* lq1  = (const float*)d_in[11];
    const float* lk1  = (const float*)d_in[12];
    const float* lq2  = (const float*)d_in[13];
    const float* lk2  = (const float*)d_in[14];
    const float* anw  = (const float*)d_in[15];
    const float* ow   = (const float*)d_in[16];
    const float* fiw  = (const float*)d_in[17];
    const float* fow  = (const float*)d_in[18];
    float* outp = (float*)d_out;

    __half *xin, *ckvn, *kvup, *cqn, *qf, *Q, *K, *V, *Ph, *af, *hb, *uv, *act;
    __half *kvdw_h, *qdw_h, *kvuw_h, *quw_h, *ow_h, *fiw_h, *fow_h;
    float *ckv, *cq, *P, *gg, *ao, *x2, *lam;
    cudaGetSymbolAddress((void**)&xin,  g_xin);
    cudaGetSymbolAddress((void**)&ckv,  g_ckv);
    cudaGetSymbolAddress((void**)&ckvn, g_ckvn);
    cudaGetSymbolAddress((void**)&kvup, g_kvup);
    cudaGetSymbolAddress((void**)&cq,   g_cq);
    cudaGetSymbolAddress((void**)&cqn,  g_cqn);
    cudaGetSymbolAddress((void**)&qf,   g_qf);
    cudaGetSymbolAddress((void**)&Q,    g_Q);
    cudaGetSymbolAddress((void**)&K,    g_K);
    cudaGetSymbolAddress((void**)&V,    g_V);
    cudaGetSymbolAddress((void**)&P,    g_P);
    cudaGetSymbolAddress((void**)&Ph,   g_Ph);
    cudaGetSymbolAddress((void**)&gg,   g_g);
    cudaGetSymbolAddress((void**)&ao,   g_ao);
    cudaGetSymbolAddress((void**)&af,   g_af);
    cudaGetSymbolAddress((void**)&x2,   g_x2);
    cudaGetSymbolAddress((void**)&hb,   g_hb);
    cudaGetSymbolAddress((void**)&uv,   g_uv);
    cudaGetSymbolAddress((void**)&act,  g_act);
    cudaGetSymbolAddress((void**)&lam,  g_lambda);
    cudaGetSymbolAddress((void**)&kvdw_h, g_kvdw_h);
    cudaGetSymbolAddress((void**)&qdw_h,  g_qdw_h);
    cudaGetSymbolAddress((void**)&kvuw_h, g_kvuw_h);
    cudaGetSymbolAddress((void**)&quw_h,  g_quw_h);
    cudaGetSymbolAddress((void**)&ow_h,   g_ow_h);
    cudaGetSymbolAddress((void**)&fiw_h,  g_fiw_h);
    cudaGetSymbolAddress((void**)&fow_h,  g_fow_h);

    static bool attr_set = false;
    if (!attr_set) {
        cudaFuncSetAttribute(hgemm<false>, cudaFuncAttributeMaxDynamicSharedMemorySize, SMEM_H);
        cudaFuncSetAttribute(hgemm<true>,  cudaFuncAttributeMaxDynamicSharedMemorySize, SMEM_H);
        attr_set = true;
    }

    auto grid_g = [](int M, int N, int batch) {
        return dim3((unsigned)(N / 128), (unsigned)(M / 128), (unsigned)batch);
    };

    // 0. weights -> fp16 (+ zero-pad kv_down rows 288..383)
    cvt_h_k<<<288,  256>>>(kvdw, kvdw_h, 288 * DM);
    zero_h_k<<<(96 * DM + 255) / 256, 256>>>(kvdw_h + 288 * DM, 96 * DM);
    cvt_h_k<<<384,  256>>>(qdw,  qdw_h,  QCC * DM);
    cvt_h_k<<<512,  256>>>(kvuw, kvuw_h, 2048 * KVCC);
    cvt_h_k<<<576,  256>>>(quw,  quw_h,  1536 * QCC);
    cvt_h_k<<<1024, 256>>>(ow,   ow_h,   DM * DM);
    cvt_h_k<<<4096, 256>>>(fiw,  fiw_h,  2 * DFF * DM);
    cvt_h_k<<<4096, 256>>>(fow,  fow_h,  DM * DFF);

    // 1. xin = rmsnorm(x) -> fp16
    rmsnorm_h<<<S_LEN, 256>>>(x, n1w, xin, DM, DM, DM, EPS_RMS);
    // 2. ckv = xin @ kv_down^T  [1536, 384(pad)] fp32
    hgemm<false><<<grid_g(S_LEN, 384, 1), 256, SMEM_H>>>(xin, kvdw_h, nullptr, ckv,
        S_LEN, 384, DM, 0, 0, 0);
    // 3. ckvn = rmsnorm(ckv[:, :256]) -> fp16
    rmsnorm_h<<<S_LEN, 256>>>(ckv, kvnw, ckvn, KVCC, 384, KVCC, EPS_RMS);
    // 4. kvup = ckvn @ kv_up^T [1536, 2048] fp16
    hgemm<true><<<grid_g(S_LEN, 2048, 1), 256, SMEM_H>>>(ckvn, kvuw_h, nullptr, kvup,
        S_LEN, 2048, KVCC, 0, 0, 0);
    // 5. cq = xin @ q_down^T [1536, 384] fp32
    hgemm<false><<<grid_g(S_LEN, QCC, 1), 256, SMEM_H>>>(xin, qdw_h, nullptr, cq,
        S_LEN, QCC, DM, 0, 0, 0);
    // 6. cqn = rmsnorm(cq) -> fp16
    rmsnorm_h<<<S_LEN, 256>>>(cq, qnw, cqn, QCC, QCC, QCC, EPS_RMS);
    // 7. qf = cqn @ q_up^T [1536, 1536] fp16
    hgemm<true><<<grid_g(S_LEN, 1536, 1), 256, SMEM_H>>>(cqn, quw_h, nullptr, qf,
        S_LEN, 1536, QCC, 0, 0, 0);
    // 8. build Q/K/V (fp16, Q/K padded to 64)
    build_qkv_k<<<S_LEN, 128>>>(qf, kvup, ckv, fc, fs, Q, K, V);
    // 9. logits: P[h] = Q[h] @ K[h]^T fp32, 32 sub-heads, K=64
    hgemm<false><<<grid_g(S_LEN, S_LEN, H2), 256, SMEM_H>>>(Q, K, nullptr, P,
        S_LEN, S_LEN, DQKP,
        (long long)S_LEN * DQKP, (long long)S_LEN * DQKP, (long long)S_LEN * S_LEN);
    // 10. lambda
    lambda_k_<<<1, 32>>>(lq1, lk1, lq2, lk2, lam);
    // 11. softmax: fp32 logits -> fp16 probs
    softmax2_k<<<H2 * S_LEN, 256>>>(P, Ph);
    // 12. column means (fp16 in)
    colmean_k<<<dim3((S_LEN + 255) / 256, NH), 256>>>(Ph, gg);
    // 13+14. fused combine + AV (fp16 mma)
    av_k<<<dim3(S_LEN / AVM, NH), 256>>>(Ph, V, gg, lam, ao);
    // 15. attn rmsnorm -> fp16 (keeps [h][i][d] scrambled-reshape layout)
    attn_norm_k<<<dim3(S_LEN, NH), 64>>>(ao, anw, af);
    // 16. x2 = x + af @ o_w^T fp32
    hgemm<false><<<grid_g(S_LEN, DM, 1), 256, SMEM_H>>>(af, ow_h, x, x2,
        S_LEN, DM, DM, 0, 0, 0);
    // 17. hb = rmsnorm(x2) -> fp16
    rmsnorm_h<<<S_LEN, 256>>>(x2, n2w, hb, DM, DM, DM, EPS_RMS);
    // 18. uv = hb @ ff_in^T [1536, 8192] fp16
    hgemm<true><<<grid_g(S_LEN, 2 * DFF, 1), 256, SMEM_H>>>(hb, fiw_h, nullptr, uv,
        S_LEN, 2 * DFF, DM, 0, 0, 0);
    // 19. act = u * silu(vg) fp16
    {
        long long tot = (long long)S_LEN * DFF;
        swiglu_k<<<(unsigned)((tot + 255) / 256), 256>>>(uv, act);
    }
    // 20. out = x2 + act @ ff_out^T fp32
    hgemm<false><<<grid_g(S_LEN, DM, 1), 256, SMEM_H>>>(act, fow_h, x2, outp,
        S_LEN, DM, DFF, 0, 0, 0);
}

// round 9
// speedup vs baseline: 6.4891x; 1.0899x over previous
#include <cuda_runtime.h>
#include <cuda_fp16.h>
#include <math.h>
#include <stdint.h>

#define S_LEN 1536
#define DM    1024
#define NH    16
#define HD    64
#define H2    32
#define DQK   48
#define DQKP  64
#define KVCC  256
#define ROPE_ 32
#define QCC   384
#define DFF   4096
#define SPP   384
#define EPS_RMS 1.1920929e-07f
#define ATTN_EPS 1e-5f
#define SCALING 0.14433756729740643f
#define LAMBDA_INIT 0.2f

// ------------------------- device scratch -------------------------
__device__ __half g_xin [S_LEN * DM];
__device__ float  g_ckv [S_LEN * 384];            // stride 384 (padded N)
__device__ __half g_ckvn[S_LEN * KVCC];
__device__ __half g_kvup[S_LEN * 2048];
__device__ float  g_cq  [S_LEN * QCC];
__device__ __half g_cqn [S_LEN * QCC];
__device__ __half g_qf  [S_LEN * 1536];
__device__ __half g_Q   [(size_t)H2 * S_LEN * DQKP];
__device__ __half g_K   [(size_t)H2 * S_LEN * DQKP];
__device__ __half g_V   [(size_t)NH * S_LEN * HD];
__device__ __half g_Ph  [(size_t)H2 * S_LEN * S_LEN];   // scaled logits -> probs, fp16
__device__ float  g_g   [NH * S_LEN];
__device__ float  g_ao  [(size_t)NH * S_LEN * HD];
__device__ __half g_af  [S_LEN * DM];
__device__ float  g_x2  [S_LEN * DM];
__device__ __half g_hb  [S_LEN * DM];
__device__ __half g_uv  [(size_t)S_LEN * 2 * DFF];
__device__ __half g_act [(size_t)S_LEN * DFF];
__device__ float  g_lambda;
// fp16 weight copies
__device__ __half g_kvdw_h[384 * DM];             // padded 288 -> 384 rows
__device__ __half g_qdw_h [QCC * DM];
__device__ __half g_kvuw_h[2048 * KVCC];
__device__ __half g_quw_h [1536 * QCC];
__device__ __half g_ow_h  [(size_t)DM * DM];
__device__ __half g_fiw_h [(size_t)2 * DFF * DM];
__device__ __half g_fow_h [(size_t)DM * DFF];

// ------------------------- helpers -------------------------
__device__ __forceinline__ void cpa16(void* smem_dst, const void* gsrc) {
    unsigned a = (unsigned)__cvta_generic_to_shared(smem_dst);
    asm volatile("cp.async.ca.shared.global [%0], [%1], 16;\n" :: "r"(a), "l"(gsrc));
}
__device__ __forceinline__ void cpa_commit() { asm volatile("cp.async.commit_group;\n"); }
template <int NG>
__device__ __forceinline__ void cpa_wait() { asm volatile("cp.async.wait_group %0;\n" :: "n"(NG)); }

#define LDM_X4(a0,a1,a2,a3,p) \
    asm volatile("ldmatrix.sync.aligned.m8n8.x4.shared.b16 {%0,%1,%2,%3}, [%4];" \
        : "=r"(a0), "=r"(a1), "=r"(a2), "=r"(a3) \
        : "r"((unsigned)__cvta_generic_to_shared(p)))
#define LDM_X2(b0,b1,p) \
    asm volatile("ldmatrix.sync.aligned.m8n8.x2.shared.b16 {%0,%1}, [%2];" \
        : "=r"(b0), "=r"(b1) \
        : "r"((unsigned)__cvta_generic_to_shared(p)))
#define LDM_X2T(b0,b1,p) \
    asm volatile("ldmatrix.sync.aligned.m8n8.x2.trans.shared.b16 {%0,%1}, [%2];" \
        : "=r"(b0), "=r"(b1) \
        : "r"((unsigned)__cvta_generic_to_shared(p)))
#define MMA_F16(d, a, b) \
    asm volatile( \
        "mma.sync.aligned.m16n8k16.row.col.f32.f16.f16.f32 " \
        "{%0,%1,%2,%3}, {%4,%5,%6,%7}, {%8,%9}, {%0,%1,%2,%3};" \
        : "+f"(d[0]), "+f"(d[1]), "+f"(d[2]), "+f"(d[3]) \
        : "r"(a[0]), "r"(a[1]), "r"(a[2]), "r"(a[3]), "r"(b[0]), "r"(b[1]))

#define HSTR 40    /* halves; 80B row stride -> conflict-free ldmatrix */
#define GBK  32

// ------------------------- FP16 GEMM: 128x128 tiles, C = scale*(A*B^T) (+Res) ---
// A[M,K], B[N,K] row-major __half. M%128==0, N%128==0, K%32==0. Batched via z.
#define SMEM_H (2 * 2 * 128 * HSTR * 2)

template <bool HALF_OUT>
__global__ __launch_bounds__(256, 2)
void hgemm(const __half* __restrict__ A, const __half* __restrict__ B,
           const float* __restrict__ Res, void* __restrict__ Cv,
           int M, int N, int K, long long sA, long long sB, long long sC,
           float scale)
{
    extern __shared__ __half hsm[];
    __half* AsB = hsm;                   // [2][128*HSTR]
    __half* BsB = hsm + 2 * 128 * HSTR;  // [2][128*HSTR]

    A += (long long)blockIdx.z * sA;
    B += (long long)blockIdx.z * sB;
    float*  Cf = (float*)Cv  + (long long)blockIdx.z * sC;
    __half* Ch = (__half*)Cv + (long long)blockIdx.z * sC;

    const int tid  = threadIdx.x;
    const int lane = tid & 31;
    const int warp = tid >> 5;
    const int wm   = warp >> 2;
    const int wn   = warp & 3;
    const int row0 = blockIdx.y * 128;
    const int col0 = blockIdx.x * 128;
    const int grp  = lane >> 2;
    const int tig  = lane & 3;

    const int nk = K / GBK;

    auto load_tiles = [&](int ki, int buf) {
        const __half* Ag = A + (long long)row0 * K + ki * GBK;
        __half* Ad = AsB + buf * 128 * HSTR;
#pragma unroll
        for (int it = 0; it < 2; it++) {
            int f = tid + it * 256;
            int r = f >> 2, c8 = (f & 3) * 8;
            cpa16(Ad + r * HSTR + c8, Ag + (long long)r * K + c8);
        }
        const __half* Bg = B + (long long)col0 * K + ki * GBK;
        __half* Bd = BsB + buf * 128 * HSTR;
#pragma unroll
        for (int it = 0; it < 2; it++) {
            int f = tid + it * 256;
            int r = f >> 2, c8 = (f & 3) * 8;
            cpa16(Bd + r * HSTR + c8, Bg + (long long)r * K + c8);
        }
    };

    float acc[4][4][4];
#pragma unroll
    for (int i = 0; i < 4; i++)
#pragma unroll
        for (int j = 0; j < 4; j++)
#pragma unroll
            for (int l = 0; l < 4; l++) acc[i][j][l] = 0.f;

    load_tiles(0, 0);
    cpa_commit();

    const int arow = (lane & 15);
    const int asel = (lane >> 4) * 8;
    const int brow = (lane & 7);
    const int bsel = ((lane >> 3) & 1) * 8;

    for (int i = 0; i < nk; i++) {
        int cur = i & 1;
        if (i + 1 < nk) { load_tiles(i + 1, cur ^ 1); cpa_commit(); cpa_wait<1>(); }
        else            { cpa_wait<0>(); }
        __syncthreads();

        const __half* Ab = AsB + cur * 128 * HSTR;
        const __half* Bb = BsB + cur * 128 * HSTR;
#pragma unroll
        for (int kc = 0; kc < 2; kc++) {
            unsigned a[4][4], b[4][2];
            int acol = kc * 16 + asel;
            int bcol = kc * 16 + bsel;
#pragma unroll
            for (int mi = 0; mi < 4; mi++) {
                const __half* p = Ab + (wm * 64 + mi * 16 + arow) * HSTR + acol;
                LDM_X4(a[mi][0], a[mi][1], a[mi][2], a[mi][3], p);
            }
#pragma unroll
            for (int ni = 0; ni < 4; ni++) {
                const __half* p = Bb + (wn * 32 + ni * 8 + brow) * HSTR + bcol;
                LDM_X2(b[ni][0], b[ni][1], p);
            }
#pragma unroll
            for (int mi = 0; mi < 4; mi++)
#pragma unroll
                for (int ni = 0; ni < 4; ni++)
                    MMA_F16(acc[mi][ni], a[mi], b[ni]);
        }
        __syncthreads();
    }

#pragma unroll
    for (int mi = 0; mi < 4; mi++)
#pragma unroll
        for (int ni = 0; ni < 4; ni++)
#pragma unroll
            for (int h = 0; h < 2; h++) {
                int r = row0 + wm * 64 + mi * 16 + grp + h * 8;
                int cc = col0 + wn * 32 + ni * 8 + tig * 2;
                long long o = (long long)r * N + cc;
                float v0 = acc[mi][ni][h * 2 + 0] * scale;
                float v1 = acc[mi][ni][h * 2 + 1] * scale;
                if (HALF_OUT) {
                    *(__half2*)(Ch + o) = __floats2half2_rn(v0, v1);
                } else {
                    if (Res) { v0 += Res[o]; v1 += Res[o + 1]; }
                    Cf[o] = v0; Cf[o + 1] = v1;
                }
            }
}

// ------------------------- fused differential-combine + AV GEMM (fp16) ---------
#define AVM 64
#define VSTR 72

__global__ __launch_bounds__(256)
void av_k(const __half* __restrict__ Ph, const __half* __restrict__ V,
          const float* __restrict__ g, const float* __restrict__ lamp,
          float* __restrict__ O)
{
    __shared__ __half As[AVM * HSTR];
    __shared__ __half Bs[GBK * VSTR];

    const int h    = blockIdx.y;
    const int row0 = blockIdx.x * AVM;
    const int tid  = threadIdx.x;
    const int lane = tid & 31;
    const int warp = tid >> 5;
    const int wm   = warp >> 1;
    const int wn   = warp & 1;
    const int grp  = lane >> 2;
    const int tig  = lane & 3;

    const float lam = *lamp;
    const __half* p1 = Ph + (long long)(2 * h) * S_LEN * S_LEN;
    const __half* p2 = Ph + (long long)(2 * h + 1) * S_LEN * S_LEN;
    const __half* Vh = V + (long long)h * S_LEN * HD;
    const float*  gh = g + h * S_LEN;

    float acc[4][4];
#pragma unroll
    for (int j = 0; j < 4; j++)
#pragma unroll
        for (int l = 0; l < 4; l++) acc[j][l] = 0.f;

    const int dr  = tid >> 2;
    const int dc8 = (tid & 3) * 8;
    const int ip  = (row0 + dr) % SPP;

    for (int j0 = 0; j0 < S_LEN; j0 += GBK) {
        {
            int kk = tid >> 3, c8 = (tid & 7) * 8;
            cpa16(Bs + kk * VSTR + c8, Vh + (long long)(j0 + kk) * HD + c8);
        }
        cpa_commit();

        {
            long long off = (long long)(row0 + dr) * S_LEN + j0 + dc8;
            uint4 u1 = *(const uint4*)(p1 + off);
            uint4 u2 = *(const uint4*)(p2 + off);
            const __half2* h1 = (const __half2*)&u1;
            const __half2* h2 = (const __half2*)&u2;
            __half outh[8];
            int jb = j0 + dc8;
#pragma unroll
            for (int e = 0; e < 4; e++) {
                float2 f1 = __half22float2(h1[e]);
                float2 f2 = __half22float2(h2[e]);
                int ja = jb + 2 * e, jbb = ja + 1;
                float o0 = ((ja  % SPP) > ip) ? 0.f : (f1.x - lam * f2.x + lam * gh[ja]);
                float o1 = ((jbb % SPP) > ip) ? 0.f : (f1.y - lam * f2.y + lam * gh[jbb]);
                outh[2 * e]     = __float2half_rn(o0);
                outh[2 * e + 1] = __float2half_rn(o1);
            }
            *(uint4*)(As + dr * HSTR + dc8) = *(uint4*)outh;
        }
        cpa_wait<0>();
        __syncthreads();

#pragma unroll
        for (int kc = 0; kc < 2; kc++) {
            unsigned a[4], b[4][2];
            {
                const __half* p = As + (wm * 16 + (lane & 15)) * HSTR
                                     + kc * 16 + (lane >> 4) * 8;
                LDM_X4(a[0], a[1], a[2], a[3], p);
            }
#pragma unroll
            for (int ni = 0; ni < 4; ni++) {
                int krow = kc * 16 + ((lane >> 3) & 1) * 8 + (lane & 7);
                int ncol = wn * 32 + ni * 8;
                const __half* p = Bs + krow * VSTR + ncol;
                LDM_X2T(b[ni][0], b[ni][1], p);
            }
#pragma unroll
            for (int ni = 0; ni < 4; ni++)
                MMA_F16(acc[ni], a, b[ni]);
        }
        __syncthreads();
    }

#pragma unroll
    for (int ni = 0; ni < 4; ni++)
#pragma unroll
        for (int hh = 0; hh < 2; hh++) {
            int r = row0 + wm * 16 + grp + hh * 8;
            int cc = wn * 32 + ni * 8 + tig * 2;
            long long o = ((long long)h * S_LEN + r) * HD + cc;
            O[o]     = acc[ni][hh * 2 + 0];
            O[o + 1] = acc[ni][hh * 2 + 1];
        }
}

// ------------------------- rmsnorm: fp32 in -> fp16 out -------------------------
__global__ void rmsnorm_h(const float* __restrict__ in, const float* __restrict__ w,
                          __half* __restrict__ out, int cols, int in_ld, int out_ld,
                          float eps)
{
    const long long row = blockIdx.x;
    const float* ip = in + row * in_ld;
    __half* op = out + row * out_ld;

    float ss = 0.f;
    for (int j = threadIdx.x; j < cols; j += blockDim.x) {
        float v = ip[j];
        ss += v * v;
    }
    __shared__ float sh[32];
    int lane = threadIdx.x & 31, wid = threadIdx.x >> 5;
#pragma unroll
    for (int o = 16; o; o >>= 1) ss += __shfl_xor_sync(0xffffffffu, ss, o);
    if (lane == 0) sh[wid] = ss;
    __syncthreads();
    int nw = (blockDim.x + 31) >> 5;
    float tot = 0.f;
    if (threadIdx.x < nw) tot = sh[threadIdx.x];
    if (wid == 0) {
#pragma unroll
        for (int o = 16; o; o >>= 1) tot += __shfl_xor_sync(0xffffffffu, tot, o);
        if (lane == 0) sh[0] = tot;
    }
    __syncthreads();
    float inv = rsqrtf(sh[0] / (float)cols + eps);
    for (int j = threadIdx.x; j < cols; j += blockDim.x)
        op[j] = __float2half_rn(ip[j] * inv * w[j]);
}

// ------------------------- build Q/K/V with RoPE (fp16 out) --------------------
__global__ void build_qkv_k(const __half* __restrict__ qf, const __half* __restrict__ kvup,
                            const float* __restrict__ ckv,
                            const float* __restrict__ fcos, const float* __restrict__ fsin,
                            __half* __restrict__ Q, __half* __restrict__ K,
                            __half* __restrict__ V)
{
    const int i = blockIdx.x;
    const int tid = threadIdx.x;              // 128
    __shared__ float cs[8], sn[8];
    int p = i >> 2;
    if (tid < 8) {
        if (p == 0) { cs[tid] = 1.f; sn[tid] = 0.f; }
        else { cs[tid] = fcos[(p - 1) * 8 + tid]; sn[tid] = fsin[(p - 1) * 8 + tid]; }
    }
    __syncthreads();

    const __half* qrow = qf + (long long)i * 1536;
    const __half* krow = kvup + (long long)i * 2048;
    const float*  crow = ckv + (long long)i * 384;

    for (int e = tid; e < H2 * DQKP; e += 128) {
        int h2 = e / DQKP, d = e % DQKP;
        int h = h2 >> 1, c = h2 & 1;
        float qv = 0.f, kv = 0.f;
        if (d < 32) {
            qv = __half2float(qrow[h * 96 + c * 32 + d]);
            kv = __half2float(krow[h * 128 + c * 32 + d]);
        } else if (d < DQK) {
            int ee = d - 32;
            int f = ee >> 1;
            float q0 = __half2float(qrow[h * 96 + 64 + c * 16 + 2 * f]);
            float q1 = __half2float(qrow[h * 96 + 64 + c * 16 + 2 * f + 1]);
            float k0 = crow[KVCC + c * 16 + 2 * f];
            float k1 = crow[KVCC + c * 16 + 2 * f + 1];
            float C = cs[f], Sv = sn[f];
            if ((ee & 1) == 0) { qv = q0 * C - q1 * Sv; kv = k0 * C - k1 * Sv; }
            else               { qv = q0 * Sv + q1 * C; kv = k0 * Sv + k1 * C; }
        }
        Q[(long long)h2 * S_LEN * DQKP + (long long)i * DQKP + d] = __float2half_rn(qv);
        K[(long long)h2 * S_LEN * DQKP + (long long)i * DQKP + d] = __float2half_rn(kv);
    }
    for (int e = tid; e < NH * HD; e += 128) {
        int h = e >> 6, d = e & 63;
        V[(long long)h * S_LEN * HD + (long long)i * HD + d] = krow[h * 128 + 64 + d];
    }
}

// ------------- softmax: fp16 scaled logits -> fp16 probs, in place -------------
// 192 threads x 8 contiguous halves; SPP%8==0 so per-chunk mod never wraps.
__global__ __launch_bounds__(192)
void softmax3_k(__half* __restrict__ Ph)
{
    const long long rowi = blockIdx.x;
    const int r = (int)(rowi % S_LEN);
    __half* row = Ph + rowi * S_LEN;
    const int rp = r % SPP;
    const int tid = threadIdx.x;
    const int j0 = tid * 8;
    const int jm = j0 % SPP;

    __shared__ float sh[8];
    int lane = tid & 31, wid = tid >> 5;

    uint4 u = *(const uint4*)(row + j0);
    const __half2* hp = (const __half2*)&u;
    float v[8];
    bool msk[8];
#pragma unroll
    for (int e = 0; e < 4; e++) {
        float2 f = __half22float2(hp[e]);
        v[2 * e] = f.x; v[2 * e + 1] = f.y;
    }
#pragma unroll
    for (int e = 0; e < 8; e++) {
        msk[e] = (jm + e) > rp;
        if (msk[e]) v[e] = -3.4e38f;
    }
    float mx = v[0];
#pragma unroll
    for (int e = 1; e < 8; e++) mx = fmaxf(mx, v[e]);
#pragma unroll
    for (int o = 16; o; o >>= 1) mx = fmaxf(mx, __shfl_xor_sync(0xffffffffu, mx, o));
    if (lane == 0) sh[wid] = mx;
    __syncthreads();
    float gmx = sh[0];
#pragma unroll
    for (int w2 = 1; w2 < 6; w2++) gmx = fmaxf(gmx, sh[w2]);

    float sum = 0.f;
#pragma unroll
    for (int e = 0; e < 8; e++) {
        float ex = msk[e] ? 0.f : __expf(v[e] - gmx);
        v[e] = ex;
        sum += ex;
    }
#pragma unroll
    for (int o = 16; o; o >>= 1) sum += __shfl_xor_sync(0xffffffffu, sum, o);
    __syncthreads();
    if (lane == 0) sh[wid] = sum;
    __syncthreads();
    float gs = sh[0];
#pragma unroll
    for (int w2 = 1; w2 < 6; w2++) gs += sh[w2];
    float inv = 1.f / gs;

    uint4 o4;
    __half2* op = (__half2*)&o4;
#pragma unroll
    for (int e = 0; e < 4; e++)
        op[e] = __floats2half2_rn(v[2 * e] * inv, v[2 * e + 1] * inv);
    *(uint4*)(row + j0) = o4;
}

// ------------------------- column mean of even sub-heads (fp16 in) -------------
__global__ void colmean_k(const __half* __restrict__ Ph, float* __restrict__ g)
{
    int j = blockIdx.x * blockDim.x + threadIdx.x;
    int h = blockIdx.y;
    if (j >= S_LEN) return;
    const __half* base = Ph + (long long)(2 * h) * S_LEN * S_LEN + j;
    float s = 0.f;
    for (int i = 0; i < S_LEN; i++) s += __half2float(base[(long long)i * S_LEN]);
    g[h * S_LEN + j] = s / (float)S_LEN;
}

// ------------------------- lambda scalar -------------------------
__global__ void lambda_k_(const float* __restrict__ q1, const float* __restrict__ k1,
                          const float* __restrict__ q2, const float* __restrict__ k2,
                          float* __restrict__ out)
{
    int t = threadIdx.x;
    float a = q1[t] * k1[t];
    float b = q2[t] * k2[t];
#pragma unroll
    for (int o = 16; o; o >>= 1) {
        a += __shfl_xor_sync(0xffffffffu, a, o);
        b += __shfl_xor_sync(0xffffffffu, b, o);
    }
    if (t == 0) *out = expf(a) - expf(b) + LAMBDA_INIT;
}

// ------------------------- per (token, head) rmsnorm: fp32 -> fp16 -------------
__global__ void attn_norm_k(const float* __restrict__ ao, const float* __restrict__ w,
                            __half* __restrict__ outf)
{
    int i = blockIdx.x, h = blockIdx.y, d = threadIdx.x;
    long long idx = ((long long)h * S_LEN + i) * HD + d;
    float v = ao[idx];
    float sq = v * v;
    __shared__ float sh[2];
#pragma unroll
    for (int o = 16; o; o >>= 1) sq += __shfl_xor_sync(0xffffffffu, sq, o);
    if ((d & 31) == 0) sh[d >> 5] = sq;
    __syncthreads();
    float tot = sh[0] + sh[1];
    outf[idx] = __float2half_rn(v * rsqrtf(tot / (float)HD + ATTN_EPS) * w[d]);
}

// ------------------------- SwiGLU: fp16 in -> fp16 out -------------------------
__global__ void swiglu_k(const __half* __restrict__ uv, __half* __restrict__ act)
{
    long long idx = (long long)blockIdx.x * blockDim.x + threadIdx.x;
    if (idx >= (long long)S_LEN * DFF) return;
    long long i = idx / DFF, j = idx % DFF;
    float u  = __half2float(uv[i * (2 * DFF) + j]);
    float vg = __half2float(uv[i * (2 * DFF) + DFF + j]);
    act[idx] = __float2half_rn(u * (vg / (1.f + __expf(-vg))));
}

// ------------------------- fp32 -> fp16 weight convert (vectorized) ------------
__global__ void cvt_h_k(const float* __restrict__ in, __half* __restrict__ out, int n)
{
    int i = (blockIdx.x * blockDim.x + threadIdx.x) * 4;
    int stride = gridDim.x * blockDim.x * 4;
    for (; i < n; i += stride) {
        float4 v = *(const float4*)(in + i);
        *(__half2*)(out + i)     = __floats2half2_rn(v.x, v.y);
        *(__half2*)(out + i + 2) = __floats2half2_rn(v.z, v.w);
    }
}
__global__ void zero_h_k(__half* __restrict__ p, int n)
{
    int i = blockIdx.x * blockDim.x + threadIdx.x;
    if (i < n) p[i] = __float2half(0.f);
}

// ------------------------- host -------------------------
extern "C" void kernel_launch(void* const* d_in, const int* in_sizes, int n_in,
                              void* d_out, int out_size)
{
    const float* x    = (const float*)d_in[0];
    const float* fc   = (const float*)d_in[1];
    const float* fs   = (const float*)d_in[2];
    const float* n1w  = (const float*)d_in[3];
    const float* n2w  = (const float*)d_in[4];
    const float* kvdw = (const float*)d_in[5];
    const float* qdw  = (const float*)d_in[6];
    const float* kvnw = (const float*)d_in[7];
    const float* qnw  = (const float*)d_in[8];
    const float* kvuw = (const float*)d_in[9];
    const float* quw  = (const float*)d_in[10];
    const float* lq1  = (const float*)d_in[11];
    const float* lk1  = (const float*)d_in[12];
    const float* lq2  = (const float*)d_in[13];
    const float* lk2  = (const float*)d_in[14];
    const float* anw  = (const float*)d_in[15];
    const float* ow   = (const float*)d_in[16];
    const float* fiw  = (const float*)d_in[17];
    const float* fow  = (const float*)d_in[18];
    float* outp = (float*)d_out;

    __half *xin, *ckvn, *kvup, *cqn, *qf, *Q, *K, *V, *Ph, *af, *hb, *uv, *act;
    __half *kvdw_h, *qdw_h, *kvuw_h, *quw_h, *ow_h, *fiw_h, *fow_h;
    float *ckv, *cq, *gg, *ao, *x2, *lam;
    cudaGetSymbolAddress((void**)&xin,  g_xin);
    cudaGetSymbolAddress((void**)&ckv,  g_ckv);
    cudaGetSymbolAddress((void**)&ckvn, g_ckvn);
    cudaGetSymbolAddress((void**)&kvup, g_kvup);
    cudaGetSymbolAddress((void**)&cq,   g_cq);
    cudaGetSymbolAddress((void**)&cqn,  g_cqn);
    cudaGetSymbolAddress((void**)&qf,   g_qf);
    cudaGetSymbolAddress((void**)&Q,    g_Q);
    cudaGetSymbolAddress((void**)&K,    g_K);
    cudaGetSymbolAddress((void**)&V,    g_V);
    cudaGetSymbolAddress((void**)&Ph,   g_Ph);
    cudaGetSymbolAddress((void**)&gg,   g_g);
    cudaGetSymbolAddress((void**)&ao,   g_ao);
    cudaGetSymbolAddress((void**)&af,   g_af);
    cudaGetSymbolAddress((void**)&x2,   g_x2);
    cudaGetSymbolAddress((void**)&hb,   g_hb);
    cudaGetSymbolAddress((void**)&uv,   g_uv);
    cudaGetSymbolAddress((void**)&act,  g_act);
    cudaGetSymbolAddress((void**)&lam,  g_lambda);
    cudaGetSymbolAddress((void**)&kvdw_h, g_kvdw_h);
    cudaGetSymbolAddress((void**)&qdw_h,  g_qdw_h);
    cudaGetSymbolAddress((void**)&kvuw_h, g_kvuw_h);
    cudaGetSymbolAddress((void**)&quw_h,  g_quw_h);
    cudaGetSymbolAddress((void**)&ow_h,   g_ow_h);
    cudaGetSymbolAddress((void**)&fiw_h,  g_fiw_h);
    cudaGetSymbolAddress((void**)&fow_h,  g_fow_h);

    static bool attr_set = false;
    if (!attr_set) {
        cudaFuncSetAttribute(hgemm<false>, cudaFuncAttributeMaxDynamicSharedMemorySize, SMEM_H);
        cudaFuncSetAttribute(hgemm<true>,  cudaFuncAttributeMaxDynamicSharedMemorySize, SMEM_H);
        attr_set = true;
    }

    auto grid_g = [](int M, int N, int batch) {
        return dim3((unsigned)(N / 128), (unsigned)(M / 128), (unsigned)batch);
    };

    // 0. weights -> fp16 (+ zero-pad kv_down rows 288..383)
    cvt_h_k<<<288,  256>>>(kvdw, kvdw_h, 288 * DM);
    zero_h_k<<<(96 * DM + 255) / 256, 256>>>(kvdw_h + 288 * DM, 96 * DM);
    cvt_h_k<<<384,  256>>>(qdw,  qdw_h,  QCC * DM);
    cvt_h_k<<<512,  256>>>(kvuw, kvuw_h, 2048 * KVCC);
    cvt_h_k<<<576,  256>>>(quw,  quw_h,  1536 * QCC);
    cvt_h_k<<<1024, 256>>>(ow,   ow_h,   DM * DM);
    cvt_h_k<<<4096, 256>>>(fiw,  fiw_h,  2 * DFF * DM);
    cvt_h_k<<<4096, 256>>>(fow,  fow_h,  DM * DFF);

    // 1. xin = rmsnorm(x) -> fp16
    rmsnorm_h<<<S_LEN, 256>>>(x, n1w, xin, DM, DM, DM, EPS_RMS);
    // 2. ckv = xin @ kv_down^T  [1536, 384(pad)] fp32
    hgemm<false><<<grid_g(S_LEN, 384, 1), 256, SMEM_H>>>(xin, kvdw_h, nullptr, ckv,
        S_LEN, 384, DM, 0, 0, 0, 1.f);
    // 3. ckvn = rmsnorm(ckv[:, :256]) -> fp16
    rmsnorm_h<<<S_LEN, 256>>>(ckv, kvnw, ckvn, KVCC, 384, KVCC, EPS_RMS);
    // 4. kvup = ckvn @ kv_up^T [1536, 2048] fp16
    hgemm<true><<<grid_g(S_LEN, 2048, 1), 256, SMEM_H>>>(ckvn, kvuw_h, nullptr, kvup,
        S_LEN, 2048, KVCC, 0, 0, 0, 1.f);
    // 5. cq = xin @ q_down^T [1536, 384] fp32
    hgemm<false><<<grid_g(S_LEN, QCC, 1), 256, SMEM_H>>>(xin, qdw_h, nullptr, cq,
        S_LEN, QCC, DM, 0, 0, 0, 1.f);
    // 6. cqn = rmsnorm(cq) -> fp16
    rmsnorm_h<<<S_LEN, 256>>>(cq, qnw, cqn, QCC, QCC, QCC, EPS_RMS);
    // 7. qf = cqn @ q_up^T [1536, 1536] fp16
    hgemm<true><<<grid_g(S_LEN, 1536, 1), 256, SMEM_H>>>(cqn, quw_h, nullptr, qf,
        S_LEN, 1536, QCC, 0, 0, 0, 1.f);
    // 8. build Q/K/V (fp16, Q/K padded to 64)
    build_qkv_k<<<S_LEN, 128>>>(qf, kvup, ckv, fc, fs, Q, K, V);
    // 9. logits: Ph[h] = SCALING * Q[h] @ K[h]^T -> fp16 (in-place softmax next)
    hgemm<true><<<grid_g(S_LEN, S_LEN, H2), 256, SMEM_H>>>(Q, K, nullptr, Ph,
        S_LEN, S_LEN, DQKP,
        (long long)S_LEN * DQKP, (long long)S_LEN * DQKP, (long long)S_LEN * S_LEN,
        SCALING);
    // 10. lambda
    lambda_k_<<<1, 32>>>(lq1, lk1, lq2, lk2, lam);
    // 11. softmax in place on fp16
    softmax3_k<<<H2 * S_LEN, 192>>>(Ph);
    // 12. column means (fp16 in)
    colmean_k<<<dim3((S_LEN + 255) / 256, NH), 256>>>(Ph, gg);
    // 13+14. fused combine + AV (fp16 mma)
    av_k<<<dim3(S_LEN / AVM, NH), 256>>>(Ph, V, gg, lam, ao);
    // 15. attn rmsnorm -> fp16 (keeps [h][i][d] scrambled-reshape layout)
    attn_norm_k<<<dim3(S_LEN, NH), 64>>>(ao, anw, af);
    // 16. x2 = x + af @ o_w^T fp32
    hgemm<false><<<grid_g(S_LEN, DM, 1), 256, SMEM_H>>>(af, ow_h, x, x2,
        S_LEN, DM, DM, 0, 0, 0, 1.f);
    // 17. hb = rmsnorm(x2) -> fp16
    rmsnorm_h<<<S_LEN, 256>>>(x2, n2w, hb, DM, DM, DM, EPS_RMS);
    // 18. uv = hb @ ff_in^T [1536, 8192] fp16
    hgemm<true><<<grid_g(S_LEN, 2 * DFF, 1), 256, SMEM_H>>>(hb, fiw_h, nullptr, uv,
        S_LEN, 2 * DFF, DM, 0, 0, 0, 1.f);
    // 19. act = u * silu(vg) fp16
    {
        long long tot = (long long)S_LEN * DFF;
        swiglu_k<<<(unsigned)((tot + 255) / 256), 256>>>(uv, act);
    }
    // 20. out = x2 + act @ ff_out^T fp32
    hgemm<false><<<grid_g(S_LEN, DM, 1), 256, SMEM_H>>>(act, fow_h, x2, outp,
        S_LEN, DM, DFF, 0, 0, 0, 1.f);
}

// round 10
// speedup vs baseline: 6.5208x; 1.0049x over previous
#include <cuda_runtime.h>
#include <cuda_fp16.h>
#include <math.h>
#include <stdint.h>

#define S_LEN 1536
#define DM    1024
#define NH    16
#define HD    64
#define H2    32
#define DQK   48
#define DQKP  64
#define KVCC  256
#define ROPE_ 32
#define QCC   384
#define DFF   4096
#define SPP   384
#define EPS_RMS 1.1920929e-07f
#define ATTN_EPS 1e-5f
#define SCALING 0.14433756729740643f
#define LAMBDA_INIT 0.2f

// ------------------------- device scratch -------------------------
__device__ __half g_xin [S_LEN * DM];
__device__ float  g_ckv [S_LEN * 384];
__device__ __half g_ckvn[S_LEN * KVCC];
__device__ __half g_kvup[S_LEN * 2048];
__device__ float  g_cq  [S_LEN * QCC];
__device__ __half g_cqn [S_LEN * QCC];
__device__ __half g_qf  [S_LEN * 1536];
__device__ __half g_Q   [(size_t)H2 * S_LEN * DQKP];
__device__ __half g_K   [(size_t)H2 * S_LEN * DQKP];
__device__ __half g_V   [(size_t)NH * S_LEN * HD];
__device__ __half g_Ph  [(size_t)H2 * S_LEN * S_LEN];   // UNNORMALIZED exp, fp16
__device__ float  g_inv [H2 * S_LEN];                    // per-row 1/sum
__device__ float  g_g   [NH * S_LEN];
__device__ float  g_ao  [(size_t)NH * S_LEN * HD];
__device__ __half g_af  [S_LEN * DM];
__device__ float  g_x2  [S_LEN * DM];
__device__ __half g_hb  [S_LEN * DM];
__device__ __half g_uv  [(size_t)S_LEN * 2 * DFF];
__device__ __half g_act [(size_t)S_LEN * DFF];
__device__ float  g_lambda;
// fp16 weight copies
__device__ __half g_kvdw_h[384 * DM];
__device__ __half g_qdw_h [QCC * DM];
__device__ __half g_kvuw_h[2048 * KVCC];
__device__ __half g_quw_h [1536 * QCC];
__device__ __half g_ow_h  [(size_t)DM * DM];
__device__ __half g_fiw_h [(size_t)2 * DFF * DM];
__device__ __half g_fow_h [(size_t)DM * DFF];

// ------------------------- helpers -------------------------
__device__ __forceinline__ void cpa16(void* smem_dst, const void* gsrc) {
    unsigned a = (unsigned)__cvta_generic_to_shared(smem_dst);
    asm volatile("cp.async.ca.shared.global [%0], [%1], 16;\n" :: "r"(a), "l"(gsrc));
}
__device__ __forceinline__ void cpa_commit() { asm volatile("cp.async.commit_group;\n"); }
template <int NG>
__device__ __forceinline__ void cpa_wait() { asm volatile("cp.async.wait_group %0;\n" :: "n"(NG)); }

#define LDM_X4(a0,a1,a2,a3,p) \
    asm volatile("ldmatrix.sync.aligned.m8n8.x4.shared.b16 {%0,%1,%2,%3}, [%4];" \
        : "=r"(a0), "=r"(a1), "=r"(a2), "=r"(a3) \
        : "r"((unsigned)__cvta_generic_to_shared(p)))
#define LDM_X2(b0,b1,p) \
    asm volatile("ldmatrix.sync.aligned.m8n8.x2.shared.b16 {%0,%1}, [%2];" \
        : "=r"(b0), "=r"(b1) \
        : "r"((unsigned)__cvta_generic_to_shared(p)))
#define LDM_X2T(b0,b1,p) \
    asm volatile("ldmatrix.sync.aligned.m8n8.x2.trans.shared.b16 {%0,%1}, [%2];" \
        : "=r"(b0), "=r"(b1) \
        : "r"((unsigned)__cvta_generic_to_shared(p)))
#define MMA_F16(d, a, b) \
    asm volatile( \
        "mma.sync.aligned.m16n8k16.row.col.f32.f16.f16.f32 " \
        "{%0,%1,%2,%3}, {%4,%5,%6,%7}, {%8,%9}, {%0,%1,%2,%3};" \
        : "+f"(d[0]), "+f"(d[1]), "+f"(d[2]), "+f"(d[3]) \
        : "r"(a[0]), "r"(a[1]), "r"(a[2]), "r"(a[3]), "r"(b[0]), "r"(b[1]))

#define HSTR 40
#define GBK  32

// ------------------------- FP16 GEMM: 128x128 tiles, 3-stage pipeline ----------
#define SMEM_H (3 * 2 * 128 * HSTR * 2)

template <bool HALF_OUT>
__global__ __launch_bounds__(256, 2)
void hgemm(const __half* __restrict__ A, const __half* __restrict__ B,
           const float* __restrict__ Res, void* __restrict__ Cv,
           int M, int N, int K, long long sA, long long sB, long long sC,
           float scale)
{
    extern __shared__ __half hsm[];
    __half* AsB = hsm;                   // [3][128*HSTR]
    __half* BsB = hsm + 3 * 128 * HSTR;  // [3][128*HSTR]

    A += (long long)blockIdx.z * sA;
    B += (long long)blockIdx.z * sB;
    float*  Cf = (float*)Cv  + (long long)blockIdx.z * sC;
    __half* Ch = (__half*)Cv + (long long)blockIdx.z * sC;

    const int tid  = threadIdx.x;
    const int lane = tid & 31;
    const int warp = tid >> 5;
    const int wm   = warp >> 2;
    const int wn   = warp & 3;
    const int row0 = blockIdx.y * 128;
    const int col0 = blockIdx.x * 128;
    const int grp  = lane >> 2;
    const int tig  = lane & 3;

    const int nk = K / GBK;

    auto load_tiles = [&](int ki, int buf) {
        const __half* Ag = A + (long long)row0 * K + ki * GBK;
        __half* Ad = AsB + buf * 128 * HSTR;
#pragma unroll
        for (int it = 0; it < 2; it++) {
            int f = tid + it * 256;
            int r = f >> 2, c8 = (f & 3) * 8;
            cpa16(Ad + r * HSTR + c8, Ag + (long long)r * K + c8);
        }
        const __half* Bg = B + (long long)col0 * K + ki * GBK;
        __half* Bd = BsB + buf * 128 * HSTR;
#pragma unroll
        for (int it = 0; it < 2; it++) {
            int f = tid + it * 256;
            int r = f >> 2, c8 = (f & 3) * 8;
            cpa16(Bd + r * HSTR + c8, Bg + (long long)r * K + c8);
        }
    };

    float acc[4][4][4];
#pragma unroll
    for (int i = 0; i < 4; i++)
#pragma unroll
        for (int j = 0; j < 4; j++)
#pragma unroll
            for (int l = 0; l < 4; l++) acc[i][j][l] = 0.f;

    load_tiles(0, 0); cpa_commit();
    load_tiles(1, 1); cpa_commit();

    const int arow = (lane & 15);
    const int asel = (lane >> 4) * 8;
    const int brow = (lane & 7);
    const int bsel = ((lane >> 3) & 1) * 8;

    int cur = 0;
    for (int i = 0; i < nk; i++) {
        if (i + 2 < nk) { load_tiles(i + 2, (i + 2) % 3); cpa_commit(); cpa_wait<2>(); }
        else if (i + 1 < nk) { cpa_wait<1>(); }
        else { cpa_wait<0>(); }
        __syncthreads();

        const __half* Ab = AsB + cur * 128 * HSTR;
        const __half* Bb = BsB + cur * 128 * HSTR;
#pragma unroll
        for (int kc = 0; kc < 2; kc++) {
            unsigned a[4][4], b[4][2];
            int acol = kc * 16 + asel;
            int bcol = kc * 16 + bsel;
#pragma unroll
            for (int mi = 0; mi < 4; mi++) {
                const __half* p = Ab + (wm * 64 + mi * 16 + arow) * HSTR + acol;
                LDM_X4(a[mi][0], a[mi][1], a[mi][2], a[mi][3], p);
            }
#pragma unroll
            for (int ni = 0; ni < 4; ni++) {
                const __half* p = Bb + (wn * 32 + ni * 8 + brow) * HSTR + bcol;
                LDM_X2(b[ni][0], b[ni][1], p);
            }
#pragma unroll
            for (int mi = 0; mi < 4; mi++)
#pragma unroll
                for (int ni = 0; ni < 4; ni++)
                    MMA_F16(acc[mi][ni], a[mi], b[ni]);
        }
        __syncthreads();
        cur = (cur + 1 == 3) ? 0 : cur + 1;
    }

#pragma unroll
    for (int mi = 0; mi < 4; mi++)
#pragma unroll
        for (int ni = 0; ni < 4; ni++)
#pragma unroll
            for (int h = 0; h < 2; h++) {
                int r = row0 + wm * 64 + mi * 16 + grp + h * 8;
                int cc = col0 + wn * 32 + ni * 8 + tig * 2;
                long long o = (long long)r * N + cc;
                float v0 = acc[mi][ni][h * 2 + 0] * scale;
                float v1 = acc[mi][ni][h * 2 + 1] * scale;
                if (HALF_OUT) {
                    *(__half2*)(Ch + o) = __floats2half2_rn(v0, v1);
                } else {
                    if (Res) { v0 += Res[o]; v1 += Res[o + 1]; }
                    Cf[o] = v0; Cf[o + 1] = v1;
                }
            }
}

// --------- fused QK^T + masked unnormalized softmax (writes e, 1/rowsum) -------
// grid (S_LEN/128, H2), 256 threads. K dim = 64.
#define QKS 72   /* smem stride (halves) for 64-wide tiles */
#define QK_SMEM (128*QKS*2 + 2*64*QKS*2 + 128*QKS*2)

__global__ __launch_bounds__(256)
void qk_softmax_k(const __half* __restrict__ Q, const __half* __restrict__ Kg,
                  __half* __restrict__ Ph, float* __restrict__ invp)
{
    extern __shared__ char qsm[];
    __half* Qs = (__half*)qsm;            // 128 x QKS
    __half* Ks = Qs + 128 * QKS;          // [2][64 x QKS]
    __half* Os = Ks + 2 * 64 * QKS;       // 128 x QKS staging

    const int h2   = blockIdx.y;
    const int row0 = blockIdx.x * 128;
    const int tid  = threadIdx.x;
    const int lane = tid & 31;
    const int warp = tid >> 5;
    const int grp  = lane >> 2;
    const int tig  = lane & 3;

    const __half* Qh = Q + (long long)h2 * S_LEN * DQKP;
    const __half* Kh = Kg + (long long)h2 * S_LEN * DQKP;
    __half* Pout = Ph + (long long)h2 * S_LEN * S_LEN;

    // load Q tile (group 1)
#pragma unroll
    for (int it = 0; it < 4; it++) {
        int f = tid + it * 256, r = f >> 3, c8 = (f & 7) * 8;
        cpa16(Qs + r * QKS + c8, Qh + (long long)(row0 + r) * DQKP + c8);
    }
    cpa_commit();

    auto loadK = [&](int jt, int buf) {
#pragma unroll
        for (int it = 0; it < 2; it++) {
            int f = tid + it * 256, r = f >> 3, c8 = (f & 7) * 8;
            cpa16(Ks + buf * 64 * QKS + r * QKS + c8,
                  Kh + (long long)(jt * 64 + r) * DQKP + c8);
        }
        cpa_commit();
    };

    const int r0  = warp * 16 + grp;
    const int ip0 = (row0 + r0) % SPP;
    const int ip1 = (row0 + r0 + 8) % SPP;

    float s0 = 0.f, s1 = 0.f;

    loadK(0, 0);

    const int NJT = S_LEN / 64;   // 24
    for (int jt = 0; jt < NJT; jt++) {
        int buf = jt & 1;
        if (jt + 1 < NJT) { loadK(jt + 1, buf ^ 1); cpa_wait<1>(); }
        else              { cpa_wait<0>(); }
        __syncthreads();

        float acc[8][4];
#pragma unroll
        for (int ni = 0; ni < 8; ni++)
#pragma unroll
            for (int l = 0; l < 4; l++) acc[ni][l] = 0.f;

        const __half* Kb = Ks + buf * 64 * QKS;
#pragma unroll
        for (int kc = 0; kc < 4; kc++) {
            unsigned a[4];
            const __half* pa = Qs + (warp * 16 + (lane & 15)) * QKS
                                  + kc * 16 + (lane >> 4) * 8;
            LDM_X4(a[0], a[1], a[2], a[3], pa);
#pragma unroll
            for (int ni = 0; ni < 8; ni++) {
                unsigned bb[2];
                const __half* pb = Kb + (ni * 8 + (lane & 7)) * QKS
                                      + kc * 16 + ((lane >> 3) & 1) * 8;
                LDM_X2(bb[0], bb[1], pb);
                MMA_F16(acc[ni], a, bb);
            }
        }

        // epilogue: masked unnormalized exp -> Os, accumulate row sums
#pragma unroll
        for (int ni = 0; ni < 8; ni++) {
            int c0  = jt * 64 + ni * 8 + tig * 2;
            int jm0 = c0 % SPP;           // c0 even -> jm0+1 valid for c0+1
            float e00 = (jm0     <= ip0) ? __expf(fminf(acc[ni][0] * SCALING, 10.f)) : 0.f;
            float e01 = (jm0 + 1 <= ip0) ? __expf(fminf(acc[ni][1] * SCALING, 10.f)) : 0.f;
            float e10 = (jm0     <= ip1) ? __expf(fminf(acc[ni][2] * SCALING, 10.f)) : 0.f;
            float e11 = (jm0 + 1 <= ip1) ? __expf(fminf(acc[ni][3] * SCALING, 10.f)) : 0.f;
            s0 += e00 + e01;
            s1 += e10 + e11;
            *(__half2*)(Os + r0 * QKS + ni * 8 + tig * 2)       = __floats2half2_rn(e00, e01);
            *(__half2*)(Os + (r0 + 8) * QKS + ni * 8 + tig * 2) = __floats2half2_rn(e10, e11);
        }
        __syncthreads();

        // coalesced copy Os -> global
#pragma unroll
        for (int it = 0; it < 4; it++) {
            int f = tid + it * 256, r = f >> 3, c8 = (f & 7) * 8;
            uint4 u = *(uint4*)(Os + r * QKS + c8);
            *(uint4*)(Pout + (long long)(row0 + r) * S_LEN + jt * 64 + c8) = u;
        }
        __syncthreads();
    }

    // quad-reduce row sums, write inverse
#pragma unroll
    for (int x = 1; x <= 2; x <<= 1) {
        s0 += __shfl_xor_sync(0xffffffffu, s0, x);
        s1 += __shfl_xor_sync(0xffffffffu, s1, x);
    }
    if (tig == 0) {
        invp[h2 * S_LEN + row0 + r0]     = 1.f / s0;
        invp[h2 * S_LEN + row0 + r0 + 8] = 1.f / s1;
    }
}

// ------------------------- fused differential-combine + AV GEMM ----------------
#define AVM 64
#define VSTR 72

__global__ __launch_bounds__(256)
void av_k(const __half* __restrict__ Ph, const float* __restrict__ invp,
          const __half* __restrict__ V,
          const float* __restrict__ g, const float* __restrict__ lamp,
          float* __restrict__ O)
{
    __shared__ __half As[AVM * HSTR];
    __shared__ __half Bs[GBK * VSTR];

    const int h    = blockIdx.y;
    const int row0 = blockIdx.x * AVM;
    const int tid  = threadIdx.x;
    const int lane = tid & 31;
    const int warp = tid >> 5;
    const int wm   = warp >> 1;
    const int wn   = warp & 1;
    const int grp  = lane >> 2;
    const int tig  = lane & 3;

    const float lam = *lamp;
    const float gl  = lam * (1.f / (float)S_LEN);
    const __half* p1 = Ph + (long long)(2 * h) * S_LEN * S_LEN;
    const __half* p2 = Ph + (long long)(2 * h + 1) * S_LEN * S_LEN;
    const __half* Vh = V + (long long)h * S_LEN * HD;
    const float*  gh = g + h * S_LEN;

    float acc[4][4];
#pragma unroll
    for (int j = 0; j < 4; j++)
#pragma unroll
        for (int l = 0; l < 4; l++) acc[j][l] = 0.f;

    const int dr  = tid >> 2;
    const int dc8 = (tid & 3) * 8;
    const int ip  = (row0 + dr) % SPP;
    const float i1 = invp[(2 * h) * S_LEN + row0 + dr];
    const float i2 = invp[(2 * h + 1) * S_LEN + row0 + dr];

    for (int j0 = 0; j0 < S_LEN; j0 += GBK) {
        {
            int kk = tid >> 3, c8 = (tid & 7) * 8;
            cpa16(Bs + kk * VSTR + c8, Vh + (long long)(j0 + kk) * HD + c8);
        }
        cpa_commit();

        {
            long long off = (long long)(row0 + dr) * S_LEN + j0 + dc8;
            uint4 u1 = *(const uint4*)(p1 + off);
            uint4 u2 = *(const uint4*)(p2 + off);
            const __half2* h1 = (const __half2*)&u1;
            const __half2* h2 = (const __half2*)&u2;
            __half outh[8];
            int jb = j0 + dc8;
#pragma unroll
            for (int e = 0; e < 4; e++) {
                float2 f1 = __half22float2(h1[e]);
                float2 f2 = __half22float2(h2[e]);
                int ja = jb + 2 * e, jbb = ja + 1;
                float o0 = ((ja  % SPP) > ip) ? 0.f
                           : (f1.x * i1 - lam * (f2.x * i2) + gl * gh[ja]);
                float o1 = ((jbb % SPP) > ip) ? 0.f
                           : (f1.y * i1 - lam * (f2.y * i2) + gl * gh[jbb]);
                outh[2 * e]     = __float2half_rn(o0);
                outh[2 * e + 1] = __float2half_rn(o1);
            }
            *(uint4*)(As + dr * HSTR + dc8) = *(uint4*)outh;
        }
        cpa_wait<0>();
        __syncthreads();

#pragma unroll
        for (int kc = 0; kc < 2; kc++) {
            unsigned a[4], b[4][2];
            {
                const __half* p = As + (wm * 16 + (lane & 15)) * HSTR
                                     + kc * 16 + (lane >> 4) * 8;
                LDM_X4(a[0], a[1], a[2], a[3], p);
            }
#pragma unroll
            for (int ni = 0; ni < 4; ni++) {
                int krow = kc * 16 + ((lane >> 3) & 1) * 8 + (lane & 7);
                int ncol = wn * 32 + ni * 8;
                const __half* p = Bs + krow * VSTR + ncol;
                LDM_X2T(b[ni][0], b[ni][1], p);
            }
#pragma unroll
            for (int ni = 0; ni < 4; ni++)
                MMA_F16(acc[ni], a, b[ni]);
        }
        __syncthreads();
    }

#pragma unroll
    for (int ni = 0; ni < 4; ni++)
#pragma unroll
        for (int hh = 0; hh < 2; hh++) {
            int r = row0 + wm * 16 + grp + hh * 8;
            int cc = wn * 32 + ni * 8 + tig * 2;
            long long o = ((long long)h * S_LEN + r) * HD + cc;
            O[o]     = acc[ni][hh * 2 + 0];
            O[o + 1] = acc[ni][hh * 2 + 1];
        }
}

// ------------------------- rmsnorm: fp32 in -> fp16 out -------------------------
__global__ void rmsnorm_h(const float* __restrict__ in, const float* __restrict__ w,
                          __half* __restrict__ out, int cols, int in_ld, int out_ld,
                          float eps)
{
    const long long row = blockIdx.x;
    const float* ip = in + row * in_ld;
    __half* op = out + row * out_ld;

    float ss = 0.f;
    for (int j = threadIdx.x; j < cols; j += blockDim.x) {
        float v = ip[j];
        ss += v * v;
    }
    __shared__ float sh[32];
    int lane = threadIdx.x & 31, wid = threadIdx.x >> 5;
#pragma unroll
    for (int o = 16; o; o >>= 1) ss += __shfl_xor_sync(0xffffffffu, ss, o);
    if (lane == 0) sh[wid] = ss;
    __syncthreads();
    int nw = (blockDim.x + 31) >> 5;
    float tot = 0.f;
    if (threadIdx.x < nw) tot = sh[threadIdx.x];
    if (wid == 0) {
#pragma unroll
        for (int o = 16; o; o >>= 1) tot += __shfl_xor_sync(0xffffffffu, tot, o);
        if (lane == 0) sh[0] = tot;
    }
    __syncthreads();
    float inv = rsqrtf(sh[0] / (float)cols + eps);
    for (int j = threadIdx.x; j < cols; j += blockDim.x)
        op[j] = __float2half_rn(ip[j] * inv * w[j]);
}

// ------------------------- build Q/K/V with RoPE (fp16 out) --------------------
__global__ void build_qkv_k(const __half* __restrict__ qf, const __half* __restrict__ kvup,
                            const float* __restrict__ ckv,
                            const float* __restrict__ fcos, const float* __restrict__ fsin,
                            __half* __restrict__ Q, __half* __restrict__ K,
                            __half* __restrict__ V)
{
    const int i = blockIdx.x;
    const int tid = threadIdx.x;              // 128
    __shared__ float cs[8], sn[8];
    int p = i >> 2;
    if (tid < 8) {
        if (p == 0) { cs[tid] = 1.f; sn[tid] = 0.f; }
        else { cs[tid] = fcos[(p - 1) * 8 + tid]; sn[tid] = fsin[(p - 1) * 8 + tid]; }
    }
    __syncthreads();

    const __half* qrow = qf + (long long)i * 1536;
    const __half* krow = kvup + (long long)i * 2048;
    const float*  crow = ckv + (long long)i * 384;

    for (int e = tid; e < H2 * DQKP; e += 128) {
        int h2 = e / DQKP, d = e % DQKP;
        int h = h2 >> 1, c = h2 & 1;
        float qv = 0.f, kv = 0.f;
        if (d < 32) {
            qv = __half2float(qrow[h * 96 + c * 32 + d]);
            kv = __half2float(krow[h * 128 + c * 32 + d]);
        } else if (d < DQK) {
            int ee = d - 32;
            int f = ee >> 1;
            float q0 = __half2float(qrow[h * 96 + 64 + c * 16 + 2 * f]);
            float q1 = __half2float(qrow[h * 96 + 64 + c * 16 + 2 * f + 1]);
            float k0 = crow[KVCC + c * 16 + 2 * f];
            float k1 = crow[KVCC + c * 16 + 2 * f + 1];
            float C = cs[f], Sv = sn[f];
            if ((ee & 1) == 0) { qv = q0 * C - q1 * Sv; kv = k0 * C - k1 * Sv; }
            else               { qv = q0 * Sv + q1 * C; kv = k0 * Sv + k1 * C; }
        }
        Q[(long long)h2 * S_LEN * DQKP + (long long)i * DQKP + d] = __float2half_rn(qv);
        K[(long long)h2 * S_LEN * DQKP + (long long)i * DQKP + d] = __float2half_rn(kv);
    }
    for (int e = tid; e < NH * HD; e += 128) {
        int h = e >> 6, d = e & 63;
        V[(long long)h * S_LEN * HD + (long long)i * HD + d] = krow[h * 128 + 64 + d];
    }
}

// ---------- column sums of normalized even-head probs: g[h][j]=sum_i e*inv -----
__global__ void colmean_k(const __half* __restrict__ Ph, const float* __restrict__ invp,
                          float* __restrict__ g)
{
    int j = blockIdx.x * blockDim.x + threadIdx.x;
    int h = blockIdx.y;
    if (j >= S_LEN) return;
    const __half* base = Ph + (long long)(2 * h) * S_LEN * S_LEN + j;
    const float*  iv   = invp + (2 * h) * S_LEN;
    float s = 0.f;
    for (int i = 0; i < S_LEN; i++)
        s += __half2float(base[(long long)i * S_LEN]) * iv[i];
    g[h * S_LEN + j] = s;   // raw sum; av multiplies by lam/S_LEN
}

// ------------------------- lambda scalar -------------------------
__global__ void lambda_k_(const float* __restrict__ q1, const float* __restrict__ k1,
                          const float* __restrict__ q2, const float* __restrict__ k2,
                          float* __restrict__ out)
{
    int t = threadIdx.x;
    float a = q1[t] * k1[t];
    float b = q2[t] * k2[t];
#pragma unroll
    for (int o = 16; o; o >>= 1) {
        a += __shfl_xor_sync(0xffffffffu, a, o);
        b += __shfl_xor_sync(0xffffffffu, b, o);
    }
    if (t == 0) *out = expf(a) - expf(b) + LAMBDA_INIT;
}

// ------------------------- per (token, head) rmsnorm: fp32 -> fp16 -------------
__global__ void attn_norm_k(const float* __restrict__ ao, const float* __restrict__ w,
                            __half* __restrict__ outf)
{
    int i = blockIdx.x, h = blockIdx.y, d = threadIdx.x;
    long long idx = ((long long)h * S_LEN + i) * HD + d;
    float v = ao[idx];
    float sq = v * v;
    __shared__ float sh[2];
#pragma unroll
    for (int o = 16; o; o >>= 1) sq += __shfl_xor_sync(0xffffffffu, sq, o);
    if ((d & 31) == 0) sh[d >> 5] = sq;
    __syncthreads();
    float tot = sh[0] + sh[1];
    outf[idx] = __float2half_rn(v * rsqrtf(tot / (float)HD + ATTN_EPS) * w[d]);
}

// ------------------------- SwiGLU: fp16 in -> fp16 out -------------------------
__global__ void swiglu_k(const __half* __restrict__ uv, __half* __restrict__ act)
{
    long long idx = (long long)blockIdx.x * blockDim.x + threadIdx.x;
    if (idx >= (long long)S_LEN * DFF) return;
    long long i = idx / DFF, j = idx % DFF;
    float u  = __half2float(uv[i * (2 * DFF) + j]);
    float vg = __half2float(uv[i * (2 * DFF) + DFF + j]);
    act[idx] = __float2half_rn(u * (vg / (1.f + __expf(-vg))));
}

// ------------------------- fp32 -> fp16 weight convert (vectorized) ------------
__global__ void cvt_h_k(const float* __restrict__ in, __half* __restrict__ out, int n)
{
    int i = (blockIdx.x * blockDim.x + threadIdx.x) * 4;
    int stride = gridDim.x * blockDim.x * 4;
    for (; i < n; i += stride) {
        float4 v = *(const float4*)(in + i);
        *(__half2*)(out + i)     = __floats2half2_rn(v.x, v.y);
        *(__half2*)(out + i + 2) = __floats2half2_rn(v.z, v.w);
    }
}
__global__ void zero_h_k(__half* __restrict__ p, int n)
{
    int i = blockIdx.x * blockDim.x + threadIdx.x;
    if (i < n) p[i] = __float2half(0.f);
}

// ------------------------- host -------------------------
extern "C" void kernel_launch(void* const* d_in, const int* in_sizes, int n_in,
                              void* d_out, int out_size)
{
    const float* x    = (const float*)d_in[0];
    const float* fc   = (const float*)d_in[1];
    const float* fs   = (const float*)d_in[2];
    const float* n1w  = (const float*)d_in[3];
    const float* n2w  = (const float*)d_in[4];
    const float* kvdw = (const float*)d_in[5];
    const float* qdw  = (const float*)d_in[6];
    const float* kvnw = (const float*)d_in[7];
    const float* qnw  = (const float*)d_in[8];
    const float* kvuw = (const float*)d_in[9];
    const float* quw  = (const float*)d_in[10];
    const float* lq1  = (const float*)d_in[11];
    const float* lk1  = (const float*)d_in[12];
    const float* lq2  = (const float*)d_in[13];
    const float* lk2  = (const float*)d_in[14];
    const float* anw  = (const float*)d_in[15];
    const float* ow   = (const float*)d_in[16];
    const float* fiw  = (const float*)d_in[17];
    const float* fow  = (const float*)d_in[18];
    float* outp = (float*)d_out;

    __half *xin, *ckvn, *kvup, *cqn, *qf, *Q, *K, *V, *Ph, *af, *hb, *uv, *act;
    __half *kvdw_h, *qdw_h, *kvuw_h, *quw_h, *ow_h, *fiw_h, *fow_h;
    float *ckv, *cq, *gg, *ao, *x2, *lam, *invp;
    cudaGetSymbolAddress((void**)&xin,  g_xin);
    cudaGetSymbolAddress((void**)&ckv,  g_ckv);
    cudaGetSymbolAddress((void**)&ckvn, g_ckvn);
    cudaGetSymbolAddress((void**)&kvup, g_kvup);
    cudaGetSymbolAddress((void**)&cq,   g_cq);
    cudaGetSymbolAddress((void**)&cqn,  g_cqn);
    cudaGetSymbolAddress((void**)&qf,   g_qf);
    cudaGetSymbolAddress((void**)&Q,    g_Q);
    cudaGetSymbolAddress((void**)&K,    g_K);
    cudaGetSymbolAddress((void**)&V,    g_V);
    cudaGetSymbolAddress((void**)&Ph,   g_Ph);
    cudaGetSymbolAddress((void**)&invp, g_inv);
    cudaGetSymbolAddress((void**)&gg,   g_g);
    cudaGetSymbolAddress((void**)&ao,   g_ao);
    cudaGetSymbolAddress((void**)&af,   g_af);
    cudaGetSymbolAddress((void**)&x2,   g_x2);
    cudaGetSymbolAddress((void**)&hb,   g_hb);
    cudaGetSymbolAddress((void**)&uv,   g_uv);
    cudaGetSymbolAddress((void**)&act,  g_act);
    cudaGetSymbolAddress((void**)&lam,  g_lambda);
    cudaGetSymbolAddress((void**)&kvdw_h, g_kvdw_h);
    cudaGetSymbolAddress((void**)&qdw_h,  g_qdw_h);
    cudaGetSymbolAddress((void**)&kvuw_h, g_kvuw_h);
    cudaGetSymbolAddress((void**)&quw_h,  g_quw_h);
    cudaGetSymbolAddress((void**)&ow_h,   g_ow_h);
    cudaGetSymbolAddress((void**)&fiw_h,  g_fiw_h);
    cudaGetSymbolAddress((void**)&fow_h,  g_fow_h);

    static bool attr_set = false;
    if (!attr_set) {
        cudaFuncSetAttribute(hgemm<false>, cudaFuncAttributeMaxDynamicSharedMemorySize, SMEM_H);
        cudaFuncSetAttribute(hgemm<true>,  cudaFuncAttributeMaxDynamicSharedMemorySize, SMEM_H);
        cudaFuncSetAttribute(qk_softmax_k, cudaFuncAttributeMaxDynamicSharedMemorySize, QK_SMEM);
        attr_set = true;
    }

    auto grid_g = [](int M, int N, int batch) {
        return dim3((unsigned)(N / 128), (unsigned)(M / 128), (unsigned)batch);
    };

    // 0. weights -> fp16 (+ zero-pad kv_down rows 288..383)
    cvt_h_k<<<288,  256>>>(kvdw, kvdw_h, 288 * DM);
    zero_h_k<<<(96 * DM + 255) / 256, 256>>>(kvdw_h + 288 * DM, 96 * DM);
    cvt_h_k<<<384,  256>>>(qdw,  qdw_h,  QCC * DM);
    cvt_h_k<<<512,  256>>>(kvuw, kvuw_h, 2048 * KVCC);
    cvt_h_k<<<576,  256>>>(quw,  quw_h,  1536 * QCC);
    cvt_h_k<<<1024, 256>>>(ow,   ow_h,   DM * DM);
    cvt_h_k<<<4096, 256>>>(fiw,  fiw_h,  2 * DFF * DM);
    cvt_h_k<<<4096, 256>>>(fow,  fow_h,  DM * DFF);

    // 1. xin = rmsnorm(x) -> fp16
    rmsnorm_h<<<S_LEN, 256>>>(x, n1w, xin, DM, DM, DM, EPS_RMS);
    // 2. ckv = xin @ kv_down^T  [1536, 384(pad)] fp32
    hgemm<false><<<grid_g(S_LEN, 384, 1), 256, SMEM_H>>>(xin, kvdw_h, nullptr, ckv,
        S_LEN, 384, DM, 0, 0, 0, 1.f);
    // 3. ckvn = rmsnorm(ckv[:, :256]) -> fp16
    rmsnorm_h<<<S_LEN, 256>>>(ckv, kvnw, ckvn, KVCC, 384, KVCC, EPS_RMS);
    // 4. kvup = ckvn @ kv_up^T [1536, 2048] fp16
    hgemm<true><<<grid_g(S_LEN, 2048, 1), 256, SMEM_H>>>(ckvn, kvuw_h, nullptr, kvup,
        S_LEN, 2048, KVCC, 0, 0, 0, 1.f);
    // 5. cq = xin @ q_down^T [1536, 384] fp32
    hgemm<false><<<grid_g(S_LEN, QCC, 1), 256, SMEM_H>>>(xin, qdw_h, nullptr, cq,
        S_LEN, QCC, DM, 0, 0, 0, 1.f);
    // 6. cqn = rmsnorm(cq) -> fp16
    rmsnorm_h<<<S_LEN, 256>>>(cq, qnw, cqn, QCC, QCC, QCC, EPS_RMS);
    // 7. qf = cqn @ q_up^T [1536, 1536] fp16
    hgemm<true><<<grid_g(S_LEN, 1536, 1), 256, SMEM_H>>>(cqn, quw_h, nullptr, qf,
        S_LEN, 1536, QCC, 0, 0, 0, 1.f);
    // 8. build Q/K/V (fp16, Q/K padded to 64)
    build_qkv_k<<<S_LEN, 128>>>(qf, kvup, ckv, fc, fs, Q, K, V);
    // 9. fused QK^T + masked unnormalized softmax (writes e fp16 + 1/rowsum)
    qk_softmax_k<<<dim3(S_LEN / 128, H2), 256, QK_SMEM>>>(Q, K, Ph, invp);
    // 10. lambda
    lambda_k_<<<1, 32>>>(lq1, lk1, lq2, lk2, lam);
    // 11. column sums of normalized even-head probs
    colmean_k<<<dim3((S_LEN + 255) / 256, NH), 256>>>(Ph, invp, gg);
    // 12+13. fused combine (normalize on the fly) + AV
    av_k<<<dim3(S_LEN / AVM, NH), 256>>>(Ph, invp, V, gg, lam, ao);
    // 14. attn rmsnorm -> fp16 (keeps [h][i][d] scrambled-reshape layout)
    attn_norm_k<<<dim3(S_LEN, NH), 64>>>(ao, anw, af);
    // 15. x2 = x + af @ o_w^T fp32
    hgemm<false><<<grid_g(S_LEN, DM, 1), 256, SMEM_H>>>(af, ow_h, x, x2,
        S_LEN, DM, DM, 0, 0, 0, 1.f);
    // 16. hb = rmsnorm(x2) -> fp16
    rmsnorm_h<<<S_LEN, 256>>>(x2, n2w, hb, DM, DM, DM, EPS_RMS);
    // 17. uv = hb @ ff_in^T [1536, 8192] fp16
    hgemm<true><<<grid_g(S_LEN, 2 * DFF, 1), 256, SMEM_H>>>(hb, fiw_h, nullptr, uv,
        S_LEN, 2 * DFF, DM, 0, 0, 0, 1.f);
    // 18. act = u * silu(vg) fp16
    {
        long long tot = (long long)S_LEN * DFF;
        swiglu_k<<<(unsigned)((tot + 255) / 256), 256>>>(uv, act);
    }
    // 19. out = x2 + act @ ff_out^T fp32
    hgemm<false><<<grid_g(S_LEN, DM, 1), 256, SMEM_H>>>(act, fow_h, x2, outp,
        S_LEN, DM, DFF, 0, 0, 0, 1.f);
}

// round 11
// speedup vs baseline: 8.5914x; 1.3175x over previous
#include <cuda_runtime.h>
#include <cuda_fp16.h>
#include <math.h>
#include <stdint.h>

#define S_LEN 1536
#define DM    1024
#define NH    16
#define HD    64
#define H2    32
#define DQK   48
#define DQKP  64
#define KVCC  256
#define ROPE_ 32
#define QCC   384
#define DFF   4096
#define SPP   384
#define EPS_RMS 1.1920929e-07f
#define ATTN_EPS 1e-5f
#define SCALING 0.14433756729740643f
#define LAMBDA_INIT 0.2f

// ------------------------- device scratch -------------------------
__device__ __half g_xin [S_LEN * DM];
__device__ float  g_ckv [S_LEN * 384];
__device__ __half g_ckvn[S_LEN * KVCC];
__device__ __half g_kvup[S_LEN * 2048];
__device__ float  g_cq  [S_LEN * QCC];
__device__ __half g_cqn [S_LEN * QCC];
__device__ __half g_qf  [S_LEN * 1536];
__device__ __half g_Q   [(size_t)H2 * S_LEN * DQKP];
__device__ __half g_K   [(size_t)H2 * S_LEN * DQKP];
__device__ __half g_V   [(size_t)NH * S_LEN * HD];
__device__ __half g_Ph  [(size_t)H2 * S_LEN * S_LEN];   // UNNORMALIZED exp, fp16
__device__ float  g_inv [H2 * S_LEN];                    // per-row 1/sum
__device__ float  g_g   [NH * S_LEN];
__device__ float  g_gp  [12 * NH * S_LEN];               // colmean partials
__device__ float  g_ao  [(size_t)NH * S_LEN * HD];
__device__ __half g_af  [S_LEN * DM];
__device__ float  g_x2  [S_LEN * DM];
__device__ __half g_hb  [S_LEN * DM];
__device__ __half g_uv  [(size_t)S_LEN * 2 * DFF];
__device__ __half g_act [(size_t)S_LEN * DFF];
__device__ float  g_lambda;
// fp16 weight copies
__device__ __half g_kvdw_h[384 * DM];
__device__ __half g_qdw_h [QCC * DM];
__device__ __half g_kvuw_h[2048 * KVCC];
__device__ __half g_quw_h [1536 * QCC];
__device__ __half g_ow_h  [(size_t)DM * DM];
__device__ __half g_fiw_h [(size_t)2 * DFF * DM];
__device__ __half g_fow_h [(size_t)DM * DFF];

// ------------------------- helpers -------------------------
__device__ __forceinline__ void cpa16(void* smem_dst, const void* gsrc) {
    unsigned a = (unsigned)__cvta_generic_to_shared(smem_dst);
    asm volatile("cp.async.ca.shared.global [%0], [%1], 16;\n" :: "r"(a), "l"(gsrc));
}
__device__ __forceinline__ void cpa_commit() { asm volatile("cp.async.commit_group;\n"); }
template <int NG>
__device__ __forceinline__ void cpa_wait() { asm volatile("cp.async.wait_group %0;\n" :: "n"(NG)); }

#define LDM_X4(a0,a1,a2,a3,p) \
    asm volatile("ldmatrix.sync.aligned.m8n8.x4.shared.b16 {%0,%1,%2,%3}, [%4];" \
        : "=r"(a0), "=r"(a1), "=r"(a2), "=r"(a3) \
        : "r"((unsigned)__cvta_generic_to_shared(p)))
#define LDM_X2(b0,b1,p) \
    asm volatile("ldmatrix.sync.aligned.m8n8.x2.shared.b16 {%0,%1}, [%2];" \
        : "=r"(b0), "=r"(b1) \
        : "r"((unsigned)__cvta_generic_to_shared(p)))
#define LDM_X2T(b0,b1,p) \
    asm volatile("ldmatrix.sync.aligned.m8n8.x2.trans.shared.b16 {%0,%1}, [%2];" \
        : "=r"(b0), "=r"(b1) \
        : "r"((unsigned)__cvta_generic_to_shared(p)))
#define MMA_F16(d, a, b) \
    asm volatile( \
        "mma.sync.aligned.m16n8k16.row.col.f32.f16.f16.f32 " \
        "{%0,%1,%2,%3}, {%4,%5,%6,%7}, {%8,%9}, {%0,%1,%2,%3};" \
        : "+f"(d[0]), "+f"(d[1]), "+f"(d[2]), "+f"(d[3]) \
        : "r"(a[0]), "r"(a[1]), "r"(a[2]), "r"(a[3]), "r"(b[0]), "r"(b[1]))

#define HSTR 40     /* stride for 32-wide tiles (av_k) */
#define GBK  32
#define KSTR 72     /* stride (halves) for 64-wide k-tiles */

// ------------------- FP16 GEMM: 128x128 tiles, K-tile=64, 2-stage --------------
// One __syncthreads per k-iteration (wait -> sync -> issue loads -> compute).
#define SMEM_H (2 * 2 * 128 * KSTR * 2)

template <bool HALF_OUT>
__global__ __launch_bounds__(256, 2)
void hgemm(const __half* __restrict__ A, const __half* __restrict__ B,
           const float* __restrict__ Res, void* __restrict__ Cv,
           int M, int N, int K, long long sA, long long sB, long long sC,
           float scale)
{
    extern __shared__ __half hsm[];
    __half* AsB = hsm;                   // [2][128*KSTR]
    __half* BsB = hsm + 2 * 128 * KSTR;  // [2][128*KSTR]

    A += (long long)blockIdx.z * sA;
    B += (long long)blockIdx.z * sB;
    float*  Cf = (float*)Cv  + (long long)blockIdx.z * sC;
    __half* Ch = (__half*)Cv + (long long)blockIdx.z * sC;

    const int tid  = threadIdx.x;
    const int lane = tid & 31;
    const int warp = tid >> 5;
    const int wm   = warp >> 2;
    const int wn   = warp & 3;
    const int row0 = blockIdx.y * 128;
    const int col0 = blockIdx.x * 128;
    const int grp  = lane >> 2;
    const int tig  = lane & 3;

    const int nk = K / 64;

    auto load_tiles = [&](int ki, int buf) {
        const __half* Ag = A + (long long)row0 * K + ki * 64;
        __half* Ad = AsB + buf * 128 * KSTR;
#pragma unroll
        for (int it = 0; it < 4; it++) {
            int f = tid + it * 256;
            int r = f >> 3, c8 = (f & 7) * 8;
            cpa16(Ad + r * KSTR + c8, Ag + (long long)r * K + c8);
        }
        const __half* Bg = B + (long long)col0 * K + ki * 64;
        __half* Bd = BsB + buf * 128 * KSTR;
#pragma unroll
        for (int it = 0; it < 4; it++) {
            int f = tid + it * 256;
            int r = f >> 3, c8 = (f & 7) * 8;
            cpa16(Bd + r * KSTR + c8, Bg + (long long)r * K + c8);
        }
        cpa_commit();
    };

    float acc[4][4][4];
#pragma unroll
    for (int i = 0; i < 4; i++)
#pragma unroll
        for (int j = 0; j < 4; j++)
#pragma unroll
            for (int l = 0; l < 4; l++) acc[i][j][l] = 0.f;

    load_tiles(0, 0);

    const int arow = (lane & 15);
    const int asel = (lane >> 4) * 8;
    const int brow = (lane & 7);
    const int bsel = ((lane >> 3) & 1) * 8;

    for (int i = 0; i < nk; i++) {
        int cur = i & 1;
        cpa_wait<0>();          // stage i data complete
        __syncthreads();        // all warps done with compute(i-1); data visible
        if (i + 1 < nk) load_tiles(i + 1, cur ^ 1);

        const __half* Ab = AsB + cur * 128 * KSTR;
        const __half* Bb = BsB + cur * 128 * KSTR;
#pragma unroll
        for (int kc = 0; kc < 4; kc++) {
            unsigned a[4][4], b[4][2];
            int acol = kc * 16 + asel;
            int bcol = kc * 16 + bsel;
#pragma unroll
            for (int mi = 0; mi < 4; mi++) {
                const __half* p = Ab + (wm * 64 + mi * 16 + arow) * KSTR + acol;
                LDM_X4(a[mi][0], a[mi][1], a[mi][2], a[mi][3], p);
            }
#pragma unroll
            for (int ni = 0; ni < 4; ni++) {
                const __half* p = Bb + (wn * 32 + ni * 8 + brow) * KSTR + bcol;
                LDM_X2(b[ni][0], b[ni][1], p);
            }
#pragma unroll
            for (int mi = 0; mi < 4; mi++)
#pragma unroll
                for (int ni = 0; ni < 4; ni++)
                    MMA_F16(acc[mi][ni], a[mi], b[ni]);
        }
        // no trailing sync: next iter's top sync provides the hazard guard
    }

#pragma unroll
    for (int mi = 0; mi < 4; mi++)
#pragma unroll
        for (int ni = 0; ni < 4; ni++)
#pragma unroll
            for (int h = 0; h < 2; h++) {
                int r = row0 + wm * 64 + mi * 16 + grp + h * 8;
                int cc = col0 + wn * 32 + ni * 8 + tig * 2;
                long long o = (long long)r * N + cc;
                float v0 = acc[mi][ni][h * 2 + 0] * scale;
                float v1 = acc[mi][ni][h * 2 + 1] * scale;
                if (HALF_OUT) {
                    *(__half2*)(Ch + o) = __floats2half2_rn(v0, v1);
                } else {
                    if (Res) { v0 += Res[o]; v1 += Res[o + 1]; }
                    Cf[o] = v0; Cf[o + 1] = v1;
                }
            }
}

// --------- fused QK^T + masked unnormalized softmax (writes e, 1/rowsum) -------
#define QKS 72
#define QK_SMEM (128*QKS*2 + 2*64*QKS*2 + 128*QKS*2)

__global__ __launch_bounds__(256)
void qk_softmax_k(const __half* __restrict__ Q, const __half* __restrict__ Kg,
                  __half* __restrict__ Ph, float* __restrict__ invp)
{
    extern __shared__ char qsm[];
    __half* Qs = (__half*)qsm;            // 128 x QKS
    __half* Ks = Qs + 128 * QKS;          // [2][64 x QKS]
    __half* Os = Ks + 2 * 64 * QKS;       // 128 x QKS staging

    const int h2   = blockIdx.y;
    const int row0 = blockIdx.x * 128;
    const int tid  = threadIdx.x;
    const int lane = tid & 31;
    const int warp = tid >> 5;
    const int grp  = lane >> 2;
    const int tig  = lane & 3;

    const __half* Qh = Q + (long long)h2 * S_LEN * DQKP;
    const __half* Kh = Kg + (long long)h2 * S_LEN * DQKP;
    __half* Pout = Ph + (long long)h2 * S_LEN * S_LEN;

#pragma unroll
    for (int it = 0; it < 4; it++) {
        int f = tid + it * 256, r = f >> 3, c8 = (f & 7) * 8;
        cpa16(Qs + r * QKS + c8, Qh + (long long)(row0 + r) * DQKP + c8);
    }
    cpa_commit();

    auto loadK = [&](int jt, int buf) {
#pragma unroll
        for (int it = 0; it < 2; it++) {
            int f = tid + it * 256, r = f >> 3, c8 = (f & 7) * 8;
            cpa16(Ks + buf * 64 * QKS + r * QKS + c8,
                  Kh + (long long)(jt * 64 + r) * DQKP + c8);
        }
        cpa_commit();
    };

    const int r0  = warp * 16 + grp;
    const int ip0 = (row0 + r0) % SPP;
    const int ip1 = (row0 + r0 + 8) % SPP;

    float s0 = 0.f, s1 = 0.f;

    loadK(0, 0);

    const int NJT = S_LEN / 64;   // 24
    for (int jt = 0; jt < NJT; jt++) {
        int buf = jt & 1;
        if (jt + 1 < NJT) { loadK(jt + 1, buf ^ 1); cpa_wait<1>(); }
        else              { cpa_wait<0>(); }
        __syncthreads();

        float acc[8][4];
#pragma unroll
        for (int ni = 0; ni < 8; ni++)
#pragma unroll
            for (int l = 0; l < 4; l++) acc[ni][l] = 0.f;

        const __half* Kb = Ks + buf * 64 * QKS;
#pragma unroll
        for (int kc = 0; kc < 4; kc++) {
            unsigned a[4];
            const __half* pa = Qs + (warp * 16 + (lane & 15)) * QKS
                                  + kc * 16 + (lane >> 4) * 8;
            LDM_X4(a[0], a[1], a[2], a[3], pa);
#pragma unroll
            for (int ni = 0; ni < 8; ni++) {
                unsigned bb[2];
                const __half* pb = Kb + (ni * 8 + (lane & 7)) * QKS
                                      + kc * 16 + ((lane >> 3) & 1) * 8;
                LDM_X2(bb[0], bb[1], pb);
                MMA_F16(acc[ni], a, bb);
            }
        }

#pragma unroll
        for (int ni = 0; ni < 8; ni++) {
            int c0  = jt * 64 + ni * 8 + tig * 2;
            int jm0 = c0 % SPP;
            float e00 = (jm0     <= ip0) ? __expf(fminf(acc[ni][0] * SCALING, 10.f)) : 0.f;
            float e01 = (jm0 + 1 <= ip0) ? __expf(fminf(acc[ni][1] * SCALING, 10.f)) : 0.f;
            float e10 = (jm0     <= ip1) ? __expf(fminf(acc[ni][2] * SCALING, 10.f)) : 0.f;
            float e11 = (jm0 + 1 <= ip1) ? __expf(fminf(acc[ni][3] * SCALING, 10.f)) : 0.f;
            s0 += e00 + e01;
            s1 += e10 + e11;
            *(__half2*)(Os + r0 * QKS + ni * 8 + tig * 2)       = __floats2half2_rn(e00, e01);
            *(__half2*)(Os + (r0 + 8) * QKS + ni * 8 + tig * 2) = __floats2half2_rn(e10, e11);
        }
        __syncthreads();

#pragma unroll
        for (int it = 0; it < 4; it++) {
            int f = tid + it * 256, r = f >> 3, c8 = (f & 7) * 8;
            uint4 u = *(uint4*)(Os + r * QKS + c8);
            *(uint4*)(Pout + (long long)(row0 + r) * S_LEN + jt * 64 + c8) = u;
        }
        __syncthreads();
    }

#pragma unroll
    for (int x = 1; x <= 2; x <<= 1) {
        s0 += __shfl_xor_sync(0xffffffffu, s0, x);
        s1 += __shfl_xor_sync(0xffffffffu, s1, x);
    }
    if (tig == 0) {
        invp[h2 * S_LEN + row0 + r0]     = 1.f / s0;
        invp[h2 * S_LEN + row0 + r0 + 8] = 1.f / s1;
    }
}

// ------------------------- fused differential-combine + AV GEMM ----------------
#define AVM 64
#define VSTR 72

__global__ __launch_bounds__(256)
void av_k(const __half* __restrict__ Ph, const float* __restrict__ invp,
          const __half* __restrict__ V,
          const float* __restrict__ g, const float* __restrict__ lamp,
          float* __restrict__ O)
{
    __shared__ __half As[AVM * HSTR];
    __shared__ __half Bs[GBK * VSTR];

    const int h    = blockIdx.y;
    const int row0 = blockIdx.x * AVM;
    const int tid  = threadIdx.x;
    const int lane = tid & 31;
    const int warp = tid >> 5;
    const int wm   = warp >> 1;
    const int wn   = warp & 1;
    const int grp  = lane >> 2;
    const int tig  = lane & 3;

    const float lam = *lamp;
    const float gl  = lam * (1.f / (float)S_LEN);
    const __half* p1 = Ph + (long long)(2 * h) * S_LEN * S_LEN;
    const __half* p2 = Ph + (long long)(2 * h + 1) * S_LEN * S_LEN;
    const __half* Vh = V + (long long)h * S_LEN * HD;
    const float*  gh = g + h * S_LEN;

    float acc[4][4];
#pragma unroll
    for (int j = 0; j < 4; j++)
#pragma unroll
        for (int l = 0; l < 4; l++) acc[j][l] = 0.f;

    const int dr  = tid >> 2;
    const int dc8 = (tid & 3) * 8;
    const int ip  = (row0 + dr) % SPP;
    const float i1 = invp[(2 * h) * S_LEN + row0 + dr];
    const float i2 = invp[(2 * h + 1) * S_LEN + row0 + dr];

    for (int j0 = 0; j0 < S_LEN; j0 += GBK) {
        {
            int kk = tid >> 3, c8 = (tid & 7) * 8;
            cpa16(Bs + kk * VSTR + c8, Vh + (long long)(j0 + kk) * HD + c8);
        }
        cpa_commit();

        {
            long long off = (long long)(row0 + dr) * S_LEN + j0 + dc8;
            uint4 u1 = *(const uint4*)(p1 + off);
            uint4 u2 = *(const uint4*)(p2 + off);
            const __half2* h1 = (const __half2*)&u1;
            const __half2* h2 = (const __half2*)&u2;
            __half outh[8];
            int jb = j0 + dc8;
#pragma unroll
            for (int e = 0; e < 4; e++) {
                float2 f1 = __half22float2(h1[e]);
                float2 f2 = __half22float2(h2[e]);
                int ja = jb + 2 * e, jbb = ja + 1;
                float o0 = ((ja  % SPP) > ip) ? 0.f
                           : (f1.x * i1 - lam * (f2.x * i2) + gl * gh[ja]);
                float o1 = ((jbb % SPP) > ip) ? 0.f
                           : (f1.y * i1 - lam * (f2.y * i2) + gl * gh[jbb]);
                outh[2 * e]     = __float2half_rn(o0);
                outh[2 * e + 1] = __float2half_rn(o1);
            }
            *(uint4*)(As + dr * HSTR + dc8) = *(uint4*)outh;
        }
        cpa_wait<0>();
        __syncthreads();

#pragma unroll
        for (int kc = 0; kc < 2; kc++) {
            unsigned a[4], b[4][2];
            {
                const __half* p = As + (wm * 16 + (lane & 15)) * HSTR
                                     + kc * 16 + (lane >> 4) * 8;
                LDM_X4(a[0], a[1], a[2], a[3], p);
            }
#pragma unroll
            for (int ni = 0; ni < 4; ni++) {
                int krow = kc * 16 + ((lane >> 3) & 1) * 8 + (lane & 7);
                int ncol = wn * 32 + ni * 8;
                const __half* p = Bs + krow * VSTR + ncol;
                LDM_X2T(b[ni][0], b[ni][1], p);
            }
#pragma unroll
            for (int ni = 0; ni < 4; ni++)
                MMA_F16(acc[ni], a, b[ni]);
        }
        __syncthreads();
    }

#pragma unroll
    for (int ni = 0; ni < 4; ni++)
#pragma unroll
        for (int hh = 0; hh < 2; hh++) {
            int r = row0 + wm * 16 + grp + hh * 8;
            int cc = wn * 32 + ni * 8 + tig * 2;
            long long o = ((long long)h * S_LEN + r) * HD + cc;
            O[o]     = acc[ni][hh * 2 + 0];
            O[o + 1] = acc[ni][hh * 2 + 1];
        }
}

// ------------------------- rmsnorm: fp32 in -> fp16 out -------------------------
__global__ void rmsnorm_h(const float* __restrict__ in, const float* __restrict__ w,
                          __half* __restrict__ out, int cols, int in_ld, int out_ld,
                          float eps)
{
    const long long row = blockIdx.x;
    const float* ip = in + row * in_ld;
    __half* op = out + row * out_ld;

    float ss = 0.f;
    for (int j = threadIdx.x; j < cols; j += blockDim.x) {
        float v = ip[j];
        ss += v * v;
    }
    __shared__ float sh[32];
    int lane = threadIdx.x & 31, wid = threadIdx.x >> 5;
#pragma unroll
    for (int o = 16; o; o >>= 1) ss += __shfl_xor_sync(0xffffffffu, ss, o);
    if (lane == 0) sh[wid] = ss;
    __syncthreads();
    int nw = (blockDim.x + 31) >> 5;
    float tot = 0.f;
    if (threadIdx.x < nw) tot = sh[threadIdx.x];
    if (wid == 0) {
#pragma unroll
        for (int o = 16; o; o >>= 1) tot += __shfl_xor_sync(0xffffffffu, tot, o);
        if (lane == 0) sh[0] = tot;
    }
    __syncthreads();
    float inv = rsqrtf(sh[0] / (float)cols + eps);
    for (int j = threadIdx.x; j < cols; j += blockDim.x)
        op[j] = __float2half_rn(ip[j] * inv * w[j]);
}

// ------------------------- build Q/K/V with RoPE (fp16 out) --------------------
__global__ void build_qkv_k(const __half* __restrict__ qf, const __half* __restrict__ kvup,
                            const float* __restrict__ ckv,
                            const float* __restrict__ fcos, const float* __restrict__ fsin,
                            __half* __restrict__ Q, __half* __restrict__ K,
                            __half* __restrict__ V)
{
    const int i = blockIdx.x;
    const int tid = threadIdx.x;              // 128
    __shared__ float cs[8], sn[8];
    int p = i >> 2;
    if (tid < 8) {
        if (p == 0) { cs[tid] = 1.f; sn[tid] = 0.f; }
        else { cs[tid] = fcos[(p - 1) * 8 + tid]; sn[tid] = fsin[(p - 1) * 8 + tid]; }
    }
    __syncthreads();

    const __half* qrow = qf + (long long)i * 1536;
    const __half* krow = kvup + (long long)i * 2048;
    const float*  crow = ckv + (long long)i * 384;

    for (int e = tid; e < H2 * DQKP; e += 128) {
        int h2 = e / DQKP, d = e % DQKP;
        int h = h2 >> 1, c = h2 & 1;
        float qv = 0.f, kv = 0.f;
        if (d < 32) {
            qv = __half2float(qrow[h * 96 + c * 32 + d]);
            kv = __half2float(krow[h * 128 + c * 32 + d]);
        } else if (d < DQK) {
            int ee = d - 32;
            int f = ee >> 1;
            float q0 = __half2float(qrow[h * 96 + 64 + c * 16 + 2 * f]);
            float q1 = __half2float(qrow[h * 96 + 64 + c * 16 + 2 * f + 1]);
            float k0 = crow[KVCC + c * 16 + 2 * f];
            float k1 = crow[KVCC + c * 16 + 2 * f + 1];
            float C = cs[f], Sv = sn[f];
            if ((ee & 1) == 0) { qv = q0 * C - q1 * Sv; kv = k0 * C - k1 * Sv; }
            else               { qv = q0 * Sv + q1 * C; kv = k0 * Sv + k1 * C; }
        }
        Q[(long long)h2 * S_LEN * DQKP + (long long)i * DQKP + d] = __float2half_rn(qv);
        K[(long long)h2 * S_LEN * DQKP + (long long)i * DQKP + d] = __float2half_rn(kv);
    }
    for (int e = tid; e < NH * HD; e += 128) {
        int h = e >> 6, d = e & 63;
        V[(long long)h * S_LEN * HD + (long long)i * HD + d] = krow[h * 128 + 64 + d];
    }
}

// ---------- colmean stage 1: partial column sums over 128-row slabs ------------
__global__ void colmean_part_k(const __half* __restrict__ Ph, const float* __restrict__ invp,
                               float* __restrict__ gp)
{
    int j = blockIdx.x * blockDim.x + threadIdx.x;
    int h = blockIdx.y;
    int slab = blockIdx.z;                 // 0..11
    if (j >= S_LEN) return;
    const __half* base = Ph + (long long)(2 * h) * S_LEN * S_LEN + j;
    const float*  iv   = invp + (2 * h) * S_LEN;
    int i0 = slab * 128;
    float s = 0.f;
#pragma unroll 4
    for (int i = i0; i < i0 + 128; i++)
        s += __half2float(base[(long long)i * S_LEN]) * iv[i];
    gp[((long long)slab * NH + h) * S_LEN + j] = s;
}
// ---------- colmean stage 2: reduce 12 slabs ------------------------------------
__global__ void colmean_red_k(const float* __restrict__ gp, float* __restrict__ g)
{
    int j = blockIdx.x * blockDim.x + threadIdx.x;
    int h = blockIdx.y;
    if (j >= S_LEN) return;
    float s = 0.f;
#pragma unroll
    for (int slab = 0; slab < 12; slab++)
        s += gp[((long long)slab * NH + h) * S_LEN + j];
    g[h * S_LEN + j] = s;   // raw sum; av multiplies by lam/S_LEN
}

// ------------------------- lambda scalar -------------------------
__global__ void lambda_k_(const float* __restrict__ q1, const float* __restrict__ k1,
                          const float* __restrict__ q2, const float* __restrict__ k2,
                          float* __restrict__ out)
{
    int t = threadIdx.x;
    float a = q1[t] * k1[t];
    float b = q2[t] * k2[t];
#pragma unroll
    for (int o = 16; o; o >>= 1) {
        a += __shfl_xor_sync(0xffffffffu, a, o);
        b += __shfl_xor_sync(0xffffffffu, b, o);
    }
    if (t == 0) *out = expf(a) - expf(b) + LAMBDA_INIT;
}

// ------------------------- per (token, head) rmsnorm: fp32 -> fp16 -------------
__global__ void attn_norm_k(const float* __restrict__ ao, const float* __restrict__ w,
                            __half* __restrict__ outf)
{
    int i = blockIdx.x, h = blockIdx.y, d = threadIdx.x;
    long long idx = ((long long)h * S_LEN + i) * HD + d;
    float v = ao[idx];
    float sq = v * v;
    __shared__ float sh[2];
#pragma unroll
    for (int o = 16; o; o >>= 1) sq += __shfl_xor_sync(0xffffffffu, sq, o);
    if ((d & 31) == 0) sh[d >> 5] = sq;
    __syncthreads();
    float tot = sh[0] + sh[1];
    outf[idx] = __float2half_rn(v * rsqrtf(tot / (float)HD + ATTN_EPS) * w[d]);
}

// ------------------------- SwiGLU: fp16 in -> fp16 out -------------------------
__global__ void swiglu_k(const __half* __restrict__ uv, __half* __restrict__ act)
{
    long long idx = (long long)blockIdx.x * blockDim.x + threadIdx.x;
    if (idx >= (long long)S_LEN * DFF) return;
    long long i = idx / DFF, j = idx % DFF;
    float u  = __half2float(uv[i * (2 * DFF) + j]);
    float vg = __half2float(uv[i * (2 * DFF) + DFF + j]);
    act[idx] = __float2half_rn(u * (vg / (1.f + __expf(-vg))));
}

// ------------------------- fp32 -> fp16 weight convert (vectorized) ------------
__global__ void cvt_h_k(const float* __restrict__ in, __half* __restrict__ out, int n)
{
    int i = (blockIdx.x * blockDim.x + threadIdx.x) * 4;
    int stride = gridDim.x * blockDim.x * 4;
    for (; i < n; i += stride) {
        float4 v = *(const float4*)(in + i);
        *(__half2*)(out + i)     = __floats2half2_rn(v.x, v.y);
        *(__half2*)(out + i + 2) = __floats2half2_rn(v.z, v.w);
    }
}
__global__ void zero_h_k(__half* __restrict__ p, int n)
{
    int i = blockIdx.x * blockDim.x + threadIdx.x;
    if (i < n) p[i] = __float2half(0.f);
}

// ------------------------- host -------------------------
extern "C" void kernel_launch(void* const* d_in, const int* in_sizes, int n_in,
                              void* d_out, int out_size)
{
    const float* x    = (const float*)d_in[0];
    const float* fc   = (const float*)d_in[1];
    const float* fs   = (const float*)d_in[2];
    const float* n1w  = (const float*)d_in[3];
    const float* n2w  = (const float*)d_in[4];
    const float* kvdw = (const float*)d_in[5];
    const float* qdw  = (const float*)d_in[6];
    const float* kvnw = (const float*)d_in[7];
    const float* qnw  = (const float*)d_in[8];
    const float* kvuw = (const float*)d_in[9];
    const float* quw  = (const float*)d_in[10];
    const float* lq1  = (const float*)d_in[11];
    const float* lk1  = (const float*)d_in[12];
    const float* lq2  = (const float*)d_in[13];
    const float* lk2  = (const float*)d_in[14];
    const float* anw  = (const float*)d_in[15];
    const float* ow   = (const float*)d_in[16];
    const float* fiw  = (const float*)d_in[17];
    const float* fow  = (const float*)d_in[18];
    float* outp = (float*)d_out;

    __half *xin, *ckvn, *kvup, *cqn, *qf, *Q, *K, *V, *Ph, *af, *hb, *uv, *act;
    __half *kvdw_h, *qdw_h, *kvuw_h, *quw_h, *ow_h, *fiw_h, *fow_h;
    float *ckv, *cq, *gg, *gp, *ao, *x2, *lam, *invp;
    cudaGetSymbolAddress((void**)&xin,  g_xin);
    cudaGetSymbolAddress((void**)&ckv,  g_ckv);
    cudaGetSymbolAddress((void**)&ckvn, g_ckvn);
    cudaGetSymbolAddress((void**)&kvup, g_kvup);
    cudaGetSymbolAddress((void**)&cq,   g_cq);
    cudaGetSymbolAddress((void**)&cqn,  g_cqn);
    cudaGetSymbolAddress((void**)&qf,   g_qf);
    cudaGetSymbolAddress((void**)&Q,    g_Q);
    cudaGetSymbolAddress((void**)&K,    g_K);
    cudaGetSymbolAddress((void**)&V,    g_V);
    cudaGetSymbolAddress((void**)&Ph,   g_Ph);
    cudaGetSymbolAddress((void**)&invp, g_inv);
    cudaGetSymbolAddress((void**)&gg,   g_g);
    cudaGetSymbolAddress((void**)&gp,   g_gp);
    cudaGetSymbolAddress((void**)&ao,   g_ao);
    cudaGetSymbolAddress((void**)&af,   g_af);
    cudaGetSymbolAddress((void**)&x2,   g_x2);
    cudaGetSymbolAddress((void**)&hb,   g_hb);
    cudaGetSymbolAddress((void**)&uv,   g_uv);
    cudaGetSymbolAddress((void**)&act,  g_act);
    cudaGetSymbolAddress((void**)&lam,  g_lambda);
    cudaGetSymbolAddress((void**)&kvdw_h, g_kvdw_h);
    cudaGetSymbolAddress((void**)&qdw_h,  g_qdw_h);
    cudaGetSymbolAddress((void**)&kvuw_h, g_kvuw_h);
    cudaGetSymbolAddress((void**)&quw_h,  g_quw_h);
    cudaGetSymbolAddress((void**)&ow_h,   g_ow_h);
    cudaGetSymbolAddress((void**)&fiw_h,  g_fiw_h);
    cudaGetSymbolAddress((void**)&fow_h,  g_fow_h);

    static bool attr_set = false;
    if (!attr_set) {
        cudaFuncSetAttribute(hgemm<false>, cudaFuncAttributeMaxDynamicSharedMemorySize, SMEM_H);
        cudaFuncSetAttribute(hgemm<true>,  cudaFuncAttributeMaxDynamicSharedMemorySize, SMEM_H);
        cudaFuncSetAttribute(qk_softmax_k, cudaFuncAttributeMaxDynamicSharedMemorySize, QK_SMEM);
        attr_set = true;
    }

    auto grid_g = [](int M, int N, int batch) {
        return dim3((unsigned)(N / 128), (unsigned)(M / 128), (unsigned)batch);
    };

    // 0. weights -> fp16 (+ zero-pad kv_down rows 288..383)
    cvt_h_k<<<288,  256>>>(kvdw, kvdw_h, 288 * DM);
    zero_h_k<<<(96 * DM + 255) / 256, 256>>>(kvdw_h + 288 * DM, 96 * DM);
    cvt_h_k<<<384,  256>>>(qdw,  qdw_h,  QCC * DM);
    cvt_h_k<<<512,  256>>>(kvuw, kvuw_h, 2048 * KVCC);
    cvt_h_k<<<576,  256>>>(quw,  quw_h,  1536 * QCC);
    cvt_h_k<<<1024, 256>>>(ow,   ow_h,   DM * DM);
    cvt_h_k<<<4096, 256>>>(fiw,  fiw_h,  2 * DFF * DM);
    cvt_h_k<<<4096, 256>>>(fow,  fow_h,  DM * DFF);

    // 1. xin = rmsnorm(x) -> fp16
    rmsnorm_h<<<S_LEN, 256>>>(x, n1w, xin, DM, DM, DM, EPS_RMS);
    // 2. ckv = xin @ kv_down^T  [1536, 384(pad)] fp32
    hgemm<false><<<grid_g(S_LEN, 384, 1), 256, SMEM_H>>>(xin, kvdw_h, nullptr, ckv,
        S_LEN, 384, DM, 0, 0, 0, 1.f);
    // 3. ckvn = rmsnorm(ckv[:, :256]) -> fp16
    rmsnorm_h<<<S_LEN, 256>>>(ckv, kvnw, ckvn, KVCC, 384, KVCC, EPS_RMS);
    // 4. kvup = ckvn @ kv_up^T [1536, 2048] fp16
    hgemm<true><<<grid_g(S_LEN, 2048, 1), 256, SMEM_H>>>(ckvn, kvuw_h, nullptr, kvup,
        S_LEN, 2048, KVCC, 0, 0, 0, 1.f);
    // 5. cq = xin @ q_down^T [1536, 384] fp32
    hgemm<false><<<grid_g(S_LEN, QCC, 1), 256, SMEM_H>>>(xin, qdw_h, nullptr, cq,
        S_LEN, QCC, DM, 0, 0, 0, 1.f);
    // 6. cqn = rmsnorm(cq) -> fp16
    rmsnorm_h<<<S_LEN, 256>>>(cq, qnw, cqn, QCC, QCC, QCC, EPS_RMS);
    // 7. qf = cqn @ q_up^T [1536, 1536] fp16
    hgemm<true><<<grid_g(S_LEN, 1536, 1), 256, SMEM_H>>>(cqn, quw_h, nullptr, qf,
        S_LEN, 1536, QCC, 0, 0, 0, 1.f);
    // 8. build Q/K/V (fp16, Q/K padded to 64)
    build_qkv_k<<<S_LEN, 128>>>(qf, kvup, ckv, fc, fs, Q, K, V);
    // 9. fused QK^T + masked unnormalized softmax (writes e fp16 + 1/rowsum)
    qk_softmax_k<<<dim3(S_LEN / 128, H2), 256, QK_SMEM>>>(Q, K, Ph, invp);
    // 10. lambda
    lambda_k_<<<1, 32>>>(lq1, lk1, lq2, lk2, lam);
    // 11. column sums (two-stage deterministic)
    colmean_part_k<<<dim3((S_LEN + 255) / 256, NH, 12), 256>>>(Ph, invp, gp);
    colmean_red_k<<<dim3((S_LEN + 255) / 256, NH), 256>>>(gp, gg);
    // 12+13. fused combine (normalize on the fly) + AV
    av_k<<<dim3(S_LEN / AVM, NH), 256>>>(Ph, invp, V, gg, lam, ao);
    // 14. attn rmsnorm -> fp16 (keeps [h][i][d] scrambled-reshape layout)
    attn_norm_k<<<dim3(S_LEN, NH), 64>>>(ao, anw, af);
    // 15. x2 = x + af @ o_w^T fp32
    hgemm<false><<<grid_g(S_LEN, DM, 1), 256, SMEM_H>>>(af, ow_h, x, x2,
        S_LEN, DM, DM, 0, 0, 0, 1.f);
    // 16. hb = rmsnorm(x2) -> fp16
    rmsnorm_h<<<S_LEN, 256>>>(x2, n2w, hb, DM, DM, DM, EPS_RMS);
    // 17. uv = hb @ ff_in^T [1536, 8192] fp16
    hgemm<true><<<grid_g(S_LEN, 2 * DFF, 1), 256, SMEM_H>>>(hb, fiw_h, nullptr, uv,
        S_LEN, 2 * DFF, DM, 0, 0, 0, 1.f);
    // 18. act = u * silu(vg) fp16
    {
        long long tot = (long long)S_LEN * DFF;
        swiglu_k<<<(unsigned)((tot + 255) / 256), 256>>>(uv, act);
    }
    // 19. out = x2 + act @ ff_out^T fp32
    hgemm<false><<<grid_g(S_LEN, DM, 1), 256, SMEM_H>>>(act, fow_h, x2, outp,
        S_LEN, DM, DFF, 0, 0, 0, 1.f);
}